// round 7
// baseline (speedup 1.0000x reference)
#include <cuda_runtime.h>
#include <cuda_bf16.h>
#include <math.h>

// Problem dims
#define B_  2
#define S_  2048
#define H_  512
#define NH_ 8
#define DH_ 64
#define L_  6
#define FF_ 2048          // 4*H
#define M_  (B_*S_)       // 4096 tokens

// Contraction-dim octet permutation: value for logical col c stored at P8(c).
// Readers fetch float2 at position 2*lt to obtain logicals (lt, lt+4).
#define P8(c) (((c) & ~7) | (((c) & 3) << 1) | (((c) & 4) >> 2))

// ---------------- device scratch (no cudaMalloc allowed) ----------------
__device__ float g_x  [M_*H_];
__device__ float g_xr [M_*H_];       // tf32-rounded, k-permuted copy of x
__device__ float g_q  [M_*H_];       // k-permuted (d within head octets)
__device__ float g_k  [M_*H_];       // k-permuted
__device__ float g_v  [M_*H_];       // NOT permuted
__device__ float g_t  [M_*H_];       // k-permuted (flash output)
__device__ float g_t2a[M_*H_];
__device__ float g_t2b[M_*H_];
__device__ float g_res[M_*H_];
__device__ float g_resr[M_*H_];      // rounded + permuted copy of res
__device__ float g_h1 [M_*FF_];      // permuted (FFN1 output)
__device__ float g_mb [M_];          // mask bias: 0 or -1e20 per (b,s)
__device__ float g_wr [18874368];    // tf32-rounded weights [Wq|Wk|Wv|Wo|W1|W2]

#define WOFF_Q  0
#define WOFF_K  (L_*H_*H_)
#define WOFF_V  (2*L_*H_*H_)
#define WOFF_O  (3*L_*H_*H_)
#define WOFF_1  (4*L_*H_*H_)
#define WOFF_2  (4*L_*H_*H_ + L_*H_*FF_)

// ---------------- helpers ----------------
__device__ __forceinline__ float tf32r(float x) {
    float y;
    asm("cvt.rna.tf32.f32 %0, %1;" : "=f"(y) : "f"(x));
    return y;
}
__device__ __forceinline__ float4 tf32r4(float4 v) {
    v.x = tf32r(v.x); v.y = tf32r(v.y); v.z = tf32r(v.z); v.w = tf32r(v.w);
    return v;
}
__device__ __forceinline__ void mma_tf32(
    float& c0, float& c1, float& c2, float& c3,
    float a0, float a1, float a2, float a3, float b0, float b1)
{
    asm volatile(
        "mma.sync.aligned.m16n8k8.row.col.f32.tf32.tf32.f32 "
        "{%0,%1,%2,%3}, {%4,%5,%6,%7}, {%8,%9}, {%0,%1,%2,%3};\n"
        : "+f"(c0), "+f"(c1), "+f"(c2), "+f"(c3)
        : "r"(__float_as_uint(a0)), "r"(__float_as_uint(a1)),
          "r"(__float_as_uint(a2)), "r"(__float_as_uint(a3)),
          "r"(__float_as_uint(b0)), "r"(__float_as_uint(b1)));
}
__device__ __forceinline__ void cp_async16(float* dst, const float* src) {
    unsigned s = (unsigned)__cvta_generic_to_shared(dst);
    asm volatile("cp.async.cg.shared.global [%0], [%1], 16;" :: "r"(s), "l"(src));
}
__device__ __forceinline__ void cp_commit() {
    asm volatile("cp.async.commit_group;");
}

// ---------------- weight rounding: all 6 tensors in one launch ----------------
#define RQ_ (L_*H_*H_/4)
#define R1_ (L_*H_*FF_/4)
__global__ __launch_bounds__(256) void round_all_kernel(
    const float* __restrict__ Wq, const float* __restrict__ Wk,
    const float* __restrict__ Wv, const float* __restrict__ Wo,
    const float* __restrict__ W1, const float* __restrict__ W2,
    float* __restrict__ dst)
{
    long i = (long)blockIdx.x * 256 + threadIdx.x;
    const float* src;
    long local;
    if (i < 4L * RQ_) {
        int region = (int)(i / RQ_);
        local = i - (long)region * RQ_;
        src = (region == 0) ? Wq : (region == 1) ? Wk : (region == 2) ? Wv : Wo;
    } else if (i < 4L * RQ_ + R1_) {
        local = i - 4L * RQ_;
        src = W1;
    } else {
        local = i - 4L * RQ_ - R1_;
        src = W2;
    }
    *(float4*)&dst[i * 4] = tf32r4(*(const float4*)&src[local * 4]);
}

// ---------------- embedding + sinusoidal posenc ----------------
__global__ __launch_bounds__(256) void embed_kernel(
    const int* __restrict__ src, const float* __restrict__ emb,
    float* __restrict__ x, float* __restrict__ xr)
{
    int idx = blockIdx.x * 256 + threadIdx.x;
    int d   = idx & (H_ - 1);
    int tok = idx >> 9;
    int s   = tok & (S_ - 1);
    int j2  = (d >> 1) * 2;
    float div = powf(10000.0f, (float)j2 * (1.0f / (float)H_));
    float arg = (float)s / div;
    float pe  = (d & 1) ? cosf(arg) : sinf(arg);
    float v = emb[(size_t)src[tok] * H_ + d] + pe;
    x[idx]  = v;
    xr[P8(idx)] = tf32r(v);     // permuted (octet-local, so global index ok)
}

__global__ __launch_bounds__(256) void maskbias_kernel(
    const int* __restrict__ mask, float* __restrict__ mb)
{
    int i = blockIdx.x * 256 + threadIdx.x;
    if (i < M_) mb[i] = mask[i] ? 0.f : -1e20f;
}

// =========================================================================
// 3-stage cp.async tf32 GEMM core.  BM=128 BN=128 BK=32, 8 warps (4x2),
// warp tile 32x64.  A gmem is k-PERMUTED; a-frags load as LDS.64.
// permout: store output columns permuted (for q,k,h1).
// =========================================================================
#define GAS 36
#define GBS 136
#define GEMM_SMEM ((3 * (128 * GAS + 32 * GBS)) * 4)

template<bool RELU, bool ROUND>
__device__ __forceinline__ void gemm_core(
    const float* __restrict__ A, const float* __restrict__ W,
    const float* __restrict__ bias, float biasScale, float* __restrict__ C,
    int brow, int bcol, int N, int Kfull, int koff, int Kspan, bool permout)
{
    extern __shared__ float sm[];
    float* As = sm;
    float* Bs = sm + 3 * 128 * GAS;

    int tid  = threadIdx.x;
    int lane = tid & 31;
    int warp = tid >> 5;
    int warp_m = (warp >> 1) * 32;
    int warp_n = (warp & 1) * 64;
    int lg = lane >> 2, lt = lane & 3;

    int a_row0 = warp * 4 + (lane >> 3);
    int a_col  = (((lane & 7) - (lane >> 3)) & 7) * 4;
    int b_row0 = tid >> 5;
    int b_col  = lane * 4;

    auto load_tile = [&](int st, int k0) {
        float* as = As + st * 128 * GAS;
        float* bs = Bs + st * 32 * GBS;
        #pragma unroll
        for (int i = 0; i < 4; i++) {
            int r = a_row0 + i * 32;
            cp_async16(&as[r * GAS + a_col], &A[(size_t)(brow + r) * Kfull + koff + k0 + a_col]);
        }
        #pragma unroll
        for (int i = 0; i < 4; i++) {
            int r = b_row0 + i * 8;
            cp_async16(&bs[r * GBS + b_col], &W[(size_t)(koff + k0 + r) * N + bcol + b_col]);
        }
        cp_commit();
    };

    int nk = Kspan / 32;
    load_tile(0, 0);
    load_tile(1, 32);

    float acc[2][8][4];
    #pragma unroll
    for (int i = 0; i < 2; i++)
        #pragma unroll
        for (int j = 0; j < 8; j++)
            #pragma unroll
            for (int r = 0; r < 4; r++) acc[i][j][r] = 0.f;

    for (int t = 0; t < nk; t++) {
        asm volatile("cp.async.wait_group 1;");
        __syncthreads();
        if (t + 2 < nk) load_tile((t + 2) % 3, (t + 2) * 32);
        else cp_commit();

        const float* as = As + (t % 3) * 128 * GAS;
        const float* bs = Bs + (t % 3) * 32 * GBS;

        #pragma unroll
        for (int kk = 0; kk < 32; kk += 8) {
            float af[2][4];
            #pragma unroll
            for (int i = 0; i < 2; i++) {
                int mb = warp_m + i * 16;
                float2 f0 = *(const float2*)&as[(mb + lg) * GAS + kk + 2 * lt];
                float2 f1 = *(const float2*)&as[(mb + 8 + lg) * GAS + kk + 2 * lt];
                af[i][0] = f0.x; af[i][2] = f0.y;   // logical k = lt, lt+4
                af[i][1] = f1.x; af[i][3] = f1.y;
            }
            float bf[8][2];
            #pragma unroll
            for (int j = 0; j < 8; j++) {
                int nb = warp_n + j * 8 + lg;
                bf[j][0] = bs[(kk + lt) * GBS + nb];
                bf[j][1] = bs[(kk + 4 + lt) * GBS + nb];
            }
            #pragma unroll
            for (int i = 0; i < 2; i++)
                #pragma unroll
                for (int j = 0; j < 8; j++)
                    mma_tf32(acc[i][j][0], acc[i][j][1], acc[i][j][2], acc[i][j][3],
                             af[i][0], af[i][1], af[i][2], af[i][3],
                             bf[j][0], bf[j][1]);
        }
        __syncthreads();
    }

    #pragma unroll
    for (int i = 0; i < 2; i++) {
        #pragma unroll
        for (int j = 0; j < 8; j++) {
            int col = bcol + warp_n + j * 8 + 2 * lt;   // logical column
            float bx = bias[col] * biasScale, by = bias[col + 1] * biasScale;
            int r0 = brow + warp_m + i * 16 + lg;
            float2 v0 = make_float2(acc[i][j][0] + bx, acc[i][j][1] + by);
            float2 v1 = make_float2(acc[i][j][2] + bx, acc[i][j][3] + by);
            if (RELU) {
                v0.x = fmaxf(v0.x, 0.f); v0.y = fmaxf(v0.y, 0.f);
                v1.x = fmaxf(v1.x, 0.f); v1.y = fmaxf(v1.y, 0.f);
            }
            if (ROUND) {
                v0.x = tf32r(v0.x); v0.y = tf32r(v0.y);
                v1.x = tf32r(v1.x); v1.y = tf32r(v1.y);
            }
            if (permout) {
                int p = P8(col);               // P8(col+1) == p+2
                C[(size_t)r0 * N + p]           = v0.x;
                C[(size_t)r0 * N + p + 2]       = v0.y;
                C[(size_t)(r0 + 8) * N + p]     = v1.x;
                C[(size_t)(r0 + 8) * N + p + 2] = v1.y;
            } else {
                *(float2*)&C[(size_t)r0 * N + col]       = v0;
                *(float2*)&C[(size_t)(r0 + 8) * N + col] = v1;
            }
        }
    }
}

template<bool RELU, bool ROUND>
__global__ __launch_bounds__(256, 2) void gemm_tc_kernel(
    const float* __restrict__ A,
    const float* __restrict__ Wa, const float* __restrict__ Wb, const float* __restrict__ Wc,
    const float* __restrict__ ba, const float* __restrict__ bb, const float* __restrict__ bc,
    float* __restrict__ Ca, float* __restrict__ Cb_, float* __restrict__ Cc,
    int M, int N, int K, int permMask)
{
    int z = blockIdx.z;
    const float* W    = (z == 0) ? Wa : (z == 1) ? Wb : Wc;
    const float* bias = (z == 0) ? ba : (z == 1) ? bb : bc;
    float*       C    = (z == 0) ? Ca : (z == 1) ? Cb_ : Cc;
    gemm_core<RELU, ROUND>(A, W, bias, 1.f, C,
                           blockIdx.y * 128, blockIdx.x * 128, N, K, 0, K,
                           (permMask >> z) & 1);
}

__global__ __launch_bounds__(256, 2) void gemm_tc_sk(
    const float* __restrict__ A, const float* __restrict__ W,
    const float* __restrict__ bias,
    float* __restrict__ C0, float* __restrict__ C1,
    int M, int N, int K)
{
    int z = blockIdx.z;
    int Kh = K >> 1;
    gemm_core<false, false>(A, W, bias, z == 0 ? 1.f : 0.f,
                            z == 0 ? C0 : C1,
                            blockIdx.y * 128, blockIdx.x * 128, N, K, z * Kh, Kh, false);
}

// =========================================================================
// Fused flash attention.  q,k gmem are d-PERMUTED; v is not.
// Output t stored d-PERMUTED (consumed by O-proj GEMM).
// =========================================================================
#define QS  72
#define VS2 72
#define NKV (S_ / 64)
#define FLASH_SMEM ((128 * QS + 2 * 64 * QS + 2 * 64 * VS2 + 2 * 64) * 4)

__global__ __launch_bounds__(256) void flash_kernel(
    const float* __restrict__ q, const float* __restrict__ k,
    const float* __restrict__ v, const float* __restrict__ mbias,
    float* __restrict__ out)
{
    extern __shared__ float sm[];
    float* QP = sm;
    float* Ks = QP + 128 * QS;
    float* Vs = Ks + 2 * 64 * QS;
    float* MB = Vs + 2 * 64 * VS2;

    int tid  = threadIdx.x;
    int lane = tid & 31;
    int warp = tid >> 5;
    int wm   = warp * 16;
    int lg = lane >> 2, lt = lane & 3;
    int brow = blockIdx.x * 128;
    int bh = blockIdx.y;
    int b = bh >> 3, h = bh & 7;

    const float* Qb  = q + (size_t)b * S_ * H_ + h * DH_;
    const float* Kb  = k + (size_t)b * S_ * H_ + h * DH_;
    const float* Vb  = v + (size_t)b * S_ * H_ + h * DH_;
    const float* MBg = mbias + b * S_;

    #pragma unroll
    for (int i = 0; i < 8; i++) {
        int f4 = tid + i * 256;
        int r = f4 >> 4, c = (f4 & 15) * 4;
        *(float4*)&QP[r * QS + c] = *(const float4*)&Qb[(size_t)(brow + r) * H_ + c];
    }
    __syncthreads();

    // Q fragments (permuted layout -> float2 gives logicals lt, lt+4)
    float aq[8][4];
    #pragma unroll
    for (int kk = 0; kk < 8; kk++) {
        float2 f0 = *(const float2*)&QP[(wm + lg) * QS + kk * 8 + 2 * lt];
        float2 f1 = *(const float2*)&QP[(wm + 8 + lg) * QS + kk * 8 + 2 * lt];
        aq[kk][0] = f0.x; aq[kk][2] = f0.y;
        aq[kk][1] = f1.x; aq[kk][3] = f1.y;
    }
    __syncthreads();

    float acc_o[8][4];
    #pragma unroll
    for (int j = 0; j < 8; j++)
        #pragma unroll
        for (int r = 0; r < 4; r++) acc_o[j][r] = 0.f;
    float m0 = -1e30f, m1 = -1e30f, l0 = 0.f, l1 = 0.f;

    auto load_kv = [&](int buf, int it) {
        int kv0 = it * 64;
        float* kd = Ks + buf * 64 * QS;
        float* vd = Vs + buf * 64 * VS2;
        #pragma unroll
        for (int i = 0; i < 4; i++) {
            int f4 = tid + i * 256;
            int r = f4 >> 4, c = (f4 & 15) * 4;
            cp_async16(&kd[r * QS + c],  &Kb[(size_t)(kv0 + r) * H_ + c]);
            cp_async16(&vd[r * VS2 + c], &Vb[(size_t)(kv0 + r) * H_ + c]);
        }
        if (tid < 16) cp_async16(&MB[buf * 64 + tid * 4], &MBg[kv0 + tid * 4]);
    };

    load_kv(0, 0);
    cp_commit();

    for (int it = 0; it < NKV; it++) {
        int buf = it & 1;
        if (it + 1 < NKV) {
            load_kv(buf ^ 1, it + 1);
            cp_commit();
            asm volatile("cp.async.wait_group 1;");
        } else {
            asm volatile("cp.async.wait_group 0;");
        }
        __syncthreads();

        const float* Kt  = Ks + buf * 64 * QS;
        const float* Vt  = Vs + buf * 64 * VS2;
        const float* MBt = MB + buf * 64;

        // ---- S = Q @ K^T; K fragments via float2 (permuted layout) ----
        float accs[8][4];
        #pragma unroll
        for (int j = 0; j < 8; j++)
            #pragma unroll
            for (int r = 0; r < 4; r++) accs[j][r] = 0.f;
        #pragma unroll
        for (int kk = 0; kk < 8; kk++) {
            #pragma unroll
            for (int j = 0; j < 8; j++) {
                float2 fb = *(const float2*)&Kt[(j * 8 + lg) * QS + kk * 8 + 2 * lt];
                mma_tf32(accs[j][0], accs[j][1], accs[j][2], accs[j][3],
                         aq[kk][0], aq[kk][1], aq[kk][2], aq[kk][3], fb.x, fb.y);
            }
        }

        float mr0 = -1e30f, mr1 = -1e30f;
        #pragma unroll
        for (int j = 0; j < 8; j++) {
            float mb0 = MBt[j * 8 + 2 * lt];
            float mb1 = MBt[j * 8 + 2 * lt + 1];
            accs[j][0] = accs[j][0] * 0.125f + mb0;
            accs[j][1] = accs[j][1] * 0.125f + mb1;
            accs[j][2] = accs[j][2] * 0.125f + mb0;
            accs[j][3] = accs[j][3] * 0.125f + mb1;
            mr0 = fmaxf(mr0, fmaxf(accs[j][0], accs[j][1]));
            mr1 = fmaxf(mr1, fmaxf(accs[j][2], accs[j][3]));
        }
        mr0 = fmaxf(mr0, __shfl_xor_sync(0xffffffffu, mr0, 1));
        mr0 = fmaxf(mr0, __shfl_xor_sync(0xffffffffu, mr0, 2));
        mr1 = fmaxf(mr1, __shfl_xor_sync(0xffffffffu, mr1, 1));
        mr1 = fmaxf(mr1, __shfl_xor_sync(0xffffffffu, mr1, 2));

        float mn0 = fmaxf(m0, mr0), mn1 = fmaxf(m1, mr1);
        float al0 = __expf(m0 - mn0), al1 = __expf(m1 - mn1);
        m0 = mn0; m1 = mn1;

        // ---- P = exp(S - m); store to smem (non-permuted P layout) ----
        float ps0 = 0.f, ps1 = 0.f;
        #pragma unroll
        for (int j = 0; j < 8; j++) {
            float p0 = __expf(accs[j][0] - mn0);
            float p1 = __expf(accs[j][1] - mn0);
            float p2 = __expf(accs[j][2] - mn1);
            float p3 = __expf(accs[j][3] - mn1);
            ps0 += p0 + p1;
            ps1 += p2 + p3;
            int cb = j * 8 + 2 * lt;
            *(float2*)&QP[(wm + lg) * QS + cb]     = make_float2(tf32r(p0), tf32r(p1));
            *(float2*)&QP[(wm + 8 + lg) * QS + cb] = make_float2(tf32r(p2), tf32r(p3));
        }
        ps0 += __shfl_xor_sync(0xffffffffu, ps0, 1);
        ps0 += __shfl_xor_sync(0xffffffffu, ps0, 2);
        ps1 += __shfl_xor_sync(0xffffffffu, ps1, 1);
        ps1 += __shfl_xor_sync(0xffffffffu, ps1, 2);
        l0 = l0 * al0 + ps0;
        l1 = l1 * al1 + ps1;

        #pragma unroll
        for (int j = 0; j < 8; j++) {
            acc_o[j][0] *= al0; acc_o[j][1] *= al0;
            acc_o[j][2] *= al1; acc_o[j][3] *= al1;
        }
        __syncwarp();

        // ---- O += P @ V (P and V both logical layouts) ----
        #pragma unroll
        for (int kk = 0; kk < 8; kk++) {
            float a0 = QP[(wm + lg) * QS + kk * 8 + lt];
            float a1 = QP[(wm + 8 + lg) * QS + kk * 8 + lt];
            float a2 = QP[(wm + lg) * QS + kk * 8 + 4 + lt];
            float a3 = QP[(wm + 8 + lg) * QS + kk * 8 + 4 + lt];
            #pragma unroll
            for (int j = 0; j < 8; j++) {
                float b0 = Vt[(kk * 8 + lt) * VS2 + j * 8 + lg];
                float b1 = Vt[(kk * 8 + 4 + lt) * VS2 + j * 8 + lg];
                mma_tf32(acc_o[j][0], acc_o[j][1], acc_o[j][2], acc_o[j][3],
                         a0, a1, a2, a3, b0, b1);
            }
        }
        __syncthreads();
    }

    // ---- epilogue: divide by l; store d-PERMUTED for O-proj ----
    float i0 = 1.f / l0, i1 = 1.f / l1;
    int r0 = brow + wm + lg;
    int tok0 = b * S_ + r0;
    #pragma unroll
    for (int j = 0; j < 8; j++) {
        int col = h * DH_ + j * 8 + 2 * lt;   // logical
        int p = P8(col);                       // P8(col+1) == p+2
        out[(size_t)tok0 * H_ + p]           = tf32r(acc_o[j][0] * i0);
        out[(size_t)tok0 * H_ + p + 2]       = tf32r(acc_o[j][1] * i0);
        out[(size_t)(tok0 + 8) * H_ + p]     = tf32r(acc_o[j][2] * i1);
        out[(size_t)(tok0 + 8) * H_ + p + 2] = tf32r(acc_o[j][3] * i1);
    }
}

// ------- residual + LayerNorm over (ya+yb); out_r is rounded+PERMUTED ----
__global__ __launch_bounds__(256) void add_ln_kernel(
    const float* __restrict__ xin,
    const float* __restrict__ ya, const float* __restrict__ yb,
    const float* __restrict__ gamma, const float* __restrict__ beta,
    float* __restrict__ out, float* __restrict__ out_r)
{
    int t = blockIdx.x;
    int tid = threadIdx.x;
    size_t base = (size_t)t * H_;
    float v0 = ya[base + tid]       + yb[base + tid];
    float v1 = ya[base + tid + 256] + yb[base + tid + 256];
    __shared__ float s1[256], s2[256];
    s1[tid] = v0 + v1;
    s2[tid] = v0 * v0 + v1 * v1;
    __syncthreads();
    for (int off = 128; off > 0; off >>= 1) {
        if (tid < off) { s1[tid] += s1[tid + off]; s2[tid] += s2[tid + off]; }
        __syncthreads();
    }
    float mean = s1[0] * (1.f / (float)H_);
    float var  = s2[0] * (1.f / (float)H_) - mean * mean;
    float r = rsqrtf(var + 1e-5f);
    float o0 = xin[base + tid]       + (v0 - mean) * r * gamma[tid]       + beta[tid];
    float o1 = xin[base + tid + 256] + (v1 - mean) * r * gamma[tid + 256] + beta[tid + 256];
    out[base + tid]       = o0;
    out[base + tid + 256] = o1;
    out_r[base + P8(tid)]        = tf32r(o0);
    out_r[base + 256 + P8(tid)]  = tf32r(o1);
}

// ---------------- host launcher ----------------
extern "C" void kernel_launch(void* const* d_in, const int* in_sizes, int n_in,
                              void* d_out, int out_size)
{
    const int*   src  = (const int*)  d_in[0];
    const int*   mask = (const int*)  d_in[1];
    const float* emb  = (const float*)d_in[2];
    const float* Wq   = (const float*)d_in[3];
    const float* bq   = (const float*)d_in[4];
    const float* Wk   = (const float*)d_in[5];
    const float* bk   = (const float*)d_in[6];
    const float* Wv   = (const float*)d_in[7];
    const float* bv   = (const float*)d_in[8];
    const float* Wo   = (const float*)d_in[9];
    const float* bo   = (const float*)d_in[10];
    const float* gamma= (const float*)d_in[11];
    const float* beta = (const float*)d_in[12];
    const float* W1   = (const float*)d_in[13];
    const float* b1   = (const float*)d_in[14];
    const float* W2   = (const float*)d_in[15];
    const float* b2   = (const float*)d_in[16];

    float *x, *xr, *q, *k, *v, *t, *t2a, *t2b, *res, *resr, *h1, *mb, *wr;
    cudaGetSymbolAddress((void**)&x,    g_x);
    cudaGetSymbolAddress((void**)&xr,   g_xr);
    cudaGetSymbolAddress((void**)&q,    g_q);
    cudaGetSymbolAddress((void**)&k,    g_k);
    cudaGetSymbolAddress((void**)&v,    g_v);
    cudaGetSymbolAddress((void**)&t,    g_t);
    cudaGetSymbolAddress((void**)&t2a,  g_t2a);
    cudaGetSymbolAddress((void**)&t2b,  g_t2b);
    cudaGetSymbolAddress((void**)&res,  g_res);
    cudaGetSymbolAddress((void**)&resr, g_resr);
    cudaGetSymbolAddress((void**)&h1,   g_h1);
    cudaGetSymbolAddress((void**)&mb,   g_mb);
    cudaGetSymbolAddress((void**)&wr,   g_wr);

    cudaFuncSetAttribute(flash_kernel,
                         cudaFuncAttributeMaxDynamicSharedMemorySize, FLASH_SMEM);
    cudaFuncSetAttribute(gemm_tc_kernel<false, true>,
                         cudaFuncAttributeMaxDynamicSharedMemorySize, GEMM_SMEM);
    cudaFuncSetAttribute(gemm_tc_kernel<true, true>,
                         cudaFuncAttributeMaxDynamicSharedMemorySize, GEMM_SMEM);
    cudaFuncSetAttribute(gemm_tc_sk,
                         cudaFuncAttributeMaxDynamicSharedMemorySize, GEMM_SMEM);

    round_all_kernel<<<(4 * RQ_ + 2 * R1_) / 256, 256>>>(Wq, Wk, Wv, Wo, W1, W2, wr);

    embed_kernel<<<(M_ * H_) / 256, 256>>>(src, emb, x, xr);
    maskbias_kernel<<<(M_ + 255) / 256, 256>>>(mask, mb);

    dim3 gQKV (H_ / 128,  M_ / 128, 3);          // 384
    dim3 gSK  (H_ / 128,  M_ / 128, 2);          // 256 (split-K)
    dim3 gFfn1(FF_ / 128, M_ / 128, 1);          // 512
    dim3 gFlash(S_ / 128, B_ * NH_);             // 256

    for (int i = 0; i < L_; i++) {
        const float* Wq_i = wr + WOFF_Q + (size_t)i * H_ * H_;
        const float* Wk_i = wr + WOFF_K + (size_t)i * H_ * H_;
        const float* Wv_i = wr + WOFF_V + (size_t)i * H_ * H_;
        const float* Wo_i = wr + WOFF_O + (size_t)i * H_ * H_;
        const float* W1_i = wr + WOFF_1 + (size_t)i * H_ * FF_;
        const float* W2_i = wr + WOFF_2 + (size_t)i * FF_ * H_;
        const float* bq_i = bq + i * H_;
        const float* bk_i = bk + i * H_;
        const float* bv_i = bv + i * H_;
        const float* bo_i = bo + i * H_;
        const float* b1_i = b1 + i * FF_;
        const float* b2_i = b2 + i * H_;
        const float* g_i  = gamma + i * H_;
        const float* be_i = beta  + i * H_;
        float* xout = (i == L_ - 1) ? (float*)d_out : x;

        // fused QKV: q,k stored permuted (mask 0b011), v logical
        gemm_tc_kernel<false, true><<<gQKV, 256, GEMM_SMEM>>>(
            xr, Wq_i, Wk_i, Wv_i, bq_i, bk_i, bv_i, q, k, v, M_, H_, H_, 0x3);

        flash_kernel<<<gFlash, 256, FLASH_SMEM>>>(q, k, v, mb, t);

        gemm_tc_sk<<<gSK, 256, GEMM_SMEM>>>(t, Wo_i, bo_i, t2a, t2b, M_, H_, H_);
        add_ln_kernel<<<M_, 256>>>(x, t2a, t2b, g_i, be_i, res, resr);

        // FFN1: h1 stored permuted (consumed as A by FFN2)
        gemm_tc_kernel<true, true><<<gFfn1, 256, GEMM_SMEM>>>(
            resr, W1_i, W1_i, W1_i, b1_i, b1_i, b1_i, h1, h1, h1, M_, FF_, H_, 0x1);

        gemm_tc_sk<<<gSK, 256, GEMM_SMEM>>>(h1, W2_i, b2_i, t2a, t2b, M_, H_, FF_);
        add_ln_kernel<<<M_, 256>>>(res, t2a, t2b, g_i, be_i, xout, xr);
    }
}

// round 9
// speedup vs baseline: 1.0623x; 1.0623x over previous
#include <cuda_runtime.h>
#include <cuda_bf16.h>
#include <math.h>

// Problem dims
#define B_  2
#define S_  2048
#define H_  512
#define NH_ 8
#define DH_ 64
#define L_  6
#define FF_ 2048          // 4*H
#define M_  (B_*S_)       // 4096 tokens

// ---------------- device scratch (no cudaMalloc allowed) ----------------
__device__ float g_x  [M_*H_];
__device__ float g_xr [M_*H_];       // tf32-rounded copy of x (GEMM A input)
__device__ float g_q  [M_*H_];
__device__ float g_k  [M_*H_];
__device__ float g_v  [M_*H_];
__device__ float g_t  [M_*H_];
__device__ float g_t2a[M_*H_];
__device__ float g_t2b[M_*H_];
__device__ float g_res[M_*H_];
__device__ float g_resr[M_*H_];      // rounded copy of res
__device__ float g_h1 [M_*FF_];
__device__ float g_mb [M_];          // mask bias: 0 or -1e20 per (b,s)
__device__ float g_wr [18874368];    // tf32-rounded weights [Wq|Wk|Wv|Wo|W1|W2]

#define WOFF_Q  0
#define WOFF_K  (L_*H_*H_)
#define WOFF_V  (2*L_*H_*H_)
#define WOFF_O  (3*L_*H_*H_)
#define WOFF_1  (4*L_*H_*H_)
#define WOFF_2  (4*L_*H_*H_ + L_*H_*FF_)

// ---------------- helpers ----------------
__device__ __forceinline__ float tf32r(float x) {
    float y;
    asm("cvt.rna.tf32.f32 %0, %1;" : "=f"(y) : "f"(x));
    return y;
}
__device__ __forceinline__ float4 tf32r4(float4 v) {
    v.x = tf32r(v.x); v.y = tf32r(v.y); v.z = tf32r(v.z); v.w = tf32r(v.w);
    return v;
}
__device__ __forceinline__ void mma_tf32(
    float& c0, float& c1, float& c2, float& c3,
    float a0, float a1, float a2, float a3, float b0, float b1)
{
    asm volatile(
        "mma.sync.aligned.m16n8k8.row.col.f32.tf32.tf32.f32 "
        "{%0,%1,%2,%3}, {%4,%5,%6,%7}, {%8,%9}, {%0,%1,%2,%3};\n"
        : "+f"(c0), "+f"(c1), "+f"(c2), "+f"(c3)
        : "r"(__float_as_uint(a0)), "r"(__float_as_uint(a1)),
          "r"(__float_as_uint(a2)), "r"(__float_as_uint(a3)),
          "r"(__float_as_uint(b0)), "r"(__float_as_uint(b1)));
}
__device__ __forceinline__ void cp_async16(float* dst, const float* src) {
    unsigned s = (unsigned)__cvta_generic_to_shared(dst);
    asm volatile("cp.async.cg.shared.global [%0], [%1], 16;" :: "r"(s), "l"(src));
}
__device__ __forceinline__ void cp_commit() {
    asm volatile("cp.async.commit_group;");
}

// ---------------- weight rounding: all 6 tensors in one launch ----------------
#define RQ_ (L_*H_*H_/4)
#define R1_ (L_*H_*FF_/4)
__global__ __launch_bounds__(256) void round_all_kernel(
    const float* __restrict__ Wq, const float* __restrict__ Wk,
    const float* __restrict__ Wv, const float* __restrict__ Wo,
    const float* __restrict__ W1, const float* __restrict__ W2,
    float* __restrict__ dst)
{
    long i = (long)blockIdx.x * 256 + threadIdx.x;
    const float* src;
    long local;
    if (i < 4L * RQ_) {
        int region = (int)(i / RQ_);
        local = i - (long)region * RQ_;
        src = (region == 0) ? Wq : (region == 1) ? Wk : (region == 2) ? Wv : Wo;
    } else if (i < 4L * RQ_ + R1_) {
        local = i - 4L * RQ_;
        src = W1;
    } else {
        local = i - 4L * RQ_ - R1_;
        src = W2;
    }
    *(float4*)&dst[i * 4] = tf32r4(*(const float4*)&src[local * 4]);
}

// ---------------- embedding + sinusoidal posenc ----------------
__global__ __launch_bounds__(256) void embed_kernel(
    const int* __restrict__ src, const float* __restrict__ emb,
    float* __restrict__ x, float* __restrict__ xr)
{
    int idx = blockIdx.x * 256 + threadIdx.x;
    int d   = idx & (H_ - 1);
    int tok = idx >> 9;
    int s   = tok & (S_ - 1);
    int j2  = (d >> 1) * 2;
    float div = powf(10000.0f, (float)j2 * (1.0f / (float)H_));
    float arg = (float)s / div;
    float pe  = (d & 1) ? cosf(arg) : sinf(arg);
    float v = emb[(size_t)src[tok] * H_ + d] + pe;
    x[idx]  = v;
    xr[idx] = tf32r(v);
}

__global__ __launch_bounds__(256) void maskbias_kernel(
    const int* __restrict__ mask, float* __restrict__ mb)
{
    int i = blockIdx.x * 256 + threadIdx.x;
    if (i < M_) mb[i] = mask[i] ? 0.f : -1e20f;
}

// =========================================================================
// 3-stage cp.async tf32 GEMM core (R6-proven).  BM=128 BN=128 BK=32,
// 8 warps (4x2), warp tile 32x64.  outScale: exact pow2 output scaling
// (used to fold attention 1/sqrt(dh) into the Q projection).
// =========================================================================
#define GAS 36
#define GBS 136
#define GEMM_SMEM ((3 * (128 * GAS + 32 * GBS)) * 4)

template<bool RELU, bool ROUND>
__device__ __forceinline__ void gemm_core(
    const float* __restrict__ A, const float* __restrict__ W,
    const float* __restrict__ bias, float biasScale, float outScale,
    float* __restrict__ C,
    int brow, int bcol, int N, int Kfull, int koff, int Kspan)
{
    extern __shared__ float sm[];
    float* As = sm;
    float* Bs = sm + 3 * 128 * GAS;

    int tid  = threadIdx.x;
    int lane = tid & 31;
    int warp = tid >> 5;
    int warp_m = (warp >> 1) * 32;
    int warp_n = (warp & 1) * 64;
    int lg = lane >> 2, lt = lane & 3;

    int a_row0 = warp * 4 + (lane >> 3);
    int a_col  = (((lane & 7) - (lane >> 3)) & 7) * 4;
    int b_row0 = tid >> 5;
    int b_col  = lane * 4;

    auto load_tile = [&](int st, int k0) {
        float* as = As + st * 128 * GAS;
        float* bs = Bs + st * 32 * GBS;
        #pragma unroll
        for (int i = 0; i < 4; i++) {
            int r = a_row0 + i * 32;
            cp_async16(&as[r * GAS + a_col], &A[(size_t)(brow + r) * Kfull + koff + k0 + a_col]);
        }
        #pragma unroll
        for (int i = 0; i < 4; i++) {
            int r = b_row0 + i * 8;
            cp_async16(&bs[r * GBS + b_col], &W[(size_t)(koff + k0 + r) * N + bcol + b_col]);
        }
        cp_commit();
    };

    int nk = Kspan / 32;
    load_tile(0, 0);
    load_tile(1, 32);

    float acc[2][8][4];
    #pragma unroll
    for (int i = 0; i < 2; i++)
        #pragma unroll
        for (int j = 0; j < 8; j++)
            #pragma unroll
            for (int r = 0; r < 4; r++) acc[i][j][r] = 0.f;

    for (int t = 0; t < nk; t++) {
        asm volatile("cp.async.wait_group 1;");
        __syncthreads();
        if (t + 2 < nk) load_tile((t + 2) % 3, (t + 2) * 32);
        else cp_commit();

        const float* as = As + (t % 3) * 128 * GAS;
        const float* bs = Bs + (t % 3) * 32 * GBS;

        #pragma unroll
        for (int kk = 0; kk < 32; kk += 8) {
            float af[2][4];
            #pragma unroll
            for (int i = 0; i < 2; i++) {
                int mb = warp_m + i * 16;
                af[i][0] = as[(mb + lg) * GAS + kk + lt];
                af[i][1] = as[(mb + 8 + lg) * GAS + kk + lt];
                af[i][2] = as[(mb + lg) * GAS + kk + 4 + lt];
                af[i][3] = as[(mb + 8 + lg) * GAS + kk + 4 + lt];
            }
            float bf[8][2];
            #pragma unroll
            for (int j = 0; j < 8; j++) {
                int nb = warp_n + j * 8 + lg;
                bf[j][0] = bs[(kk + lt) * GBS + nb];
                bf[j][1] = bs[(kk + 4 + lt) * GBS + nb];
            }
            #pragma unroll
            for (int i = 0; i < 2; i++)
                #pragma unroll
                for (int j = 0; j < 8; j++)
                    mma_tf32(acc[i][j][0], acc[i][j][1], acc[i][j][2], acc[i][j][3],
                             af[i][0], af[i][1], af[i][2], af[i][3],
                             bf[j][0], bf[j][1]);
        }
        __syncthreads();
    }

    #pragma unroll
    for (int i = 0; i < 2; i++) {
        #pragma unroll
        for (int j = 0; j < 8; j++) {
            int col = bcol + warp_n + j * 8 + 2 * lt;
            float bx = bias[col] * biasScale, by = bias[col + 1] * biasScale;
            int r0 = brow + warp_m + i * 16 + lg;
            float2 v0 = make_float2((acc[i][j][0] + bx) * outScale,
                                    (acc[i][j][1] + by) * outScale);
            float2 v1 = make_float2((acc[i][j][2] + bx) * outScale,
                                    (acc[i][j][3] + by) * outScale);
            if (RELU) {
                v0.x = fmaxf(v0.x, 0.f); v0.y = fmaxf(v0.y, 0.f);
                v1.x = fmaxf(v1.x, 0.f); v1.y = fmaxf(v1.y, 0.f);
            }
            if (ROUND) {
                v0.x = tf32r(v0.x); v0.y = tf32r(v0.y);
                v1.x = tf32r(v1.x); v1.y = tf32r(v1.y);
            }
            *(float2*)&C[(size_t)r0 * N + col]       = v0;
            *(float2*)&C[(size_t)(r0 + 8) * N + col] = v1;
        }
    }
}

template<bool RELU, bool ROUND>
__global__ __launch_bounds__(256, 2) void gemm_tc_kernel(
    const float* __restrict__ A,
    const float* __restrict__ Wa, const float* __restrict__ Wb, const float* __restrict__ Wc,
    const float* __restrict__ ba, const float* __restrict__ bb, const float* __restrict__ bc,
    float* __restrict__ Ca, float* __restrict__ Cb_, float* __restrict__ Cc,
    int M, int N, int K, float scale0)
{
    int z = blockIdx.z;
    const float* W    = (z == 0) ? Wa : (z == 1) ? Wb : Wc;
    const float* bias = (z == 0) ? ba : (z == 1) ? bb : bc;
    float*       C    = (z == 0) ? Ca : (z == 1) ? Cb_ : Cc;
    float sc = (z == 0) ? scale0 : 1.f;
    gemm_core<RELU, ROUND>(A, W, bias, 1.f, sc, C,
                           blockIdx.y * 128, blockIdx.x * 128, N, K, 0, K);
}

// split-K=2: z selects K-half; bias only on z==0
__global__ __launch_bounds__(256, 2) void gemm_tc_sk(
    const float* __restrict__ A, const float* __restrict__ W,
    const float* __restrict__ bias,
    float* __restrict__ C0, float* __restrict__ C1,
    int M, int N, int K)
{
    int z = blockIdx.z;
    int Kh = K >> 1;
    gemm_core<false, false>(A, W, bias, z == 0 ? 1.f : 0.f, 1.f,
                            z == 0 ? C0 : C1,
                            blockIdx.y * 128, blockIdx.x * 128, N, K, z * Kh, Kh);
}

// =========================================================================
// Fused flash attention.  q is PRE-SCALED by 0.125 at the QKV epilogue.
// Skip-rescale fast path when no row max changed this tile.
// =========================================================================
#define QS  68
#define VS2 72
#define NKV (S_ / 64)
#define FLASH_SMEM ((128 * QS + 2 * 64 * QS + 2 * 64 * VS2 + 2 * 64) * 4)

__global__ __launch_bounds__(256) void flash_kernel(
    const float* __restrict__ q, const float* __restrict__ k,
    const float* __restrict__ v, const float* __restrict__ mbias,
    float* __restrict__ out)
{
    extern __shared__ float sm[];
    float* QP = sm;
    float* Ks = QP + 128 * QS;
    float* Vs = Ks + 2 * 64 * QS;
    float* MB = Vs + 2 * 64 * VS2;

    int tid  = threadIdx.x;
    int lane = tid & 31;
    int warp = tid >> 5;
    int wm   = warp * 16;
    int lg = lane >> 2, lt = lane & 3;
    int brow = blockIdx.x * 128;
    int bh = blockIdx.y;
    int b = bh >> 3, h = bh & 7;

    const float* Qb  = q + (size_t)b * S_ * H_ + h * DH_;
    const float* Kb  = k + (size_t)b * S_ * H_ + h * DH_;
    const float* Vb  = v + (size_t)b * S_ * H_ + h * DH_;
    const float* MBg = mbias + b * S_;

    #pragma unroll
    for (int i = 0; i < 8; i++) {
        int f4 = tid + i * 256;
        int r = f4 >> 4, c = (f4 & 15) * 4;
        *(float4*)&QP[r * QS + c] = *(const float4*)&Qb[(size_t)(brow + r) * H_ + c];
    }
    __syncthreads();

    float aq[8][4];
    #pragma unroll
    for (int kk = 0; kk < 8; kk++) {
        aq[kk][0] = QP[(wm + lg) * QS + kk * 8 + lt];
        aq[kk][1] = QP[(wm + 8 + lg) * QS + kk * 8 + lt];
        aq[kk][2] = QP[(wm + lg) * QS + kk * 8 + 4 + lt];
        aq[kk][3] = QP[(wm + 8 + lg) * QS + kk * 8 + 4 + lt];
    }
    __syncthreads();

    float acc_o[8][4];
    #pragma unroll
    for (int j = 0; j < 8; j++)
        #pragma unroll
        for (int rr = 0; rr < 4; rr++) acc_o[j][rr] = 0.f;
    float m0 = -1e30f, m1 = -1e30f, l0 = 0.f, l1 = 0.f;

    auto load_kv = [&](int buf, int it) {
        int kv0 = it * 64;
        float* kd = Ks + buf * 64 * QS;
        float* vd = Vs + buf * 64 * VS2;
        #pragma unroll
        for (int i = 0; i < 4; i++) {
            int f4 = tid + i * 256;
            int r = f4 >> 4, c = (f4 & 15) * 4;
            cp_async16(&kd[r * QS + c],  &Kb[(size_t)(kv0 + r) * H_ + c]);
            cp_async16(&vd[r * VS2 + c], &Vb[(size_t)(kv0 + r) * H_ + c]);
        }
        if (tid < 16) cp_async16(&MB[buf * 64 + tid * 4], &MBg[kv0 + tid * 4]);
    };

    load_kv(0, 0);
    cp_commit();

    for (int it = 0; it < NKV; it++) {
        int buf = it & 1;
        if (it + 1 < NKV) {
            load_kv(buf ^ 1, it + 1);
            cp_commit();
            asm volatile("cp.async.wait_group 1;");
        } else {
            asm volatile("cp.async.wait_group 0;");
        }
        __syncthreads();

        const float* Kt  = Ks + buf * 64 * QS;
        const float* Vt  = Vs + buf * 64 * VS2;
        const float* MBt = MB + buf * 64;

        // ---- S = Qs @ K^T (q pre-scaled by 1/8) ----
        float accs[8][4];
        #pragma unroll
        for (int j = 0; j < 8; j++)
            #pragma unroll
            for (int rr = 0; rr < 4; rr++) accs[j][rr] = 0.f;
        #pragma unroll
        for (int kk = 0; kk < 8; kk++) {
            #pragma unroll
            for (int j = 0; j < 8; j++) {
                float b0 = Kt[(j * 8 + lg) * QS + kk * 8 + lt];
                float b1 = Kt[(j * 8 + lg) * QS + kk * 8 + 4 + lt];
                mma_tf32(accs[j][0], accs[j][1], accs[j][2], accs[j][3],
                         aq[kk][0], aq[kk][1], aq[kk][2], aq[kk][3], b0, b1);
            }
        }

        // ---- + mask bias, row max ----
        float mr0 = -1e30f, mr1 = -1e30f;
        #pragma unroll
        for (int j = 0; j < 8; j++) {
            float2 mbv = *(const float2*)&MBt[j * 8 + 2 * lt];
            accs[j][0] += mbv.x;
            accs[j][1] += mbv.y;
            accs[j][2] += mbv.x;
            accs[j][3] += mbv.y;
            mr0 = fmaxf(mr0, fmaxf(accs[j][0], accs[j][1]));
            mr1 = fmaxf(mr1, fmaxf(accs[j][2], accs[j][3]));
        }
        mr0 = fmaxf(mr0, __shfl_xor_sync(0xffffffffu, mr0, 1));
        mr0 = fmaxf(mr0, __shfl_xor_sync(0xffffffffu, mr0, 2));
        mr1 = fmaxf(mr1, __shfl_xor_sync(0xffffffffu, mr1, 1));
        mr1 = fmaxf(mr1, __shfl_xor_sync(0xffffffffu, mr1, 2));

        float mn0 = fmaxf(m0, mr0), mn1 = fmaxf(m1, mr1);
        float al0 = __expf(m0 - mn0), al1 = __expf(m1 - mn1);
        m0 = mn0; m1 = mn1;

        // ---- P = exp(S - m), row sums, store P to smem (tf32) ----
        float ps0 = 0.f, ps1 = 0.f;
        #pragma unroll
        for (int j = 0; j < 8; j++) {
            float p0 = __expf(accs[j][0] - mn0);
            float p1 = __expf(accs[j][1] - mn0);
            float p2 = __expf(accs[j][2] - mn1);
            float p3 = __expf(accs[j][3] - mn1);
            ps0 += p0 + p1;
            ps1 += p2 + p3;
            int cb = j * 8 + 2 * lt;
            *(float2*)&QP[(wm + lg) * QS + cb]     = make_float2(tf32r(p0), tf32r(p1));
            *(float2*)&QP[(wm + 8 + lg) * QS + cb] = make_float2(tf32r(p2), tf32r(p3));
        }
        ps0 += __shfl_xor_sync(0xffffffffu, ps0, 1);
        ps0 += __shfl_xor_sync(0xffffffffu, ps0, 2);
        ps1 += __shfl_xor_sync(0xffffffffu, ps1, 1);
        ps1 += __shfl_xor_sync(0xffffffffu, ps1, 2);
        l0 = l0 * al0 + ps0;
        l1 = l1 * al1 + ps1;

        // rescale running output only if some row max changed (skip is exact:
        // al==1.0 means multiply-by-1, a no-op)
        if (!__all_sync(0xffffffffu, (al0 == 1.f) && (al1 == 1.f))) {
            #pragma unroll
            for (int j = 0; j < 8; j++) {
                acc_o[j][0] *= al0; acc_o[j][1] *= al0;
                acc_o[j][2] *= al1; acc_o[j][3] *= al1;
            }
        }
        __syncwarp();

        // ---- O += P @ V ----
        #pragma unroll
        for (int kk = 0; kk < 8; kk++) {
            float a0 = QP[(wm + lg) * QS + kk * 8 + lt];
            float a1 = QP[(wm + 8 + lg) * QS + kk * 8 + lt];
            float a2 = QP[(wm + lg) * QS + kk * 8 + 4 + lt];
            float a3 = QP[(wm + 8 + lg) * QS + kk * 8 + 4 + lt];
            #pragma unroll
            for (int j = 0; j < 8; j++) {
                float b0 = Vt[(kk * 8 + lt) * VS2 + j * 8 + lg];
                float b1 = Vt[(kk * 8 + 4 + lt) * VS2 + j * 8 + lg];
                mma_tf32(acc_o[j][0], acc_o[j][1], acc_o[j][2], acc_o[j][3],
                         a0, a1, a2, a3, b0, b1);
            }
        }
        __syncthreads();
    }

    float i0 = 1.f / l0, i1 = 1.f / l1;
    int r0 = brow + wm + lg;
    int tok0 = b * S_ + r0;
    #pragma unroll
    for (int j = 0; j < 8; j++) {
        int col = h * DH_ + j * 8 + 2 * lt;
        *(float2*)&out[(size_t)tok0 * H_ + col] =
            make_float2(tf32r(acc_o[j][0] * i0), tf32r(acc_o[j][1] * i0));
        *(float2*)&out[(size_t)(tok0 + 8) * H_ + col] =
            make_float2(tf32r(acc_o[j][2] * i1), tf32r(acc_o[j][3] * i1));
    }
}

// ------- residual + LayerNorm over (ya+yb), dual output (raw + rounded) ----
__global__ __launch_bounds__(256) void add_ln_kernel(
    const float* __restrict__ xin,
    const float* __restrict__ ya, const float* __restrict__ yb,
    const float* __restrict__ gamma, const float* __restrict__ beta,
    float* __restrict__ out, float* __restrict__ out_r)
{
    int t = blockIdx.x;
    int tid = threadIdx.x;
    size_t base = (size_t)t * H_;
    float v0 = ya[base + tid]       + yb[base + tid];
    float v1 = ya[base + tid + 256] + yb[base + tid + 256];
    __shared__ float s1[256], s2[256];
    s1[tid] = v0 + v1;
    s2[tid] = v0 * v0 + v1 * v1;
    __syncthreads();
    for (int off = 128; off > 0; off >>= 1) {
        if (tid < off) { s1[tid] += s1[tid + off]; s2[tid] += s2[tid + off]; }
        __syncthreads();
    }
    float mean = s1[0] * (1.f / (float)H_);
    float var  = s2[0] * (1.f / (float)H_) - mean * mean;
    float r = rsqrtf(var + 1e-5f);
    float o0 = xin[base + tid]       + (v0 - mean) * r * gamma[tid]       + beta[tid];
    float o1 = xin[base + tid + 256] + (v1 - mean) * r * gamma[tid + 256] + beta[tid + 256];
    out[base + tid]         = o0;
    out[base + tid + 256]   = o1;
    out_r[base + tid]       = tf32r(o0);
    out_r[base + tid + 256] = tf32r(o1);
}

// ---------------- host launcher ----------------
extern "C" void kernel_launch(void* const* d_in, const int* in_sizes, int n_in,
                              void* d_out, int out_size)
{
    const int*   src  = (const int*)  d_in[0];
    const int*   mask = (const int*)  d_in[1];
    const float* emb  = (const float*)d_in[2];
    const float* Wq   = (const float*)d_in[3];
    const float* bq   = (const float*)d_in[4];
    const float* Wk   = (const float*)d_in[5];
    const float* bk   = (const float*)d_in[6];
    const float* Wv   = (const float*)d_in[7];
    const float* bv   = (const float*)d_in[8];
    const float* Wo   = (const float*)d_in[9];
    const float* bo   = (const float*)d_in[10];
    const float* gamma= (const float*)d_in[11];
    const float* beta = (const float*)d_in[12];
    const float* W1   = (const float*)d_in[13];
    const float* b1   = (const float*)d_in[14];
    const float* W2   = (const float*)d_in[15];
    const float* b2   = (const float*)d_in[16];

    float *x, *xr, *q, *k, *v, *t, *t2a, *t2b, *res, *resr, *h1, *mb, *wr;
    cudaGetSymbolAddress((void**)&x,    g_x);
    cudaGetSymbolAddress((void**)&xr,   g_xr);
    cudaGetSymbolAddress((void**)&q,    g_q);
    cudaGetSymbolAddress((void**)&k,    g_k);
    cudaGetSymbolAddress((void**)&v,    g_v);
    cudaGetSymbolAddress((void**)&t,    g_t);
    cudaGetSymbolAddress((void**)&t2a,  g_t2a);
    cudaGetSymbolAddress((void**)&t2b,  g_t2b);
    cudaGetSymbolAddress((void**)&res,  g_res);
    cudaGetSymbolAddress((void**)&resr, g_resr);
    cudaGetSymbolAddress((void**)&h1,   g_h1);
    cudaGetSymbolAddress((void**)&mb,   g_mb);
    cudaGetSymbolAddress((void**)&wr,   g_wr);

    cudaFuncSetAttribute(flash_kernel,
                         cudaFuncAttributeMaxDynamicSharedMemorySize, FLASH_SMEM);
    cudaFuncSetAttribute(gemm_tc_kernel<false, true>,
                         cudaFuncAttributeMaxDynamicSharedMemorySize, GEMM_SMEM);
    cudaFuncSetAttribute(gemm_tc_kernel<true, true>,
                         cudaFuncAttributeMaxDynamicSharedMemorySize, GEMM_SMEM);
    cudaFuncSetAttribute(gemm_tc_sk,
                         cudaFuncAttributeMaxDynamicSharedMemorySize, GEMM_SMEM);

    round_all_kernel<<<(4 * RQ_ + 2 * R1_) / 256, 256>>>(Wq, Wk, Wv, Wo, W1, W2, wr);

    embed_kernel<<<(M_ * H_) / 256, 256>>>(src, emb, x, xr);
    maskbias_kernel<<<(M_ + 255) / 256, 256>>>(mask, mb);

    dim3 gQKV (H_ / 128,  M_ / 128, 3);          // 384
    dim3 gSK  (H_ / 128,  M_ / 128, 2);          // 256 (split-K)
    dim3 gFfn1(FF_ / 128, M_ / 128, 1);          // 512
    dim3 gFlash(S_ / 128, B_ * NH_);             // 256

    for (int i = 0; i < L_; i++) {
        const float* Wq_i = wr + WOFF_Q + (size_t)i * H_ * H_;
        const float* Wk_i = wr + WOFF_K + (size_t)i * H_ * H_;
        const float* Wv_i = wr + WOFF_V + (size_t)i * H_ * H_;
        const float* Wo_i = wr + WOFF_O + (size_t)i * H_ * H_;
        const float* W1_i = wr + WOFF_1 + (size_t)i * H_ * FF_;
        const float* W2_i = wr + WOFF_2 + (size_t)i * FF_ * H_;
        const float* bq_i = bq + i * H_;
        const float* bk_i = bk + i * H_;
        const float* bv_i = bv + i * H_;
        const float* bo_i = bo + i * H_;
        const float* b1_i = b1 + i * FF_;
        const float* b2_i = b2 + i * H_;
        const float* g_i  = gamma + i * H_;
        const float* be_i = beta  + i * H_;
        float* xout = (i == L_ - 1) ? (float*)d_out : x;

        // fused QKV; Q (z==0) pre-scaled by 1/8 (exact pow2)
        gemm_tc_kernel<false, true><<<gQKV, 256, GEMM_SMEM>>>(
            xr, Wq_i, Wk_i, Wv_i, bq_i, bk_i, bv_i, q, k, v, M_, H_, H_, 0.125f);

        flash_kernel<<<gFlash, 256, FLASH_SMEM>>>(q, k, v, mb, t);

        gemm_tc_sk<<<gSK, 256, GEMM_SMEM>>>(t, Wo_i, bo_i, t2a, t2b, M_, H_, H_);
        add_ln_kernel<<<M_, 256>>>(x, t2a, t2b, g_i, be_i, res, resr);

        gemm_tc_kernel<true, true><<<gFfn1, 256, GEMM_SMEM>>>(
            resr, W1_i, W1_i, W1_i, b1_i, b1_i, b1_i, h1, h1, h1, M_, FF_, H_, 1.f);

        gemm_tc_sk<<<gSK, 256, GEMM_SMEM>>>(h1, W2_i, b2_i, t2a, t2b, M_, H_, FF_);
        add_ln_kernel<<<M_, 256>>>(res, t2a, t2b, g_i, be_i, xout, xr);
    }
}

// round 10
// speedup vs baseline: 1.6432x; 1.5469x over previous
#include <cuda_runtime.h>
#include <cuda_fp16.h>
#include <math.h>
#include <stdint.h>

// Problem dims
#define B_  2
#define S_  2048
#define H_  512
#define NH_ 8
#define DH_ 64
#define L_  6
#define FF_ 2048
#define M_  (B_*S_)

// ---------------- device scratch ----------------
__device__ float  g_x  [M_*H_];
__device__ float  g_res[M_*H_];
__device__ float  g_t2a[M_*H_];
__device__ float  g_t2b[M_*H_];
__device__ float  g_mb [M_];
__device__ __half g_xr [M_*H_];     // half activations (GEMM A inputs)
__device__ __half g_q  [M_*H_];
__device__ __half g_k  [M_*H_];
__device__ __half g_vt [M_*H_];     // V TRANSPOSED: [(b*512+d)][s]
__device__ __half g_t  [M_*H_];     // flash out
__device__ __half g_resr[M_*H_];
__device__ __half g_h1 [M_*FF_];
__device__ __half g_wh [18874368];  // transposed half weights [N][K] per matrix

#define WOFF_Q  0
#define WOFF_K  (L_*H_*H_)
#define WOFF_V  (2*L_*H_*H_)
#define WOFF_O  (3*L_*H_*H_)
#define WOFF_1  (4*L_*H_*H_)
#define WOFF_2  (4*L_*H_*H_ + L_*H_*FF_)

// ---------------- helpers ----------------
__device__ __forceinline__ void mma_f16(
    float& c0, float& c1, float& c2, float& c3,
    uint32_t a0, uint32_t a1, uint32_t a2, uint32_t a3,
    uint32_t b0, uint32_t b1)
{
    asm volatile(
        "mma.sync.aligned.m16n8k16.row.col.f32.f16.f16.f32 "
        "{%0,%1,%2,%3}, {%4,%5,%6,%7}, {%8,%9}, {%0,%1,%2,%3};\n"
        : "+f"(c0), "+f"(c1), "+f"(c2), "+f"(c3)
        : "r"(a0), "r"(a1), "r"(a2), "r"(a3), "r"(b0), "r"(b1));
}
__device__ __forceinline__ uint32_t pack_h2(float lo, float hi) {
    __half2 h = __floats2half2_rn(lo, hi);
    return *(uint32_t*)&h;
}
__device__ __forceinline__ void cp_async16f(float* dst, const float* src) {
    unsigned s = (unsigned)__cvta_generic_to_shared(dst);
    asm volatile("cp.async.cg.shared.global [%0], [%1], 16;" :: "r"(s), "l"(src));
}
__device__ __forceinline__ void cp_async16h(__half* dst, const __half* src) {
    unsigned s = (unsigned)__cvta_generic_to_shared(dst);
    asm volatile("cp.async.cg.shared.global [%0], [%1], 16;" :: "r"(s), "l"(src));
}
__device__ __forceinline__ void cp_commit() {
    asm volatile("cp.async.commit_group;");
}
#define LD32(p) (*(const uint32_t*)(p))

// ---------------- weight transpose + round to half ----------------
// dst[n][k] = half(src[k][n]) ; per layer via blockIdx.z
__global__ __launch_bounds__(256) void transpose_half_kernel(
    const float* __restrict__ src, __half* __restrict__ dst, int K, int N)
{
    __shared__ float tile[32][33];
    size_t lo = (size_t)blockIdx.z * K * N;
    const float* s = src + lo;
    __half* d = dst + lo;
    int n0 = blockIdx.x * 32, k0 = blockIdx.y * 32;
    int tx = threadIdx.x, ty = threadIdx.y;
    #pragma unroll
    for (int i = 0; i < 4; i++)
        tile[ty + i * 8][tx] = s[(size_t)(k0 + ty + i * 8) * N + n0 + tx];
    __syncthreads();
    #pragma unroll
    for (int i = 0; i < 4; i++)
        d[(size_t)(n0 + ty + i * 8) * K + k0 + tx] =
            __float2half_rn(tile[tx][ty + i * 8]);
}

// ---------------- embedding + posenc ----------------
__global__ __launch_bounds__(256) void embed_kernel(
    const int* __restrict__ src, const float* __restrict__ emb,
    float* __restrict__ x, __half* __restrict__ xr)
{
    int idx = blockIdx.x * 256 + threadIdx.x;
    int d   = idx & (H_ - 1);
    int tok = idx >> 9;
    int s   = tok & (S_ - 1);
    int j2  = (d >> 1) * 2;
    float div = powf(10000.0f, (float)j2 * (1.0f / (float)H_));
    float arg = (float)s / div;
    float pe  = (d & 1) ? cosf(arg) : sinf(arg);
    float v = emb[(size_t)src[tok] * H_ + d] + pe;
    x[idx]  = v;
    xr[idx] = __float2half_rn(v);
}

__global__ __launch_bounds__(256) void maskbias_kernel(
    const int* __restrict__ mask, float* __restrict__ mb)
{
    int i = blockIdx.x * 256 + threadIdx.x;
    if (i < M_) mb[i] = mask[i] ? 0.f : -1e20f;
}

// =========================================================================
// fp16 GEMM core: C = A[M,K] @ Wt^T + bias.  A half [M][K]; Wt half [N][K].
// BM=128 BN=128 BK=32 halves.  8 warps (4x2), warp tile 32x64, m16n8k16.
// 3-stage cp.async pipeline.  smem rows padded to 40 halves (bank-free).
// OUT: 0 = float C, 1 = half C, 2 = half V-transposed scatter.
// =========================================================================
#define GST 40                       // smem row stride (halves)
#define STAGE_H (128 * GST)          // halves per operand per stage
#define GEMM_SMEM (3 * 2 * STAGE_H * 2)   // 3 stages * (A+B) * 2B = 61440

template<bool RELU, int OUT>
__device__ __forceinline__ void gemm_core(
    const __half* __restrict__ A, const __half* __restrict__ Wt,
    const float* __restrict__ bias, float biasScale, float outScale,
    void* Cv, int brow, int bcol, int N, int Kfull, int koff, int Kspan)
{
    extern __shared__ char smraw[];
    __half* sbase = (__half*)smraw;

    int tid  = threadIdx.x;
    int lane = tid & 31;
    int warp = tid >> 5;
    int warp_m = (warp >> 1) * 32;
    int warp_n = (warp & 1) * 64;
    int lg = lane >> 2, lt = lane & 3;

    auto load_tile = [&](int st, int k0) {
        __half* as = sbase + st * 2 * STAGE_H;
        __half* bs = as + STAGE_H;
        #pragma unroll
        for (int i = 0; i < 2; i++) {
            int ci = tid + i * 256;            // 512 chunks each matrix
            int r = ci >> 2, c16 = ci & 3;     // 4 chunks of 8 halves per row
            cp_async16h(as + r * GST + c16 * 8,
                        A  + (size_t)(brow + r) * Kfull + koff + k0 + c16 * 8);
            cp_async16h(bs + r * GST + c16 * 8,
                        Wt + (size_t)(bcol + r) * Kfull + koff + k0 + c16 * 8);
        }
        cp_commit();
    };

    int nk = Kspan / 32;
    load_tile(0, 0);
    load_tile(1, 32);

    float acc[2][8][4];
    #pragma unroll
    for (int i = 0; i < 2; i++)
        #pragma unroll
        for (int j = 0; j < 8; j++)
            #pragma unroll
            for (int r = 0; r < 4; r++) acc[i][j][r] = 0.f;

    for (int t = 0; t < nk; t++) {
        asm volatile("cp.async.wait_group 1;");
        __syncthreads();
        if (t + 2 < nk) load_tile((t + 2) % 3, (t + 2) * 32);
        else cp_commit();

        const __half* as = sbase + (t % 3) * 2 * STAGE_H;
        const __half* bs = as + STAGE_H;

        #pragma unroll
        for (int ks = 0; ks < 32; ks += 16) {
            uint32_t af[2][4];
            #pragma unroll
            for (int i = 0; i < 2; i++) {
                int mb = warp_m + i * 16;
                af[i][0] = LD32(as + (mb + lg) * GST + ks + 2 * lt);
                af[i][1] = LD32(as + (mb + 8 + lg) * GST + ks + 2 * lt);
                af[i][2] = LD32(as + (mb + lg) * GST + ks + 8 + 2 * lt);
                af[i][3] = LD32(as + (mb + 8 + lg) * GST + ks + 8 + 2 * lt);
            }
            uint32_t bf[8][2];
            #pragma unroll
            for (int j = 0; j < 8; j++) {
                int nb = warp_n + j * 8 + lg;
                bf[j][0] = LD32(bs + nb * GST + ks + 2 * lt);
                bf[j][1] = LD32(bs + nb * GST + ks + 8 + 2 * lt);
            }
            #pragma unroll
            for (int i = 0; i < 2; i++)
                #pragma unroll
                for (int j = 0; j < 8; j++)
                    mma_f16(acc[i][j][0], acc[i][j][1], acc[i][j][2], acc[i][j][3],
                            af[i][0], af[i][1], af[i][2], af[i][3],
                            bf[j][0], bf[j][1]);
        }
        __syncthreads();
    }

    #pragma unroll
    for (int i = 0; i < 2; i++) {
        #pragma unroll
        for (int j = 0; j < 8; j++) {
            int col = bcol + warp_n + j * 8 + 2 * lt;
            float bx = bias[col] * biasScale, by = bias[col + 1] * biasScale;
            int r0 = brow + warp_m + i * 16 + lg;
            float v0x = (acc[i][j][0] + bx) * outScale;
            float v0y = (acc[i][j][1] + by) * outScale;
            float v1x = (acc[i][j][2] + bx) * outScale;
            float v1y = (acc[i][j][3] + by) * outScale;
            if (RELU) {
                v0x = fmaxf(v0x, 0.f); v0y = fmaxf(v0y, 0.f);
                v1x = fmaxf(v1x, 0.f); v1y = fmaxf(v1y, 0.f);
            }
            if (OUT == 0) {
                float* C = (float*)Cv;
                *(float2*)&C[(size_t)r0 * N + col]       = make_float2(v0x, v0y);
                *(float2*)&C[(size_t)(r0 + 8) * N + col] = make_float2(v1x, v1y);
            } else if (OUT == 1) {
                __half* C = (__half*)Cv;
                *(__half2*)&C[(size_t)r0 * N + col]       = __floats2half2_rn(v0x, v0y);
                *(__half2*)&C[(size_t)(r0 + 8) * N + col] = __floats2half2_rn(v1x, v1y);
            } else {
                // V transposed: vt[(b*512 + col)][s]
                __half* C = (__half*)Cv;
                int bb = r0 >> 11, s = r0 & 2047;
                size_t base0 = (size_t)(bb * 512 + col) * 2048;
                size_t base1 = (size_t)(bb * 512 + col + 1) * 2048;
                C[base0 + s]     = __float2half_rn(v0x);
                C[base1 + s]     = __float2half_rn(v0y);
                C[base0 + s + 8] = __float2half_rn(v1x);
                C[base1 + s + 8] = __float2half_rn(v1y);
            }
        }
    }
}

// fused QKV: z=0 -> q (half, x0.125), z=1 -> k (half), z=2 -> vt (transposed)
__global__ __launch_bounds__(256, 2) void gemm_qkv(
    const __half* __restrict__ A,
    const __half* __restrict__ Wq, const __half* __restrict__ Wk, const __half* __restrict__ Wv,
    const float* __restrict__ bq, const float* __restrict__ bk, const float* __restrict__ bv,
    __half* q, __half* k, __half* vt, int N, int K)
{
    int z = blockIdx.z;
    if (z == 0)
        gemm_core<false, 1>(A, Wq, bq, 1.f, 0.125f, q,
                            blockIdx.y * 128, blockIdx.x * 128, N, K, 0, K);
    else if (z == 1)
        gemm_core<false, 1>(A, Wk, bk, 1.f, 1.f, k,
                            blockIdx.y * 128, blockIdx.x * 128, N, K, 0, K);
    else
        gemm_core<false, 2>(A, Wv, bv, 1.f, 1.f, vt,
                            blockIdx.y * 128, blockIdx.x * 128, N, K, 0, K);
}

// FFN1: half out + ReLU
__global__ __launch_bounds__(256, 2) void gemm_h(
    const __half* __restrict__ A, const __half* __restrict__ Wt,
    const float* __restrict__ bias, __half* C, int N, int K)
{
    gemm_core<true, 1>(A, Wt, bias, 1.f, 1.f, C,
                       blockIdx.y * 128, blockIdx.x * 128, N, K, 0, K);
}

// split-K=2: float partial outputs; bias on z==0
__global__ __launch_bounds__(256, 2) void gemm_sk(
    const __half* __restrict__ A, const __half* __restrict__ Wt,
    const float* __restrict__ bias, float* C0, float* C1, int N, int K)
{
    int z = blockIdx.z;
    int Kh = K >> 1;
    gemm_core<false, 0>(A, Wt, bias, z == 0 ? 1.f : 0.f, 1.f,
                        z == 0 ? (void*)C0 : (void*)C1,
                        blockIdx.y * 128, blockIdx.x * 128, N, K, z * Kh, Kh);
}

// =========================================================================
// fp16 flash attention.  q prescaled by 1/8.  P kept in registers
// (QK C-fragment layout == PV A-fragment layout for m16n8k16).
// K smem [kv][d]; V smem [d][kv] (from transposed gmem).  Stride 72 halves.
// =========================================================================
#define FQS 72
#define NKV (S_ / 64)
#define FLASH_SMEM (128*FQS*2 + 2*64*FQS*2 + 2*64*FQS*2 + 2*64*4)

__global__ __launch_bounds__(256) void flash_kernel(
    const __half* __restrict__ q, const __half* __restrict__ k,
    const __half* __restrict__ vt, const float* __restrict__ mbias,
    __half* __restrict__ out)
{
    extern __shared__ char smraw[];
    __half* Qh  = (__half*)smraw;
    __half* Ksm = Qh + 128 * FQS;
    __half* Vsm = Ksm + 2 * 64 * FQS;
    float*  MB  = (float*)(Vsm + 2 * 64 * FQS);

    int tid  = threadIdx.x;
    int lane = tid & 31;
    int warp = tid >> 5;
    int wm   = warp * 16;
    int lg = lane >> 2, lt = lane & 3;
    int brow = blockIdx.x * 128;
    int bh = blockIdx.y;
    int b = bh >> 3, h = bh & 7;

    const __half* Qb  = q  + (size_t)b * S_ * H_ + h * DH_;
    const __half* Kb  = k  + (size_t)b * S_ * H_ + h * DH_;
    const __half* Vtb = vt + (size_t)(b * 512 + h * 64) * 2048;
    const float*  MBg = mbias + b * S_;

    auto load_kv = [&](int buf, int it) {
        int kv0 = it * 64;
        __half* kd = Ksm + buf * 64 * FQS;
        __half* vd = Vsm + buf * 64 * FQS;
        #pragma unroll
        for (int i = 0; i < 2; i++) {
            int ci = tid + i * 256;          // 512 chunks per matrix
            int r = ci >> 3, c8 = ci & 7;    // 8 chunks of 8 halves per row
            cp_async16h(kd + r * FQS + c8 * 8,
                        Kb + (size_t)(kv0 + r) * H_ + c8 * 8);
            cp_async16h(vd + r * FQS + c8 * 8,
                        Vtb + (size_t)r * S_ + kv0 + c8 * 8);
        }
        if (tid < 16) cp_async16f(&MB[buf * 64 + tid * 4], MBg + kv0 + tid * 4);
        cp_commit();
    };

    // Q tile load (group 1) then kv0 (group 2)
    #pragma unroll
    for (int i = 0; i < 4; i++) {
        int ci = tid + i * 256;              // 1024 chunks
        int r = ci >> 3, c8 = ci & 7;
        cp_async16h(Qh + r * FQS + c8 * 8,
                    Qb + (size_t)(brow + r) * H_ + c8 * 8);
    }
    cp_commit();
    load_kv(0, 0);
    asm volatile("cp.async.wait_group 1;");  // Q done; kv0 may be in flight
    __syncthreads();

    // preload Q fragments: aq[ks][0..3] (u32 packed half2)
    uint32_t aq[4][4];
    #pragma unroll
    for (int ks = 0; ks < 4; ks++) {
        aq[ks][0] = LD32(Qh + (wm + lg) * FQS + ks * 16 + 2 * lt);
        aq[ks][1] = LD32(Qh + (wm + 8 + lg) * FQS + ks * 16 + 2 * lt);
        aq[ks][2] = LD32(Qh + (wm + lg) * FQS + ks * 16 + 8 + 2 * lt);
        aq[ks][3] = LD32(Qh + (wm + 8 + lg) * FQS + ks * 16 + 8 + 2 * lt);
    }

    float acc_o[8][4];
    #pragma unroll
    for (int j = 0; j < 8; j++)
        #pragma unroll
        for (int rr = 0; rr < 4; rr++) acc_o[j][rr] = 0.f;
    float m0 = -1e30f, m1 = -1e30f, l0 = 0.f, l1 = 0.f;

    for (int it = 0; it < NKV; it++) {
        int buf = it & 1;
        if (it + 1 < NKV) {
            load_kv(buf ^ 1, it + 1);
            asm volatile("cp.async.wait_group 1;");
        } else {
            asm volatile("cp.async.wait_group 0;");
        }
        __syncthreads();

        const __half* Kt  = Ksm + buf * 64 * FQS;
        const __half* Vt  = Vsm + buf * 64 * FQS;
        const float*  MBt = MB + buf * 64;

        // ---- S = Qs @ K^T ----
        float accs[8][4];
        #pragma unroll
        for (int j = 0; j < 8; j++)
            #pragma unroll
            for (int rr = 0; rr < 4; rr++) accs[j][rr] = 0.f;
        #pragma unroll
        for (int ks = 0; ks < 4; ks++) {
            #pragma unroll
            for (int j = 0; j < 8; j++) {
                uint32_t b0 = LD32(Kt + (j * 8 + lg) * FQS + ks * 16 + 2 * lt);
                uint32_t b1 = LD32(Kt + (j * 8 + lg) * FQS + ks * 16 + 8 + 2 * lt);
                mma_f16(accs[j][0], accs[j][1], accs[j][2], accs[j][3],
                        aq[ks][0], aq[ks][1], aq[ks][2], aq[ks][3], b0, b1);
            }
        }

        // ---- + mask bias, row max ----
        float mr0 = -1e30f, mr1 = -1e30f;
        #pragma unroll
        for (int j = 0; j < 8; j++) {
            float2 mbv = *(const float2*)&MBt[j * 8 + 2 * lt];
            accs[j][0] += mbv.x;
            accs[j][1] += mbv.y;
            accs[j][2] += mbv.x;
            accs[j][3] += mbv.y;
            mr0 = fmaxf(mr0, fmaxf(accs[j][0], accs[j][1]));
            mr1 = fmaxf(mr1, fmaxf(accs[j][2], accs[j][3]));
        }
        mr0 = fmaxf(mr0, __shfl_xor_sync(0xffffffffu, mr0, 1));
        mr0 = fmaxf(mr0, __shfl_xor_sync(0xffffffffu, mr0, 2));
        mr1 = fmaxf(mr1, __shfl_xor_sync(0xffffffffu, mr1, 1));
        mr1 = fmaxf(mr1, __shfl_xor_sync(0xffffffffu, mr1, 2));

        float mn0 = fmaxf(m0, mr0), mn1 = fmaxf(m1, mr1);
        float al0 = __expf(m0 - mn0), al1 = __expf(m1 - mn1);
        m0 = mn0; m1 = mn1;

        // ---- P = exp(S - m); pack into registers (PV A-fragments) ----
        uint32_t pp[8][2];
        float ps0 = 0.f, ps1 = 0.f;
        #pragma unroll
        for (int j = 0; j < 8; j++) {
            float p0 = __expf(accs[j][0] - mn0);
            float p1 = __expf(accs[j][1] - mn0);
            float p2 = __expf(accs[j][2] - mn1);
            float p3 = __expf(accs[j][3] - mn1);
            ps0 += p0 + p1;
            ps1 += p2 + p3;
            pp[j][0] = pack_h2(p0, p1);
            pp[j][1] = pack_h2(p2, p3);
        }
        ps0 += __shfl_xor_sync(0xffffffffu, ps0, 1);
        ps0 += __shfl_xor_sync(0xffffffffu, ps0, 2);
        ps1 += __shfl_xor_sync(0xffffffffu, ps1, 1);
        ps1 += __shfl_xor_sync(0xffffffffu, ps1, 2);
        l0 = l0 * al0 + ps0;
        l1 = l1 * al1 + ps1;

        if (!__all_sync(0xffffffffu, (al0 == 1.f) && (al1 == 1.f))) {
            #pragma unroll
            for (int j = 0; j < 8; j++) {
                acc_o[j][0] *= al0; acc_o[j][1] *= al0;
                acc_o[j][2] *= al1; acc_o[j][3] *= al1;
            }
        }

        // ---- O += P @ V  (A from registers; B from Vt [d][kv]) ----
        #pragma unroll
        for (int kk = 0; kk < 4; kk++) {
            uint32_t a0 = pp[2 * kk][0];
            uint32_t a1 = pp[2 * kk][1];
            uint32_t a2 = pp[2 * kk + 1][0];
            uint32_t a3 = pp[2 * kk + 1][1];
            #pragma unroll
            for (int j = 0; j < 8; j++) {
                uint32_t b0 = LD32(Vt + (j * 8 + lg) * FQS + kk * 16 + 2 * lt);
                uint32_t b1 = LD32(Vt + (j * 8 + lg) * FQS + kk * 16 + 8 + 2 * lt);
                mma_f16(acc_o[j][0], acc_o[j][1], acc_o[j][2], acc_o[j][3],
                        a0, a1, a2, a3, b0, b1);
            }
        }
        __syncthreads();
    }

    float i0 = 1.f / l0, i1 = 1.f / l1;
    int r0 = brow + wm + lg;
    int tok0 = b * S_ + r0;
    #pragma unroll
    for (int j = 0; j < 8; j++) {
        int col = h * DH_ + j * 8 + 2 * lt;
        *(__half2*)&out[(size_t)tok0 * H_ + col] =
            __floats2half2_rn(acc_o[j][0] * i0, acc_o[j][1] * i0);
        *(__half2*)&out[(size_t)(tok0 + 8) * H_ + col] =
            __floats2half2_rn(acc_o[j][2] * i1, acc_o[j][3] * i1);
    }
}

// ------- residual + LayerNorm over (ya+yb); out float, out_r half ----
__global__ __launch_bounds__(256) void add_ln_kernel(
    const float* __restrict__ xin,
    const float* __restrict__ ya, const float* __restrict__ yb,
    const float* __restrict__ gamma, const float* __restrict__ beta,
    float* __restrict__ out, __half* __restrict__ out_r)
{
    int t = blockIdx.x;
    int tid = threadIdx.x;
    size_t base = (size_t)t * H_;
    float v0 = ya[base + tid]       + yb[base + tid];
    float v1 = ya[base + tid + 256] + yb[base + tid + 256];
    __shared__ float s1[256], s2[256];
    s1[tid] = v0 + v1;
    s2[tid] = v0 * v0 + v1 * v1;
    __syncthreads();
    for (int off = 128; off > 0; off >>= 1) {
        if (tid < off) { s1[tid] += s1[tid + off]; s2[tid] += s2[tid + off]; }
        __syncthreads();
    }
    float mean = s1[0] * (1.f / (float)H_);
    float var  = s2[0] * (1.f / (float)H_) - mean * mean;
    float r = rsqrtf(var + 1e-5f);
    float o0 = xin[base + tid]       + (v0 - mean) * r * gamma[tid]       + beta[tid];
    float o1 = xin[base + tid + 256] + (v1 - mean) * r * gamma[tid + 256] + beta[tid + 256];
    out[base + tid]         = o0;
    out[base + tid + 256]   = o1;
    out_r[base + tid]       = __float2half_rn(o0);
    out_r[base + tid + 256] = __float2half_rn(o1);
}

// ---------------- host launcher ----------------
extern "C" void kernel_launch(void* const* d_in, const int* in_sizes, int n_in,
                              void* d_out, int out_size)
{
    const int*   src  = (const int*)  d_in[0];
    const int*   mask = (const int*)  d_in[1];
    const float* emb  = (const float*)d_in[2];
    const float* Wq   = (const float*)d_in[3];
    const float* bq   = (const float*)d_in[4];
    const float* Wk   = (const float*)d_in[5];
    const float* bk   = (const float*)d_in[6];
    const float* Wv   = (const float*)d_in[7];
    const float* bv   = (const float*)d_in[8];
    const float* Wo   = (const float*)d_in[9];
    const float* bo   = (const float*)d_in[10];
    const float* gamma= (const float*)d_in[11];
    const float* beta = (const float*)d_in[12];
    const float* W1   = (const float*)d_in[13];
    const float* b1   = (const float*)d_in[14];
    const float* W2   = (const float*)d_in[15];
    const float* b2   = (const float*)d_in[16];

    float *x, *res, *t2a, *t2b, *mb;
    __half *xr, *q, *k, *vt, *t, *resr, *h1, *wh;
    cudaGetSymbolAddress((void**)&x,    g_x);
    cudaGetSymbolAddress((void**)&res,  g_res);
    cudaGetSymbolAddress((void**)&t2a,  g_t2a);
    cudaGetSymbolAddress((void**)&t2b,  g_t2b);
    cudaGetSymbolAddress((void**)&mb,   g_mb);
    cudaGetSymbolAddress((void**)&xr,   g_xr);
    cudaGetSymbolAddress((void**)&q,    g_q);
    cudaGetSymbolAddress((void**)&k,    g_k);
    cudaGetSymbolAddress((void**)&vt,   g_vt);
    cudaGetSymbolAddress((void**)&t,    g_t);
    cudaGetSymbolAddress((void**)&resr, g_resr);
    cudaGetSymbolAddress((void**)&h1,   g_h1);
    cudaGetSymbolAddress((void**)&wh,   g_wh);

    cudaFuncSetAttribute(flash_kernel,
                         cudaFuncAttributeMaxDynamicSharedMemorySize, FLASH_SMEM);
    cudaFuncSetAttribute(gemm_qkv,
                         cudaFuncAttributeMaxDynamicSharedMemorySize, GEMM_SMEM);
    cudaFuncSetAttribute(gemm_h,
                         cudaFuncAttributeMaxDynamicSharedMemorySize, GEMM_SMEM);
    cudaFuncSetAttribute(gemm_sk,
                         cudaFuncAttributeMaxDynamicSharedMemorySize, GEMM_SMEM);

    // transpose weights to [N][K] halves
    dim3 tb(32, 8);
    transpose_half_kernel<<<dim3(H_/32,  H_/32,  L_), tb>>>(Wq, wh + WOFF_Q, H_,  H_);
    transpose_half_kernel<<<dim3(H_/32,  H_/32,  L_), tb>>>(Wk, wh + WOFF_K, H_,  H_);
    transpose_half_kernel<<<dim3(H_/32,  H_/32,  L_), tb>>>(Wv, wh + WOFF_V, H_,  H_);
    transpose_half_kernel<<<dim3(H_/32,  H_/32,  L_), tb>>>(Wo, wh + WOFF_O, H_,  H_);
    transpose_half_kernel<<<dim3(FF_/32, H_/32,  L_), tb>>>(W1, wh + WOFF_1, H_,  FF_);
    transpose_half_kernel<<<dim3(H_/32,  FF_/32, L_), tb>>>(W2, wh + WOFF_2, FF_, H_);

    embed_kernel<<<(M_ * H_) / 256, 256>>>(src, emb, x, xr);
    maskbias_kernel<<<(M_ + 255) / 256, 256>>>(mask, mb);

    dim3 gQKV (H_ / 128,  M_ / 128, 3);          // 384
    dim3 gSK  (H_ / 128,  M_ / 128, 2);          // 256
    dim3 gFfn1(FF_ / 128, M_ / 128, 1);          // 512
    dim3 gFlash(S_ / 128, B_ * NH_);             // 256

    for (int i = 0; i < L_; i++) {
        const __half* WqT = wh + WOFF_Q + (size_t)i * H_ * H_;
        const __half* WkT = wh + WOFF_K + (size_t)i * H_ * H_;
        const __half* WvT = wh + WOFF_V + (size_t)i * H_ * H_;
        const __half* WoT = wh + WOFF_O + (size_t)i * H_ * H_;
        const __half* W1T = wh + WOFF_1 + (size_t)i * H_ * FF_;
        const __half* W2T = wh + WOFF_2 + (size_t)i * FF_ * H_;
        const float* bq_i = bq + i * H_;
        const float* bk_i = bk + i * H_;
        const float* bv_i = bv + i * H_;
        const float* bo_i = bo + i * H_;
        const float* b1_i = b1 + i * FF_;
        const float* b2_i = b2 + i * H_;
        const float* g_i  = gamma + i * H_;
        const float* be_i = beta  + i * H_;
        float* xout = (i == L_ - 1) ? (float*)d_out : x;

        gemm_qkv<<<gQKV, 256, GEMM_SMEM>>>(
            xr, WqT, WkT, WvT, bq_i, bk_i, bv_i, q, k, vt, H_, H_);

        flash_kernel<<<gFlash, 256, FLASH_SMEM>>>(q, k, vt, mb, t);

        gemm_sk<<<gSK, 256, GEMM_SMEM>>>(t, WoT, bo_i, t2a, t2b, H_, H_);
        add_ln_kernel<<<M_, 256>>>(x, t2a, t2b, g_i, be_i, res, resr);

        gemm_h<<<gFfn1, 256, GEMM_SMEM>>>(resr, W1T, b1_i, h1, FF_, H_);

        gemm_sk<<<gSK, 256, GEMM_SMEM>>>(h1, W2T, b2_i, t2a, t2b, H_, FF_);
        add_ln_kernel<<<M_, 256>>>(res, t2a, t2b, g_i, be_i, xout, resr);
        // resr doubles as next-layer xr
        xr = resr;
    }
}

// round 11
// speedup vs baseline: 1.6735x; 1.0185x over previous
#include <cuda_runtime.h>
#include <cuda_fp16.h>
#include <math.h>
#include <stdint.h>

// Problem dims
#define B_  2
#define S_  2048
#define H_  512
#define NH_ 8
#define DH_ 64
#define L_  6
#define FF_ 2048
#define M_  (B_*S_)

// ---------------- device scratch ----------------
__device__ float  g_x  [M_*H_];
__device__ float  g_res[M_*H_];
__device__ float  g_t2a[M_*H_];
__device__ float  g_t2b[M_*H_];
__device__ float  g_mb [M_];
__device__ __half g_xr [M_*H_];     // half activations (GEMM A inputs)
__device__ __half g_q  [M_*H_];
__device__ __half g_k  [M_*H_];
__device__ __half g_vt [M_*H_];     // V TRANSPOSED: [(b*512+d)][s]
__device__ __half g_t  [M_*H_];     // flash out
__device__ __half g_resr[M_*H_];
__device__ __half g_h1 [M_*FF_];
__device__ __half g_wh [18874368];  // transposed half weights [N][K] per matrix

#define WOFF_Q  0
#define WOFF_K  (L_*H_*H_)
#define WOFF_V  (2*L_*H_*H_)
#define WOFF_O  (3*L_*H_*H_)
#define WOFF_1  (4*L_*H_*H_)
#define WOFF_2  (4*L_*H_*H_ + L_*H_*FF_)

// ---------------- helpers ----------------
__device__ __forceinline__ void mma_f16(
    float& c0, float& c1, float& c2, float& c3,
    uint32_t a0, uint32_t a1, uint32_t a2, uint32_t a3,
    uint32_t b0, uint32_t b1)
{
    asm volatile(
        "mma.sync.aligned.m16n8k16.row.col.f32.f16.f16.f32 "
        "{%0,%1,%2,%3}, {%4,%5,%6,%7}, {%8,%9}, {%0,%1,%2,%3};\n"
        : "+f"(c0), "+f"(c1), "+f"(c2), "+f"(c3)
        : "r"(a0), "r"(a1), "r"(a2), "r"(a3), "r"(b0), "r"(b1));
}
__device__ __forceinline__ uint32_t pack_h2(float lo, float hi) {
    __half2 h = __floats2half2_rn(lo, hi);
    return *(uint32_t*)&h;
}
__device__ __forceinline__ void cp_async16f(float* dst, const float* src) {
    unsigned s = (unsigned)__cvta_generic_to_shared(dst);
    asm volatile("cp.async.cg.shared.global [%0], [%1], 16;" :: "r"(s), "l"(src));
}
__device__ __forceinline__ void cp_async16h(__half* dst, const __half* src) {
    unsigned s = (unsigned)__cvta_generic_to_shared(dst);
    asm volatile("cp.async.cg.shared.global [%0], [%1], 16;" :: "r"(s), "l"(src));
}
__device__ __forceinline__ void cp_commit() {
    asm volatile("cp.async.commit_group;");
}
#define LD32(p) (*(const uint32_t*)(p))

// ---------------- fused weight transpose + round to half (ONE launch) ------
// 32x32 tiles; flat blockIdx decodes (layer, matrix, n-tile, k-tile).
// per layer: Wq/Wk/Wv/Wo 256 tiles each (1024), W1 1024, W2 1024 -> 3072.
__global__ __launch_bounds__(256) void transpose_all_kernel(
    const float* __restrict__ Wq, const float* __restrict__ Wk,
    const float* __restrict__ Wv, const float* __restrict__ Wo,
    const float* __restrict__ W1, const float* __restrict__ W2,
    __half* __restrict__ wh)
{
    __shared__ float tile[32][33];
    int idx = blockIdx.x;
    int layer = idx / 3072;
    int r = idx % 3072;

    const float* src;
    __half* dst;
    int K, N, nt, kt;
    if (r < 1024) {
        int m = r >> 8, t = r & 255;
        nt = t & 15; kt = t >> 4;
        K = H_; N = H_;
        src = (m == 0) ? Wq : (m == 1) ? Wk : (m == 2) ? Wv : Wo;
        dst = wh + (size_t)m * (L_ * H_ * H_);
        src += (size_t)layer * H_ * H_;
        dst += (size_t)layer * H_ * H_;
    } else if (r < 2048) {
        int t = r - 1024;
        nt = t & 63; kt = t >> 6;
        K = H_; N = FF_;
        src = W1 + (size_t)layer * H_ * FF_;
        dst = wh + WOFF_1 + (size_t)layer * H_ * FF_;
    } else {
        int t = r - 2048;
        nt = t & 15; kt = t >> 4;
        K = FF_; N = H_;
        src = W2 + (size_t)layer * FF_ * H_;
        dst = wh + WOFF_2 + (size_t)layer * FF_ * H_;
    }

    int n0 = nt * 32, k0 = kt * 32;
    int tx = threadIdx.x & 31, ty = threadIdx.x >> 5;
    #pragma unroll
    for (int i = 0; i < 4; i++)
        tile[ty + i * 8][tx] = src[(size_t)(k0 + ty + i * 8) * N + n0 + tx];
    __syncthreads();
    #pragma unroll
    for (int i = 0; i < 4; i++)
        dst[(size_t)(n0 + ty + i * 8) * K + k0 + tx] =
            __float2half_rn(tile[tx][ty + i * 8]);
}

// ---------------- embedding + posenc ----------------
__global__ __launch_bounds__(256) void embed_kernel(
    const int* __restrict__ src, const float* __restrict__ emb,
    float* __restrict__ x, __half* __restrict__ xr)
{
    int idx = blockIdx.x * 256 + threadIdx.x;
    int d   = idx & (H_ - 1);
    int tok = idx >> 9;
    int s   = tok & (S_ - 1);
    int j2  = (d >> 1) * 2;
    float div = powf(10000.0f, (float)j2 * (1.0f / (float)H_));
    float arg = (float)s / div;
    float pe  = (d & 1) ? cosf(arg) : sinf(arg);
    float v = emb[(size_t)src[tok] * H_ + d] + pe;
    x[idx]  = v;
    xr[idx] = __float2half_rn(v);
}

__global__ __launch_bounds__(256) void maskbias_kernel(
    const int* __restrict__ mask, float* __restrict__ mb)
{
    int i = blockIdx.x * 256 + threadIdx.x;
    if (i < M_) mb[i] = mask[i] ? 0.f : -1e20f;
}

// =========================================================================
// fp16 GEMM core: C = A[M,K] @ Wt^T + bias.  A half [M][K]; Wt half [N][K].
// BM=128 BN=128 BK=32 halves.  8 warps (4x2), warp tile 32x64, m16n8k16.
// 3-stage cp.async pipeline.  smem rows padded to 40 halves (bank-free).
// OUT: 0 = float C, 1 = half C, 2 = half V-transposed scatter.
// =========================================================================
#define GST 40                       // smem row stride (halves)
#define STAGE_H (128 * GST)          // halves per operand per stage
#define GEMM_SMEM (3 * 2 * STAGE_H * 2)   // 61440 B

template<bool RELU, int OUT>
__device__ __forceinline__ void gemm_core(
    const __half* __restrict__ A, const __half* __restrict__ Wt,
    const float* __restrict__ bias, float biasScale, float outScale,
    void* Cv, int brow, int bcol, int N, int Kfull, int koff, int Kspan)
{
    extern __shared__ char smraw[];
    __half* sbase = (__half*)smraw;

    int tid  = threadIdx.x;
    int lane = tid & 31;
    int warp = tid >> 5;
    int warp_m = (warp >> 1) * 32;
    int warp_n = (warp & 1) * 64;
    int lg = lane >> 2, lt = lane & 3;

    auto load_tile = [&](int st, int k0) {
        __half* as = sbase + st * 2 * STAGE_H;
        __half* bs = as + STAGE_H;
        #pragma unroll
        for (int i = 0; i < 2; i++) {
            int ci = tid + i * 256;
            int r = ci >> 2, c16 = ci & 3;
            cp_async16h(as + r * GST + c16 * 8,
                        A  + (size_t)(brow + r) * Kfull + koff + k0 + c16 * 8);
            cp_async16h(bs + r * GST + c16 * 8,
                        Wt + (size_t)(bcol + r) * Kfull + koff + k0 + c16 * 8);
        }
        cp_commit();
    };

    int nk = Kspan / 32;
    load_tile(0, 0);
    load_tile(1, 32);

    float acc[2][8][4];
    #pragma unroll
    for (int i = 0; i < 2; i++)
        #pragma unroll
        for (int j = 0; j < 8; j++)
            #pragma unroll
            for (int r = 0; r < 4; r++) acc[i][j][r] = 0.f;

    for (int t = 0; t < nk; t++) {
        asm volatile("cp.async.wait_group 1;");
        __syncthreads();
        if (t + 2 < nk) load_tile((t + 2) % 3, (t + 2) * 32);
        else cp_commit();

        const __half* as = sbase + (t % 3) * 2 * STAGE_H;
        const __half* bs = as + STAGE_H;

        #pragma unroll
        for (int ks = 0; ks < 32; ks += 16) {
            uint32_t af[2][4];
            #pragma unroll
            for (int i = 0; i < 2; i++) {
                int mb = warp_m + i * 16;
                af[i][0] = LD32(as + (mb + lg) * GST + ks + 2 * lt);
                af[i][1] = LD32(as + (mb + 8 + lg) * GST + ks + 2 * lt);
                af[i][2] = LD32(as + (mb + lg) * GST + ks + 8 + 2 * lt);
                af[i][3] = LD32(as + (mb + 8 + lg) * GST + ks + 8 + 2 * lt);
            }
            uint32_t bf[8][2];
            #pragma unroll
            for (int j = 0; j < 8; j++) {
                int nb = warp_n + j * 8 + lg;
                bf[j][0] = LD32(bs + nb * GST + ks + 2 * lt);
                bf[j][1] = LD32(bs + nb * GST + ks + 8 + 2 * lt);
            }
            #pragma unroll
            for (int i = 0; i < 2; i++)
                #pragma unroll
                for (int j = 0; j < 8; j++)
                    mma_f16(acc[i][j][0], acc[i][j][1], acc[i][j][2], acc[i][j][3],
                            af[i][0], af[i][1], af[i][2], af[i][3],
                            bf[j][0], bf[j][1]);
        }
        __syncthreads();
    }

    #pragma unroll
    for (int i = 0; i < 2; i++) {
        #pragma unroll
        for (int j = 0; j < 8; j++) {
            int col = bcol + warp_n + j * 8 + 2 * lt;
            float bx = bias[col] * biasScale, by = bias[col + 1] * biasScale;
            int r0 = brow + warp_m + i * 16 + lg;
            float v0x = (acc[i][j][0] + bx) * outScale;
            float v0y = (acc[i][j][1] + by) * outScale;
            float v1x = (acc[i][j][2] + bx) * outScale;
            float v1y = (acc[i][j][3] + by) * outScale;
            if (RELU) {
                v0x = fmaxf(v0x, 0.f); v0y = fmaxf(v0y, 0.f);
                v1x = fmaxf(v1x, 0.f); v1y = fmaxf(v1y, 0.f);
            }
            if (OUT == 0) {
                float* C = (float*)Cv;
                *(float2*)&C[(size_t)r0 * N + col]       = make_float2(v0x, v0y);
                *(float2*)&C[(size_t)(r0 + 8) * N + col] = make_float2(v1x, v1y);
            } else if (OUT == 1) {
                __half* C = (__half*)Cv;
                *(__half2*)&C[(size_t)r0 * N + col]       = __floats2half2_rn(v0x, v0y);
                *(__half2*)&C[(size_t)(r0 + 8) * N + col] = __floats2half2_rn(v1x, v1y);
            } else {
                __half* C = (__half*)Cv;
                int bb = r0 >> 11, s = r0 & 2047;
                size_t base0 = (size_t)(bb * 512 + col) * 2048;
                size_t base1 = (size_t)(bb * 512 + col + 1) * 2048;
                C[base0 + s]     = __float2half_rn(v0x);
                C[base1 + s]     = __float2half_rn(v0y);
                C[base0 + s + 8] = __float2half_rn(v1x);
                C[base1 + s + 8] = __float2half_rn(v1y);
            }
        }
    }
}

__global__ __launch_bounds__(256, 2) void gemm_qkv(
    const __half* __restrict__ A,
    const __half* __restrict__ Wq, const __half* __restrict__ Wk, const __half* __restrict__ Wv,
    const float* __restrict__ bq, const float* __restrict__ bk, const float* __restrict__ bv,
    __half* q, __half* k, __half* vt, int N, int K)
{
    int z = blockIdx.z;
    if (z == 0)
        gemm_core<false, 1>(A, Wq, bq, 1.f, 0.125f, q,
                            blockIdx.y * 128, blockIdx.x * 128, N, K, 0, K);
    else if (z == 1)
        gemm_core<false, 1>(A, Wk, bk, 1.f, 1.f, k,
                            blockIdx.y * 128, blockIdx.x * 128, N, K, 0, K);
    else
        gemm_core<false, 2>(A, Wv, bv, 1.f, 1.f, vt,
                            blockIdx.y * 128, blockIdx.x * 128, N, K, 0, K);
}

__global__ __launch_bounds__(256, 2) void gemm_h(
    const __half* __restrict__ A, const __half* __restrict__ Wt,
    const float* __restrict__ bias, __half* C, int N, int K)
{
    gemm_core<true, 1>(A, Wt, bias, 1.f, 1.f, C,
                       blockIdx.y * 128, blockIdx.x * 128, N, K, 0, K);
}

__global__ __launch_bounds__(256, 2) void gemm_sk(
    const __half* __restrict__ A, const __half* __restrict__ Wt,
    const float* __restrict__ bias, float* C0, float* C1, int N, int K)
{
    int z = blockIdx.z;
    int Kh = K >> 1;
    gemm_core<false, 0>(A, Wt, bias, z == 0 ? 1.f : 0.f, 1.f,
                        z == 0 ? (void*)C0 : (void*)C1,
                        blockIdx.y * 128, blockIdx.x * 128, N, K, z * Kh, Kh);
}

// =========================================================================
// fp16 flash attention (R10-proven) with occupancy pinned at 2 CTA/SM.
// =========================================================================
#define FQS 72
#define NKV (S_ / 64)
#define FLASH_SMEM (128*FQS*2 + 2*64*FQS*2 + 2*64*FQS*2 + 2*64*4)

__global__ __launch_bounds__(256, 2) void flash_kernel(
    const __half* __restrict__ q, const __half* __restrict__ k,
    const __half* __restrict__ vt, const float* __restrict__ mbias,
    __half* __restrict__ out)
{
    extern __shared__ char smraw[];
    __half* Qh  = (__half*)smraw;
    __half* Ksm = Qh + 128 * FQS;
    __half* Vsm = Ksm + 2 * 64 * FQS;
    float*  MB  = (float*)(Vsm + 2 * 64 * FQS);

    int tid  = threadIdx.x;
    int lane = tid & 31;
    int warp = tid >> 5;
    int wm   = warp * 16;
    int lg = lane >> 2, lt = lane & 3;
    int brow = blockIdx.x * 128;
    int bh = blockIdx.y;
    int b = bh >> 3, h = bh & 7;

    const __half* Qb  = q  + (size_t)b * S_ * H_ + h * DH_;
    const __half* Kb  = k  + (size_t)b * S_ * H_ + h * DH_;
    const __half* Vtb = vt + (size_t)(b * 512 + h * 64) * 2048;
    const float*  MBg = mbias + b * S_;

    auto load_kv = [&](int buf, int it) {
        int kv0 = it * 64;
        __half* kd = Ksm + buf * 64 * FQS;
        __half* vd = Vsm + buf * 64 * FQS;
        #pragma unroll
        for (int i = 0; i < 2; i++) {
            int ci = tid + i * 256;
            int r = ci >> 3, c8 = ci & 7;
            cp_async16h(kd + r * FQS + c8 * 8,
                        Kb + (size_t)(kv0 + r) * H_ + c8 * 8);
            cp_async16h(vd + r * FQS + c8 * 8,
                        Vtb + (size_t)r * S_ + kv0 + c8 * 8);
        }
        if (tid < 16) cp_async16f(&MB[buf * 64 + tid * 4], MBg + kv0 + tid * 4);
        cp_commit();
    };

    #pragma unroll
    for (int i = 0; i < 4; i++) {
        int ci = tid + i * 256;
        int r = ci >> 3, c8 = ci & 7;
        cp_async16h(Qh + r * FQS + c8 * 8,
                    Qb + (size_t)(brow + r) * H_ + c8 * 8);
    }
    cp_commit();
    load_kv(0, 0);
    asm volatile("cp.async.wait_group 1;");
    __syncthreads();

    uint32_t aq[4][4];
    #pragma unroll
    for (int ks = 0; ks < 4; ks++) {
        aq[ks][0] = LD32(Qh + (wm + lg) * FQS + ks * 16 + 2 * lt);
        aq[ks][1] = LD32(Qh + (wm + 8 + lg) * FQS + ks * 16 + 2 * lt);
        aq[ks][2] = LD32(Qh + (wm + lg) * FQS + ks * 16 + 8 + 2 * lt);
        aq[ks][3] = LD32(Qh + (wm + 8 + lg) * FQS + ks * 16 + 8 + 2 * lt);
    }

    float acc_o[8][4];
    #pragma unroll
    for (int j = 0; j < 8; j++)
        #pragma unroll
        for (int rr = 0; rr < 4; rr++) acc_o[j][rr] = 0.f;
    float m0 = -1e30f, m1 = -1e30f, l0 = 0.f, l1 = 0.f;

    for (int it = 0; it < NKV; it++) {
        int buf = it & 1;
        if (it + 1 < NKV) {
            load_kv(buf ^ 1, it + 1);
            asm volatile("cp.async.wait_group 1;");
        } else {
            asm volatile("cp.async.wait_group 0;");
        }
        __syncthreads();

        const __half* Kt  = Ksm + buf * 64 * FQS;
        const __half* Vt  = Vsm + buf * 64 * FQS;
        const float*  MBt = MB + buf * 64;

        float accs[8][4];
        #pragma unroll
        for (int j = 0; j < 8; j++)
            #pragma unroll
            for (int rr = 0; rr < 4; rr++) accs[j][rr] = 0.f;
        #pragma unroll
        for (int ks = 0; ks < 4; ks++) {
            #pragma unroll
            for (int j = 0; j < 8; j++) {
                uint32_t b0 = LD32(Kt + (j * 8 + lg) * FQS + ks * 16 + 2 * lt);
                uint32_t b1 = LD32(Kt + (j * 8 + lg) * FQS + ks * 16 + 8 + 2 * lt);
                mma_f16(accs[j][0], accs[j][1], accs[j][2], accs[j][3],
                        aq[ks][0], aq[ks][1], aq[ks][2], aq[ks][3], b0, b1);
            }
        }

        float mr0 = -1e30f, mr1 = -1e30f;
        #pragma unroll
        for (int j = 0; j < 8; j++) {
            float2 mbv = *(const float2*)&MBt[j * 8 + 2 * lt];
            accs[j][0] += mbv.x;
            accs[j][1] += mbv.y;
            accs[j][2] += mbv.x;
            accs[j][3] += mbv.y;
            mr0 = fmaxf(mr0, fmaxf(accs[j][0], accs[j][1]));
            mr1 = fmaxf(mr1, fmaxf(accs[j][2], accs[j][3]));
        }
        mr0 = fmaxf(mr0, __shfl_xor_sync(0xffffffffu, mr0, 1));
        mr0 = fmaxf(mr0, __shfl_xor_sync(0xffffffffu, mr0, 2));
        mr1 = fmaxf(mr1, __shfl_xor_sync(0xffffffffu, mr1, 1));
        mr1 = fmaxf(mr1, __shfl_xor_sync(0xffffffffu, mr1, 2));

        float mn0 = fmaxf(m0, mr0), mn1 = fmaxf(m1, mr1);
        float al0 = __expf(m0 - mn0), al1 = __expf(m1 - mn1);
        m0 = mn0; m1 = mn1;

        uint32_t pp[8][2];
        float ps0 = 0.f, ps1 = 0.f;
        #pragma unroll
        for (int j = 0; j < 8; j++) {
            float p0 = __expf(accs[j][0] - mn0);
            float p1 = __expf(accs[j][1] - mn0);
            float p2 = __expf(accs[j][2] - mn1);
            float p3 = __expf(accs[j][3] - mn1);
            ps0 += p0 + p1;
            ps1 += p2 + p3;
            pp[j][0] = pack_h2(p0, p1);
            pp[j][1] = pack_h2(p2, p3);
        }
        ps0 += __shfl_xor_sync(0xffffffffu, ps0, 1);
        ps0 += __shfl_xor_sync(0xffffffffu, ps0, 2);
        ps1 += __shfl_xor_sync(0xffffffffu, ps1, 1);
        ps1 += __shfl_xor_sync(0xffffffffu, ps1, 2);
        l0 = l0 * al0 + ps0;
        l1 = l1 * al1 + ps1;

        if (!__all_sync(0xffffffffu, (al0 == 1.f) && (al1 == 1.f))) {
            #pragma unroll
            for (int j = 0; j < 8; j++) {
                acc_o[j][0] *= al0; acc_o[j][1] *= al0;
                acc_o[j][2] *= al1; acc_o[j][3] *= al1;
            }
        }

        #pragma unroll
        for (int kk = 0; kk < 4; kk++) {
            uint32_t a0 = pp[2 * kk][0];
            uint32_t a1 = pp[2 * kk][1];
            uint32_t a2 = pp[2 * kk + 1][0];
            uint32_t a3 = pp[2 * kk + 1][1];
            #pragma unroll
            for (int j = 0; j < 8; j++) {
                uint32_t b0 = LD32(Vt + (j * 8 + lg) * FQS + kk * 16 + 2 * lt);
                uint32_t b1 = LD32(Vt + (j * 8 + lg) * FQS + kk * 16 + 8 + 2 * lt);
                mma_f16(acc_o[j][0], acc_o[j][1], acc_o[j][2], acc_o[j][3],
                        a0, a1, a2, a3, b0, b1);
            }
        }
        __syncthreads();
    }

    float i0 = 1.f / l0, i1 = 1.f / l1;
    int r0 = brow + wm + lg;
    int tok0 = b * S_ + r0;
    #pragma unroll
    for (int j = 0; j < 8; j++) {
        int col = h * DH_ + j * 8 + 2 * lt;
        *(__half2*)&out[(size_t)tok0 * H_ + col] =
            __floats2half2_rn(acc_o[j][0] * i0, acc_o[j][1] * i0);
        *(__half2*)&out[(size_t)(tok0 + 8) * H_ + col] =
            __floats2half2_rn(acc_o[j][2] * i1, acc_o[j][3] * i1);
    }
}

// ------- residual + LayerNorm over (ya+yb); out float, out_r half ----
__global__ __launch_bounds__(256) void add_ln_kernel(
    const float* __restrict__ xin,
    const float* __restrict__ ya, const float* __restrict__ yb,
    const float* __restrict__ gamma, const float* __restrict__ beta,
    float* __restrict__ out, __half* __restrict__ out_r)
{
    int t = blockIdx.x;
    int tid = threadIdx.x;
    size_t base = (size_t)t * H_;
    float v0 = ya[base + tid]       + yb[base + tid];
    float v1 = ya[base + tid + 256] + yb[base + tid + 256];
    __shared__ float s1[256], s2[256];
    s1[tid] = v0 + v1;
    s2[tid] = v0 * v0 + v1 * v1;
    __syncthreads();
    for (int off = 128; off > 0; off >>= 1) {
        if (tid < off) { s1[tid] += s1[tid + off]; s2[tid] += s2[tid + off]; }
        __syncthreads();
    }
    float mean = s1[0] * (1.f / (float)H_);
    float var  = s2[0] * (1.f / (float)H_) - mean * mean;
    float r = rsqrtf(var + 1e-5f);
    float o0 = xin[base + tid]       + (v0 - mean) * r * gamma[tid]       + beta[tid];
    float o1 = xin[base + tid + 256] + (v1 - mean) * r * gamma[tid + 256] + beta[tid + 256];
    out[base + tid]         = o0;
    out[base + tid + 256]   = o1;
    out_r[base + tid]       = __float2half_rn(o0);
    out_r[base + tid + 256] = __float2half_rn(o1);
}

// ---------------- host launcher ----------------
extern "C" void kernel_launch(void* const* d_in, const int* in_sizes, int n_in,
                              void* d_out, int out_size)
{
    const int*   src  = (const int*)  d_in[0];
    const int*   mask = (const int*)  d_in[1];
    const float* emb  = (const float*)d_in[2];
    const float* Wq   = (const float*)d_in[3];
    const float* bq   = (const float*)d_in[4];
    const float* Wk   = (const float*)d_in[5];
    const float* bk   = (const float*)d_in[6];
    const float* Wv   = (const float*)d_in[7];
    const float* bv   = (const float*)d_in[8];
    const float* Wo   = (const float*)d_in[9];
    const float* bo   = (const float*)d_in[10];
    const float* gamma= (const float*)d_in[11];
    const float* beta = (const float*)d_in[12];
    const float* W1   = (const float*)d_in[13];
    const float* b1   = (const float*)d_in[14];
    const float* W2   = (const float*)d_in[15];
    const float* b2   = (const float*)d_in[16];

    float *x, *res, *t2a, *t2b, *mb;
    __half *xr, *q, *k, *vt, *t, *resr, *h1, *wh;
    cudaGetSymbolAddress((void**)&x,    g_x);
    cudaGetSymbolAddress((void**)&res,  g_res);
    cudaGetSymbolAddress((void**)&t2a,  g_t2a);
    cudaGetSymbolAddress((void**)&t2b,  g_t2b);
    cudaGetSymbolAddress((void**)&mb,   g_mb);
    cudaGetSymbolAddress((void**)&xr,   g_xr);
    cudaGetSymbolAddress((void**)&q,    g_q);
    cudaGetSymbolAddress((void**)&k,    g_k);
    cudaGetSymbolAddress((void**)&vt,   g_vt);
    cudaGetSymbolAddress((void**)&t,    g_t);
    cudaGetSymbolAddress((void**)&resr, g_resr);
    cudaGetSymbolAddress((void**)&h1,   g_h1);
    cudaGetSymbolAddress((void**)&wh,   g_wh);

    cudaFuncSetAttribute(flash_kernel,
                         cudaFuncAttributeMaxDynamicSharedMemorySize, FLASH_SMEM);
    cudaFuncSetAttribute(gemm_qkv,
                         cudaFuncAttributeMaxDynamicSharedMemorySize, GEMM_SMEM);
    cudaFuncSetAttribute(gemm_h,
                         cudaFuncAttributeMaxDynamicSharedMemorySize, GEMM_SMEM);
    cudaFuncSetAttribute(gemm_sk,
                         cudaFuncAttributeMaxDynamicSharedMemorySize, GEMM_SMEM);

    // one fused transpose launch for all 36 weight matrices
    transpose_all_kernel<<<L_ * 3072, 256>>>(Wq, Wk, Wv, Wo, W1, W2, wh);

    embed_kernel<<<(M_ * H_) / 256, 256>>>(src, emb, x, xr);
    maskbias_kernel<<<(M_ + 255) / 256, 256>>>(mask, mb);

    dim3 gQKV (H_ / 128,  M_ / 128, 3);          // 384
    dim3 gSK  (H_ / 128,  M_ / 128, 2);          // 256
    dim3 gFfn1(FF_ / 128, M_ / 128, 1);          // 512
    dim3 gFlash(S_ / 128, B_ * NH_);             // 256

    for (int i = 0; i < L_; i++) {
        const __half* WqT = wh + WOFF_Q + (size_t)i * H_ * H_;
        const __half* WkT = wh + WOFF_K + (size_t)i * H_ * H_;
        const __half* WvT = wh + WOFF_V + (size_t)i * H_ * H_;
        const __half* WoT = wh + WOFF_O + (size_t)i * H_ * H_;
        const __half* W1T = wh + WOFF_1 + (size_t)i * H_ * FF_;
        const __half* W2T = wh + WOFF_2 + (size_t)i * FF_ * H_;
        const float* bq_i = bq + i * H_;
        const float* bk_i = bk + i * H_;
        const float* bv_i = bv + i * H_;
        const float* bo_i = bo + i * H_;
        const float* b1_i = b1 + i * FF_;
        const float* b2_i = b2 + i * H_;
        const float* g_i  = gamma + i * H_;
        const float* be_i = beta  + i * H_;
        float* xout = (i == L_ - 1) ? (float*)d_out : x;

        gemm_qkv<<<gQKV, 256, GEMM_SMEM>>>(
            xr, WqT, WkT, WvT, bq_i, bk_i, bv_i, q, k, vt, H_, H_);

        flash_kernel<<<gFlash, 256, FLASH_SMEM>>>(q, k, vt, mb, t);

        gemm_sk<<<gSK, 256, GEMM_SMEM>>>(t, WoT, bo_i, t2a, t2b, H_, H_);
        add_ln_kernel<<<M_, 256>>>(x, t2a, t2b, g_i, be_i, res, resr);

        gemm_h<<<gFfn1, 256, GEMM_SMEM>>>(resr, W1T, b1_i, h1, FF_, H_);

        gemm_sk<<<gSK, 256, GEMM_SMEM>>>(h1, W2T, b2_i, t2a, t2b, H_, FF_);
        add_ln_kernel<<<M_, 256>>>(res, t2a, t2b, g_i, be_i, xout, resr);
        xr = resr;
    }
}

// round 12
// speedup vs baseline: 1.8046x; 1.0783x over previous
#include <cuda_runtime.h>
#include <cuda_fp16.h>
#include <math.h>
#include <stdint.h>

// Problem dims
#define B_  2
#define S_  2048
#define H_  512
#define NH_ 8
#define DH_ 64
#define L_  6
#define FF_ 2048
#define M_  (B_*S_)

// ---------------- device scratch ----------------
__device__ float  g_x  [M_*H_];
__device__ float  g_res[M_*H_];
__device__ float  g_t2a[M_*H_];
__device__ float  g_t2b[M_*H_];
__device__ float  g_mb [M_];
__device__ __half g_xr [M_*H_];
__device__ __half g_q  [M_*H_];
__device__ __half g_k  [M_*H_];
__device__ __half g_vt [M_*H_];     // V transposed: [(b*512+d)][s]
__device__ __half g_t  [M_*H_];
__device__ __half g_resr[M_*H_];
__device__ __half g_h1 [M_*FF_];
__device__ __half g_wh [18874368];  // transposed half weights [N][K]

#define WOFF_Q  0
#define WOFF_K  (L_*H_*H_)
#define WOFF_V  (2*L_*H_*H_)
#define WOFF_O  (3*L_*H_*H_)
#define WOFF_1  (4*L_*H_*H_)
#define WOFF_2  (4*L_*H_*H_ + L_*H_*FF_)

// ---------------- helpers ----------------
__device__ __forceinline__ void mma_f16(
    float& c0, float& c1, float& c2, float& c3,
    uint32_t a0, uint32_t a1, uint32_t a2, uint32_t a3,
    uint32_t b0, uint32_t b1)
{
    asm volatile(
        "mma.sync.aligned.m16n8k16.row.col.f32.f16.f16.f32 "
        "{%0,%1,%2,%3}, {%4,%5,%6,%7}, {%8,%9}, {%0,%1,%2,%3};\n"
        : "+f"(c0), "+f"(c1), "+f"(c2), "+f"(c3)
        : "r"(a0), "r"(a1), "r"(a2), "r"(a3), "r"(b0), "r"(b1));
}
__device__ __forceinline__ uint32_t pack_h2(float lo, float hi) {
    __half2 h = __floats2half2_rn(lo, hi);
    return *(uint32_t*)&h;
}
__device__ __forceinline__ void cp_async16f(float* dst, const float* src) {
    unsigned s = (unsigned)__cvta_generic_to_shared(dst);
    asm volatile("cp.async.cg.shared.global [%0], [%1], 16;" :: "r"(s), "l"(src));
}
__device__ __forceinline__ void cp_async16h(__half* dst, const __half* src) {
    unsigned s = (unsigned)__cvta_generic_to_shared(dst);
    asm volatile("cp.async.cg.shared.global [%0], [%1], 16;" :: "r"(s), "l"(src));
}
__device__ __forceinline__ void cp_commit() {
    asm volatile("cp.async.commit_group;");
}
#define LD32(p) (*(const uint32_t*)(p))

// ---------------- fused weight transpose (one launch) ----------------
__global__ __launch_bounds__(256) void transpose_all_kernel(
    const float* __restrict__ Wq, const float* __restrict__ Wk,
    const float* __restrict__ Wv, const float* __restrict__ Wo,
    const float* __restrict__ W1, const float* __restrict__ W2,
    __half* __restrict__ wh)
{
    __shared__ float tile[32][33];
    int idx = blockIdx.x;
    int layer = idx / 3072;
    int r = idx % 3072;

    const float* src;
    __half* dst;
    int K, N, nt, kt;
    if (r < 1024) {
        int m = r >> 8, t = r & 255;
        nt = t & 15; kt = t >> 4;
        K = H_; N = H_;
        src = (m == 0) ? Wq : (m == 1) ? Wk : (m == 2) ? Wv : Wo;
        dst = wh + (size_t)m * (L_ * H_ * H_);
        src += (size_t)layer * H_ * H_;
        dst += (size_t)layer * H_ * H_;
    } else if (r < 2048) {
        int t = r - 1024;
        nt = t & 63; kt = t >> 6;
        K = H_; N = FF_;
        src = W1 + (size_t)layer * H_ * FF_;
        dst = wh + WOFF_1 + (size_t)layer * H_ * FF_;
    } else {
        int t = r - 2048;
        nt = t & 15; kt = t >> 4;
        K = FF_; N = H_;
        src = W2 + (size_t)layer * FF_ * H_;
        dst = wh + WOFF_2 + (size_t)layer * FF_ * H_;
    }

    int n0 = nt * 32, k0 = kt * 32;
    int tx = threadIdx.x & 31, ty = threadIdx.x >> 5;
    #pragma unroll
    for (int i = 0; i < 4; i++)
        tile[ty + i * 8][tx] = src[(size_t)(k0 + ty + i * 8) * N + n0 + tx];
    __syncthreads();
    #pragma unroll
    for (int i = 0; i < 4; i++)
        dst[(size_t)(n0 + ty + i * 8) * K + k0 + tx] =
            __float2half_rn(tile[tx][ty + i * 8]);
}

// ---------------- embedding + posenc ----------------
__global__ __launch_bounds__(256) void embed_kernel(
    const int* __restrict__ src, const float* __restrict__ emb,
    float* __restrict__ x, __half* __restrict__ xr)
{
    int idx = blockIdx.x * 256 + threadIdx.x;
    int d   = idx & (H_ - 1);
    int tok = idx >> 9;
    int s   = tok & (S_ - 1);
    int j2  = (d >> 1) * 2;
    float div = powf(10000.0f, (float)j2 * (1.0f / (float)H_));
    float arg = (float)s / div;
    float pe  = (d & 1) ? cosf(arg) : sinf(arg);
    float v = emb[(size_t)src[tok] * H_ + d] + pe;
    x[idx]  = v;
    xr[idx] = __float2half_rn(v);
}

__global__ __launch_bounds__(256) void maskbias_kernel(
    const int* __restrict__ mask, float* __restrict__ mb)
{
    int i = blockIdx.x * 256 + threadIdx.x;
    if (i < M_) mb[i] = mask[i] ? 0.f : -1e20f;
}

// =========================================================================
// fp16 GEMM core, BK=64, single-barrier 3-stage pipeline.
// C = A[M,K] @ Wt^T + bias.  A half [M][K]; Wt half [N][K].
// BM=128 BN=128.  8 warps (4x2), warp tile 32x64, m16n8k16.
// OUT: 0 = float C, 1 = half C, 2 = half V-transposed scatter.
// =========================================================================
#define GST 72                         // smem row stride (halves): 64 + 8 pad
#define STAGE_H (128 * GST)            // halves per operand per stage
#define GEMM_SMEM (3 * 2 * STAGE_H * 2)  // 110592 B

template<bool RELU, int OUT>
__device__ __forceinline__ void gemm_core(
    const __half* __restrict__ A, const __half* __restrict__ Wt,
    const float* __restrict__ bias, float biasScale, float outScale,
    void* Cv, int brow, int bcol, int N, int Kfull, int koff, int Kspan)
{
    extern __shared__ char smraw[];
    __half* sbase = (__half*)smraw;

    int tid  = threadIdx.x;
    int lane = tid & 31;
    int warp = tid >> 5;
    int warp_m = (warp >> 1) * 32;
    int warp_n = (warp & 1) * 64;
    int lg = lane >> 2, lt = lane & 3;

    // tile loader: 128x64 halves per operand; 1024 16B-chunks each -> 4/thread
    auto load_tile = [&](int st, int k0) {
        __half* as = sbase + st * 2 * STAGE_H;
        __half* bs = as + STAGE_H;
        #pragma unroll
        for (int i = 0; i < 4; i++) {
            int ci = tid + i * 256;
            int r = ci >> 3, c8 = ci & 7;
            cp_async16h(as + r * GST + c8 * 8,
                        A  + (size_t)(brow + r) * Kfull + koff + k0 + c8 * 8);
            cp_async16h(bs + r * GST + c8 * 8,
                        Wt + (size_t)(bcol + r) * Kfull + koff + k0 + c8 * 8);
        }
        cp_commit();
    };

    int nk = Kspan / 64;
    load_tile(0, 0);
    load_tile(1, 64);

    float acc[2][8][4];
    #pragma unroll
    for (int i = 0; i < 2; i++)
        #pragma unroll
        for (int j = 0; j < 8; j++)
            #pragma unroll
            for (int r = 0; r < 4; r++) acc[i][j][r] = 0.f;

    for (int t = 0; t < nk; t++) {
        if (t < nk - 1) asm volatile("cp.async.wait_group 1;");
        else            asm volatile("cp.async.wait_group 0;");
        __syncthreads();                       // single barrier per iteration
        if (t + 2 < nk) load_tile((t + 2) % 3, (t + 2) * 64);

        const __half* as = sbase + (t % 3) * 2 * STAGE_H;
        const __half* bs = as + STAGE_H;

        #pragma unroll
        for (int ks = 0; ks < 64; ks += 16) {
            uint32_t af[2][4];
            #pragma unroll
            for (int i = 0; i < 2; i++) {
                int mb = warp_m + i * 16;
                af[i][0] = LD32(as + (mb + lg) * GST + ks + 2 * lt);
                af[i][1] = LD32(as + (mb + 8 + lg) * GST + ks + 2 * lt);
                af[i][2] = LD32(as + (mb + lg) * GST + ks + 8 + 2 * lt);
                af[i][3] = LD32(as + (mb + 8 + lg) * GST + ks + 8 + 2 * lt);
            }
            uint32_t bf[8][2];
            #pragma unroll
            for (int j = 0; j < 8; j++) {
                int nb = warp_n + j * 8 + lg;
                bf[j][0] = LD32(bs + nb * GST + ks + 2 * lt);
                bf[j][1] = LD32(bs + nb * GST + ks + 8 + 2 * lt);
            }
            #pragma unroll
            for (int i = 0; i < 2; i++)
                #pragma unroll
                for (int j = 0; j < 8; j++)
                    mma_f16(acc[i][j][0], acc[i][j][1], acc[i][j][2], acc[i][j][3],
                            af[i][0], af[i][1], af[i][2], af[i][3],
                            bf[j][0], bf[j][1]);
        }
    }

    #pragma unroll
    for (int i = 0; i < 2; i++) {
        #pragma unroll
        for (int j = 0; j < 8; j++) {
            int col = bcol + warp_n + j * 8 + 2 * lt;
            float bx = bias[col] * biasScale, by = bias[col + 1] * biasScale;
            int r0 = brow + warp_m + i * 16 + lg;
            float v0x = (acc[i][j][0] + bx) * outScale;
            float v0y = (acc[i][j][1] + by) * outScale;
            float v1x = (acc[i][j][2] + bx) * outScale;
            float v1y = (acc[i][j][3] + by) * outScale;
            if (RELU) {
                v0x = fmaxf(v0x, 0.f); v0y = fmaxf(v0y, 0.f);
                v1x = fmaxf(v1x, 0.f); v1y = fmaxf(v1y, 0.f);
            }
            if (OUT == 0) {
                float* C = (float*)Cv;
                *(float2*)&C[(size_t)r0 * N + col]       = make_float2(v0x, v0y);
                *(float2*)&C[(size_t)(r0 + 8) * N + col] = make_float2(v1x, v1y);
            } else if (OUT == 1) {
                __half* C = (__half*)Cv;
                *(__half2*)&C[(size_t)r0 * N + col]       = __floats2half2_rn(v0x, v0y);
                *(__half2*)&C[(size_t)(r0 + 8) * N + col] = __floats2half2_rn(v1x, v1y);
            } else {
                __half* C = (__half*)Cv;
                int bb = r0 >> 11, s = r0 & 2047;
                size_t base0 = (size_t)(bb * 512 + col) * 2048;
                size_t base1 = (size_t)(bb * 512 + col + 1) * 2048;
                C[base0 + s]     = __float2half_rn(v0x);
                C[base1 + s]     = __float2half_rn(v0y);
                C[base0 + s + 8] = __float2half_rn(v1x);
                C[base1 + s + 8] = __float2half_rn(v1y);
            }
        }
    }
}

__global__ __launch_bounds__(256, 2) void gemm_qkv(
    const __half* __restrict__ A,
    const __half* __restrict__ Wq, const __half* __restrict__ Wk, const __half* __restrict__ Wv,
    const float* __restrict__ bq, const float* __restrict__ bk, const float* __restrict__ bv,
    __half* q, __half* k, __half* vt, int N, int K)
{
    int z = blockIdx.z;
    if (z == 0)
        gemm_core<false, 1>(A, Wq, bq, 1.f, 0.125f, q,
                            blockIdx.y * 128, blockIdx.x * 128, N, K, 0, K);
    else if (z == 1)
        gemm_core<false, 1>(A, Wk, bk, 1.f, 1.f, k,
                            blockIdx.y * 128, blockIdx.x * 128, N, K, 0, K);
    else
        gemm_core<false, 2>(A, Wv, bv, 1.f, 1.f, vt,
                            blockIdx.y * 128, blockIdx.x * 128, N, K, 0, K);
}

__global__ __launch_bounds__(256, 2) void gemm_h(
    const __half* __restrict__ A, const __half* __restrict__ Wt,
    const float* __restrict__ bias, __half* C, int N, int K)
{
    gemm_core<true, 1>(A, Wt, bias, 1.f, 1.f, C,
                       blockIdx.y * 128, blockIdx.x * 128, N, K, 0, K);
}

__global__ __launch_bounds__(256, 2) void gemm_sk(
    const __half* __restrict__ A, const __half* __restrict__ Wt,
    const float* __restrict__ bias, float* C0, float* C1, int N, int K)
{
    int z = blockIdx.z;
    int Kh = K >> 1;
    gemm_core<false, 0>(A, Wt, bias, z == 0 ? 1.f : 0.f, 1.f,
                        z == 0 ? (void*)C0 : (void*)C1,
                        blockIdx.y * 128, blockIdx.x * 128, N, K, z * Kh, Kh);
}

// =========================================================================
// fp16 flash attention: 3 KV buffers, single barrier per KV tile.
// =========================================================================
#define FQS 72
#define NKV (S_ / 64)
#define FLASH_SMEM (128*FQS*2 + 3*64*FQS*2 + 3*64*FQS*2 + 3*64*4)

__global__ __launch_bounds__(256, 2) void flash_kernel(
    const __half* __restrict__ q, const __half* __restrict__ k,
    const __half* __restrict__ vt, const float* __restrict__ mbias,
    __half* __restrict__ out)
{
    extern __shared__ char smraw[];
    __half* Qh  = (__half*)smraw;
    __half* Ksm = Qh + 128 * FQS;
    __half* Vsm = Ksm + 3 * 64 * FQS;
    float*  MB  = (float*)(Vsm + 3 * 64 * FQS);

    int tid  = threadIdx.x;
    int lane = tid & 31;
    int warp = tid >> 5;
    int wm   = warp * 16;
    int lg = lane >> 2, lt = lane & 3;
    int brow = blockIdx.x * 128;
    int bh = blockIdx.y;
    int b = bh >> 3, h = bh & 7;

    const __half* Qb  = q  + (size_t)b * S_ * H_ + h * DH_;
    const __half* Kb  = k  + (size_t)b * S_ * H_ + h * DH_;
    const __half* Vtb = vt + (size_t)(b * 512 + h * 64) * 2048;
    const float*  MBg = mbias + b * S_;

    auto load_kv = [&](int buf, int it) {
        int kv0 = it * 64;
        __half* kd = Ksm + buf * 64 * FQS;
        __half* vd = Vsm + buf * 64 * FQS;
        #pragma unroll
        for (int i = 0; i < 2; i++) {
            int ci = tid + i * 256;
            int r = ci >> 3, c8 = ci & 7;
            cp_async16h(kd + r * FQS + c8 * 8,
                        Kb + (size_t)(kv0 + r) * H_ + c8 * 8);
            cp_async16h(vd + r * FQS + c8 * 8,
                        Vtb + (size_t)r * S_ + kv0 + c8 * 8);
        }
        if (tid < 16) cp_async16f(&MB[buf * 64 + tid * 4], MBg + kv0 + tid * 4);
        cp_commit();
    };

    // prologue: Q (group 0), kv0 (group 1), kv1 (group 2)
    #pragma unroll
    for (int i = 0; i < 4; i++) {
        int ci = tid + i * 256;
        int r = ci >> 3, c8 = ci & 7;
        cp_async16h(Qh + r * FQS + c8 * 8,
                    Qb + (size_t)(brow + r) * H_ + c8 * 8);
    }
    cp_commit();
    load_kv(0, 0);
    load_kv(1, 1);
    asm volatile("cp.async.wait_group 2;");   // Q ready
    __syncthreads();

    uint32_t aq[4][4];
    #pragma unroll
    for (int ks = 0; ks < 4; ks++) {
        aq[ks][0] = LD32(Qh + (wm + lg) * FQS + ks * 16 + 2 * lt);
        aq[ks][1] = LD32(Qh + (wm + 8 + lg) * FQS + ks * 16 + 2 * lt);
        aq[ks][2] = LD32(Qh + (wm + lg) * FQS + ks * 16 + 8 + 2 * lt);
        aq[ks][3] = LD32(Qh + (wm + 8 + lg) * FQS + ks * 16 + 8 + 2 * lt);
    }

    float acc_o[8][4];
    #pragma unroll
    for (int j = 0; j < 8; j++)
        #pragma unroll
        for (int rr = 0; rr < 4; rr++) acc_o[j][rr] = 0.f;
    float m0 = -1e30f, m1 = -1e30f, l0 = 0.f, l1 = 0.f;

    for (int it = 0; it < NKV; it++) {
        int buf = it % 3;
        if (it < NKV - 1) asm volatile("cp.async.wait_group 1;");
        else              asm volatile("cp.async.wait_group 0;");
        __syncthreads();                      // single barrier per tile
        if (it + 2 < NKV) load_kv((it + 2) % 3, it + 2);

        const __half* Kt  = Ksm + buf * 64 * FQS;
        const __half* Vt  = Vsm + buf * 64 * FQS;
        const float*  MBt = MB + buf * 64;

        float accs[8][4];
        #pragma unroll
        for (int j = 0; j < 8; j++)
            #pragma unroll
            for (int rr = 0; rr < 4; rr++) accs[j][rr] = 0.f;
        #pragma unroll
        for (int ks = 0; ks < 4; ks++) {
            #pragma unroll
            for (int j = 0; j < 8; j++) {
                uint32_t b0 = LD32(Kt + (j * 8 + lg) * FQS + ks * 16 + 2 * lt);
                uint32_t b1 = LD32(Kt + (j * 8 + lg) * FQS + ks * 16 + 8 + 2 * lt);
                mma_f16(accs[j][0], accs[j][1], accs[j][2], accs[j][3],
                        aq[ks][0], aq[ks][1], aq[ks][2], aq[ks][3], b0, b1);
            }
        }

        float mr0 = -1e30f, mr1 = -1e30f;
        #pragma unroll
        for (int j = 0; j < 8; j++) {
            float2 mbv = *(const float2*)&MBt[j * 8 + 2 * lt];
            accs[j][0] += mbv.x;
            accs[j][1] += mbv.y;
            accs[j][2] += mbv.x;
            accs[j][3] += mbv.y;
            mr0 = fmaxf(mr0, fmaxf(accs[j][0], accs[j][1]));
            mr1 = fmaxf(mr1, fmaxf(accs[j][2], accs[j][3]));
        }
        mr0 = fmaxf(mr0, __shfl_xor_sync(0xffffffffu, mr0, 1));
        mr0 = fmaxf(mr0, __shfl_xor_sync(0xffffffffu, mr0, 2));
        mr1 = fmaxf(mr1, __shfl_xor_sync(0xffffffffu, mr1, 1));
        mr1 = fmaxf(mr1, __shfl_xor_sync(0xffffffffu, mr1, 2));

        float mn0 = fmaxf(m0, mr0), mn1 = fmaxf(m1, mr1);
        float al0 = __expf(m0 - mn0), al1 = __expf(m1 - mn1);
        m0 = mn0; m1 = mn1;

        uint32_t pp[8][2];
        float ps0 = 0.f, ps1 = 0.f;
        #pragma unroll
        for (int j = 0; j < 8; j++) {
            float p0 = __expf(accs[j][0] - mn0);
            float p1 = __expf(accs[j][1] - mn0);
            float p2 = __expf(accs[j][2] - mn1);
            float p3 = __expf(accs[j][3] - mn1);
            ps0 += p0 + p1;
            ps1 += p2 + p3;
            pp[j][0] = pack_h2(p0, p1);
            pp[j][1] = pack_h2(p2, p3);
        }
        ps0 += __shfl_xor_sync(0xffffffffu, ps0, 1);
        ps0 += __shfl_xor_sync(0xffffffffu, ps0, 2);
        ps1 += __shfl_xor_sync(0xffffffffu, ps1, 1);
        ps1 += __shfl_xor_sync(0xffffffffu, ps1, 2);
        l0 = l0 * al0 + ps0;
        l1 = l1 * al1 + ps1;

        if (!__all_sync(0xffffffffu, (al0 == 1.f) && (al1 == 1.f))) {
            #pragma unroll
            for (int j = 0; j < 8; j++) {
                acc_o[j][0] *= al0; acc_o[j][1] *= al0;
                acc_o[j][2] *= al1; acc_o[j][3] *= al1;
            }
        }

        #pragma unroll
        for (int kk = 0; kk < 4; kk++) {
            uint32_t a0 = pp[2 * kk][0];
            uint32_t a1 = pp[2 * kk][1];
            uint32_t a2 = pp[2 * kk + 1][0];
            uint32_t a3 = pp[2 * kk + 1][1];
            #pragma unroll
            for (int j = 0; j < 8; j++) {
                uint32_t b0 = LD32(Vt + (j * 8 + lg) * FQS + kk * 16 + 2 * lt);
                uint32_t b1 = LD32(Vt + (j * 8 + lg) * FQS + kk * 16 + 8 + 2 * lt);
                mma_f16(acc_o[j][0], acc_o[j][1], acc_o[j][2], acc_o[j][3],
                        a0, a1, a2, a3, b0, b1);
            }
        }
    }

    float i0 = 1.f / l0, i1 = 1.f / l1;
    int r0 = brow + wm + lg;
    int tok0 = b * S_ + r0;
    #pragma unroll
    for (int j = 0; j < 8; j++) {
        int col = h * DH_ + j * 8 + 2 * lt;
        *(__half2*)&out[(size_t)tok0 * H_ + col] =
            __floats2half2_rn(acc_o[j][0] * i0, acc_o[j][1] * i0);
        *(__half2*)&out[(size_t)(tok0 + 8) * H_ + col] =
            __floats2half2_rn(acc_o[j][2] * i1, acc_o[j][3] * i1);
    }
}

// ------- residual + LayerNorm over (ya+yb); out float, out_r half ----
__global__ __launch_bounds__(256) void add_ln_kernel(
    const float* __restrict__ xin,
    const float* __restrict__ ya, const float* __restrict__ yb,
    const float* __restrict__ gamma, const float* __restrict__ beta,
    float* __restrict__ out, __half* __restrict__ out_r)
{
    int t = blockIdx.x;
    int tid = threadIdx.x;
    size_t base = (size_t)t * H_;
    float v0 = ya[base + tid]       + yb[base + tid];
    float v1 = ya[base + tid + 256] + yb[base + tid + 256];
    __shared__ float s1[256], s2[256];
    s1[tid] = v0 + v1;
    s2[tid] = v0 * v0 + v1 * v1;
    __syncthreads();
    for (int off = 128; off > 0; off >>= 1) {
        if (tid < off) { s1[tid] += s1[tid + off]; s2[tid] += s2[tid + off]; }
        __syncthreads();
    }
    float mean = s1[0] * (1.f / (float)H_);
    float var  = s2[0] * (1.f / (float)H_) - mean * mean;
    float r = rsqrtf(var + 1e-5f);
    float o0 = xin[base + tid]       + (v0 - mean) * r * gamma[tid]       + beta[tid];
    float o1 = xin[base + tid + 256] + (v1 - mean) * r * gamma[tid + 256] + beta[tid + 256];
    out[base + tid]         = o0;
    out[base + tid + 256]   = o1;
    out_r[base + tid]       = __float2half_rn(o0);
    out_r[base + tid + 256] = __float2half_rn(o1);
}

// ---------------- host launcher ----------------
extern "C" void kernel_launch(void* const* d_in, const int* in_sizes, int n_in,
                              void* d_out, int out_size)
{
    const int*   src  = (const int*)  d_in[0];
    const int*   mask = (const int*)  d_in[1];
    const float* emb  = (const float*)d_in[2];
    const float* Wq   = (const float*)d_in[3];
    const float* bq   = (const float*)d_in[4];
    const float* Wk   = (const float*)d_in[5];
    const float* bk   = (const float*)d_in[6];
    const float* Wv   = (const float*)d_in[7];
    const float* bv   = (const float*)d_in[8];
    const float* Wo   = (const float*)d_in[9];
    const float* bo   = (const float*)d_in[10];
    const float* gamma= (const float*)d_in[11];
    const float* beta = (const float*)d_in[12];
    const float* W1   = (const float*)d_in[13];
    const float* b1   = (const float*)d_in[14];
    const float* W2   = (const float*)d_in[15];
    const float* b2   = (const float*)d_in[16];

    float *x, *res, *t2a, *t2b, *mb;
    __half *xr, *q, *k, *vt, *t, *resr, *h1, *wh;
    cudaGetSymbolAddress((void**)&x,    g_x);
    cudaGetSymbolAddress((void**)&res,  g_res);
    cudaGetSymbolAddress((void**)&t2a,  g_t2a);
    cudaGetSymbolAddress((void**)&t2b,  g_t2b);
    cudaGetSymbolAddress((void**)&mb,   g_mb);
    cudaGetSymbolAddress((void**)&xr,   g_xr);
    cudaGetSymbolAddress((void**)&q,    g_q);
    cudaGetSymbolAddress((void**)&k,    g_k);
    cudaGetSymbolAddress((void**)&vt,   g_vt);
    cudaGetSymbolAddress((void**)&t,    g_t);
    cudaGetSymbolAddress((void**)&resr, g_resr);
    cudaGetSymbolAddress((void**)&h1,   g_h1);
    cudaGetSymbolAddress((void**)&wh,   g_wh);

    cudaFuncSetAttribute(flash_kernel,
                         cudaFuncAttributeMaxDynamicSharedMemorySize, FLASH_SMEM);
    cudaFuncSetAttribute(gemm_qkv,
                         cudaFuncAttributeMaxDynamicSharedMemorySize, GEMM_SMEM);
    cudaFuncSetAttribute(gemm_h,
                         cudaFuncAttributeMaxDynamicSharedMemorySize, GEMM_SMEM);
    cudaFuncSetAttribute(gemm_sk,
                         cudaFuncAttributeMaxDynamicSharedMemorySize, GEMM_SMEM);

    transpose_all_kernel<<<L_ * 3072, 256>>>(Wq, Wk, Wv, Wo, W1, W2, wh);

    embed_kernel<<<(M_ * H_) / 256, 256>>>(src, emb, x, xr);
    maskbias_kernel<<<(M_ + 255) / 256, 256>>>(mask, mb);

    dim3 gQKV (H_ / 128,  M_ / 128, 3);          // 384
    dim3 gSK  (H_ / 128,  M_ / 128, 2);          // 256
    dim3 gFfn1(FF_ / 128, M_ / 128, 1);          // 512
    dim3 gFlash(S_ / 128, B_ * NH_);             // 256

    for (int i = 0; i < L_; i++) {
        const __half* WqT = wh + WOFF_Q + (size_t)i * H_ * H_;
        const __half* WkT = wh + WOFF_K + (size_t)i * H_ * H_;
        const __half* WvT = wh + WOFF_V + (size_t)i * H_ * H_;
        const __half* WoT = wh + WOFF_O + (size_t)i * H_ * H_;
        const __half* W1T = wh + WOFF_1 + (size_t)i * H_ * FF_;
        const __half* W2T = wh + WOFF_2 + (size_t)i * FF_ * H_;
        const float* bq_i = bq + i * H_;
        const float* bk_i = bk + i * H_;
        const float* bv_i = bv + i * H_;
        const float* bo_i = bo + i * H_;
        const float* b1_i = b1 + i * FF_;
        const float* b2_i = b2 + i * H_;
        const float* g_i  = gamma + i * H_;
        const float* be_i = beta  + i * H_;
        float* xout = (i == L_ - 1) ? (float*)d_out : x;

        gemm_qkv<<<gQKV, 256, GEMM_SMEM>>>(
            xr, WqT, WkT, WvT, bq_i, bk_i, bv_i, q, k, vt, H_, H_);

        flash_kernel<<<gFlash, 256, FLASH_SMEM>>>(q, k, vt, mb, t);

        gemm_sk<<<gSK, 256, GEMM_SMEM>>>(t, WoT, bo_i, t2a, t2b, H_, H_);
        add_ln_kernel<<<M_, 256>>>(x, t2a, t2b, g_i, be_i, res, resr);

        gemm_h<<<gFfn1, 256, GEMM_SMEM>>>(resr, W1T, b1_i, h1, FF_, H_);

        gemm_sk<<<gSK, 256, GEMM_SMEM>>>(h1, W2T, b2_i, t2a, t2b, H_, FF_);
        add_ln_kernel<<<M_, 256>>>(res, t2a, t2b, g_i, be_i, xout, resr);
        xr = resr;
    }
}

// round 13
// speedup vs baseline: 1.9321x; 1.0707x over previous
#include <cuda_runtime.h>
#include <cuda_fp16.h>
#include <math.h>
#include <stdint.h>

// Problem dims
#define B_  2
#define S_  2048
#define H_  512
#define NH_ 8
#define DH_ 64
#define L_  6
#define FF_ 2048
#define M_  (B_*S_)

// ---------------- device scratch ----------------
__device__ float  g_x  [M_*H_];
__device__ float  g_res[M_*H_];
__device__ float  g_t2a[M_*H_];
__device__ float  g_t2b[M_*H_];
__device__ float  g_mb [M_];
__device__ __half g_xr [M_*H_];
__device__ __half g_q  [M_*H_];
__device__ __half g_k  [M_*H_];
__device__ __half g_vt [M_*H_];     // V transposed: [(b*512+d)][s]
__device__ __half g_t  [M_*H_];
__device__ __half g_resr[M_*H_];
__device__ __half g_h1 [M_*FF_];
__device__ __half g_wh [18874368];  // transposed half weights [N][K]

#define WOFF_Q  0
#define WOFF_K  (L_*H_*H_)
#define WOFF_V  (2*L_*H_*H_)
#define WOFF_O  (3*L_*H_*H_)
#define WOFF_1  (4*L_*H_*H_)
#define WOFF_2  (4*L_*H_*H_ + L_*H_*FF_)

// ---------------- helpers ----------------
__device__ __forceinline__ void mma_f16(
    float& c0, float& c1, float& c2, float& c3,
    uint32_t a0, uint32_t a1, uint32_t a2, uint32_t a3,
    uint32_t b0, uint32_t b1)
{
    asm volatile(
        "mma.sync.aligned.m16n8k16.row.col.f32.f16.f16.f32 "
        "{%0,%1,%2,%3}, {%4,%5,%6,%7}, {%8,%9}, {%0,%1,%2,%3};\n"
        : "+f"(c0), "+f"(c1), "+f"(c2), "+f"(c3)
        : "r"(a0), "r"(a1), "r"(a2), "r"(a3), "r"(b0), "r"(b1));
}
__device__ __forceinline__ void ldsm_x4(
    uint32_t& r0, uint32_t& r1, uint32_t& r2, uint32_t& r3, uint32_t addr)
{
    asm volatile(
        "ldmatrix.sync.aligned.m8n8.x4.shared.b16 {%0,%1,%2,%3}, [%4];"
        : "=r"(r0), "=r"(r1), "=r"(r2), "=r"(r3) : "r"(addr));
}
__device__ __forceinline__ uint32_t smem_u32(const void* p) {
    return (uint32_t)__cvta_generic_to_shared(p);
}
__device__ __forceinline__ uint32_t pack_h2(float lo, float hi) {
    __half2 h = __floats2half2_rn(lo, hi);
    return *(uint32_t*)&h;
}
__device__ __forceinline__ void cp_async16f(float* dst, const float* src) {
    unsigned s = (unsigned)__cvta_generic_to_shared(dst);
    asm volatile("cp.async.cg.shared.global [%0], [%1], 16;" :: "r"(s), "l"(src));
}
__device__ __forceinline__ void cp_async16h(__half* dst, const __half* src) {
    unsigned s = (unsigned)__cvta_generic_to_shared(dst);
    asm volatile("cp.async.cg.shared.global [%0], [%1], 16;" :: "r"(s), "l"(src));
}
__device__ __forceinline__ void cp_commit() {
    asm volatile("cp.async.commit_group;");
}

// ---------------- fused weight transpose (one launch) ----------------
__global__ __launch_bounds__(256) void transpose_all_kernel(
    const float* __restrict__ Wq, const float* __restrict__ Wk,
    const float* __restrict__ Wv, const float* __restrict__ Wo,
    const float* __restrict__ W1, const float* __restrict__ W2,
    __half* __restrict__ wh)
{
    __shared__ float tile[32][33];
    int idx = blockIdx.x;
    int layer = idx / 3072;
    int r = idx % 3072;

    const float* src;
    __half* dst;
    int K, N, nt, kt;
    if (r < 1024) {
        int m = r >> 8, t = r & 255;
        nt = t & 15; kt = t >> 4;
        K = H_; N = H_;
        src = (m == 0) ? Wq : (m == 1) ? Wk : (m == 2) ? Wv : Wo;
        dst = wh + (size_t)m * (L_ * H_ * H_);
        src += (size_t)layer * H_ * H_;
        dst += (size_t)layer * H_ * H_;
    } else if (r < 2048) {
        int t = r - 1024;
        nt = t & 63; kt = t >> 6;
        K = H_; N = FF_;
        src = W1 + (size_t)layer * H_ * FF_;
        dst = wh + WOFF_1 + (size_t)layer * H_ * FF_;
    } else {
        int t = r - 2048;
        nt = t & 15; kt = t >> 4;
        K = FF_; N = H_;
        src = W2 + (size_t)layer * FF_ * H_;
        dst = wh + WOFF_2 + (size_t)layer * FF_ * H_;
    }

    int n0 = nt * 32, k0 = kt * 32;
    int tx = threadIdx.x & 31, ty = threadIdx.x >> 5;
    #pragma unroll
    for (int i = 0; i < 4; i++)
        tile[ty + i * 8][tx] = src[(size_t)(k0 + ty + i * 8) * N + n0 + tx];
    __syncthreads();
    #pragma unroll
    for (int i = 0; i < 4; i++)
        dst[(size_t)(n0 + ty + i * 8) * K + k0 + tx] =
            __float2half_rn(tile[tx][ty + i * 8]);
}

// ---------------- embedding + posenc ----------------
__global__ __launch_bounds__(256) void embed_kernel(
    const int* __restrict__ src, const float* __restrict__ emb,
    float* __restrict__ x, __half* __restrict__ xr)
{
    int idx = blockIdx.x * 256 + threadIdx.x;
    int d   = idx & (H_ - 1);
    int tok = idx >> 9;
    int s   = tok & (S_ - 1);
    int j2  = (d >> 1) * 2;
    float div = powf(10000.0f, (float)j2 * (1.0f / (float)H_));
    float arg = (float)s / div;
    float pe  = (d & 1) ? cosf(arg) : sinf(arg);
    float v = emb[(size_t)src[tok] * H_ + d] + pe;
    x[idx]  = v;
    xr[idx] = __float2half_rn(v);
}

__global__ __launch_bounds__(256) void maskbias_kernel(
    const int* __restrict__ mask, float* __restrict__ mb)
{
    int i = blockIdx.x * 256 + threadIdx.x;
    if (i < M_) mb[i] = mask[i] ? 0.f : -1e20f;
}

// =========================================================================
// fp16 GEMM core, BK=64, single-barrier 3-stage pipeline, LDSM fragments.
// =========================================================================
#define GST 72
#define STAGE_H (128 * GST)
#define GEMM_SMEM (3 * 2 * STAGE_H * 2)

template<bool RELU, int OUT>
__device__ __forceinline__ void gemm_core(
    const __half* __restrict__ A, const __half* __restrict__ Wt,
    const float* __restrict__ bias, float biasScale, float outScale,
    void* Cv, int brow, int bcol, int N, int Kfull, int koff, int Kspan)
{
    extern __shared__ char smraw[];
    __half* sbase = (__half*)smraw;
    uint32_t sm_u = smem_u32(sbase);

    int tid  = threadIdx.x;
    int lane = tid & 31;
    int warp = tid >> 5;
    int warp_m = (warp >> 1) * 32;
    int warp_n = (warp & 1) * 64;
    int lg = lane >> 2, lt = lane & 3;
    int g  = lane >> 3, lr = lane & 7;

    // ldmatrix per-lane row offsets (in halves)
    int a_off[2], b_off[4];
    #pragma unroll
    for (int i = 0; i < 2; i++)
        a_off[i] = (warp_m + i * 16 + (g & 1) * 8 + lr) * GST + (g >> 1) * 8;
    #pragma unroll
    for (int p = 0; p < 4; p++)
        b_off[p] = (warp_n + p * 16 + (g >> 1) * 8 + lr) * GST + (g & 1) * 8;

    auto load_tile = [&](int st, int k0) {
        __half* as = sbase + st * 2 * STAGE_H;
        __half* bs = as + STAGE_H;
        #pragma unroll
        for (int i = 0; i < 4; i++) {
            int ci = tid + i * 256;
            int r = ci >> 3, c8 = ci & 7;
            cp_async16h(as + r * GST + c8 * 8,
                        A  + (size_t)(brow + r) * Kfull + koff + k0 + c8 * 8);
            cp_async16h(bs + r * GST + c8 * 8,
                        Wt + (size_t)(bcol + r) * Kfull + koff + k0 + c8 * 8);
        }
        cp_commit();
    };

    int nk = Kspan / 64;
    load_tile(0, 0);
    load_tile(1, 64);

    float acc[2][8][4];
    #pragma unroll
    for (int i = 0; i < 2; i++)
        #pragma unroll
        for (int j = 0; j < 8; j++)
            #pragma unroll
            for (int r = 0; r < 4; r++) acc[i][j][r] = 0.f;

    for (int t = 0; t < nk; t++) {
        if (t < nk - 1) asm volatile("cp.async.wait_group 1;");
        else            asm volatile("cp.async.wait_group 0;");
        __syncthreads();
        if (t + 2 < nk) load_tile((t + 2) % 3, (t + 2) * 64);

        uint32_t as_u = sm_u + (t % 3) * 2 * STAGE_H * 2;
        uint32_t bs_u = as_u + STAGE_H * 2;

        #pragma unroll
        for (int ks = 0; ks < 64; ks += 16) {
            uint32_t af[2][4];
            #pragma unroll
            for (int i = 0; i < 2; i++)
                ldsm_x4(af[i][0], af[i][1], af[i][2], af[i][3],
                        as_u + (uint32_t)(a_off[i] + ks) * 2);
            uint32_t bf[8][2];
            #pragma unroll
            for (int p = 0; p < 4; p++)
                ldsm_x4(bf[2 * p][0], bf[2 * p][1], bf[2 * p + 1][0], bf[2 * p + 1][1],
                        bs_u + (uint32_t)(b_off[p] + ks) * 2);
            #pragma unroll
            for (int i = 0; i < 2; i++)
                #pragma unroll
                for (int j = 0; j < 8; j++)
                    mma_f16(acc[i][j][0], acc[i][j][1], acc[i][j][2], acc[i][j][3],
                            af[i][0], af[i][1], af[i][2], af[i][3],
                            bf[j][0], bf[j][1]);
        }
    }

    #pragma unroll
    for (int i = 0; i < 2; i++) {
        #pragma unroll
        for (int j = 0; j < 8; j++) {
            int col = bcol + warp_n + j * 8 + 2 * lt;
            float bx = bias[col] * biasScale, by = bias[col + 1] * biasScale;
            int r0 = brow + warp_m + i * 16 + lg;
            float v0x = (acc[i][j][0] + bx) * outScale;
            float v0y = (acc[i][j][1] + by) * outScale;
            float v1x = (acc[i][j][2] + bx) * outScale;
            float v1y = (acc[i][j][3] + by) * outScale;
            if (RELU) {
                v0x = fmaxf(v0x, 0.f); v0y = fmaxf(v0y, 0.f);
                v1x = fmaxf(v1x, 0.f); v1y = fmaxf(v1y, 0.f);
            }
            if (OUT == 0) {
                float* C = (float*)Cv;
                *(float2*)&C[(size_t)r0 * N + col]       = make_float2(v0x, v0y);
                *(float2*)&C[(size_t)(r0 + 8) * N + col] = make_float2(v1x, v1y);
            } else if (OUT == 1) {
                __half* C = (__half*)Cv;
                *(__half2*)&C[(size_t)r0 * N + col]       = __floats2half2_rn(v0x, v0y);
                *(__half2*)&C[(size_t)(r0 + 8) * N + col] = __floats2half2_rn(v1x, v1y);
            } else {
                __half* C = (__half*)Cv;
                int bb = r0 >> 11, s = r0 & 2047;
                size_t base0 = (size_t)(bb * 512 + col) * 2048;
                size_t base1 = (size_t)(bb * 512 + col + 1) * 2048;
                C[base0 + s]     = __float2half_rn(v0x);
                C[base1 + s]     = __float2half_rn(v0y);
                C[base0 + s + 8] = __float2half_rn(v1x);
                C[base1 + s + 8] = __float2half_rn(v1y);
            }
        }
    }
}

__global__ __launch_bounds__(256, 2) void gemm_qkv(
    const __half* __restrict__ A,
    const __half* __restrict__ Wq, const __half* __restrict__ Wk, const __half* __restrict__ Wv,
    const float* __restrict__ bq, const float* __restrict__ bk, const float* __restrict__ bv,
    __half* q, __half* k, __half* vt, int N, int K)
{
    int z = blockIdx.z;
    if (z == 0)
        gemm_core<false, 1>(A, Wq, bq, 1.f, 0.125f, q,
                            blockIdx.y * 128, blockIdx.x * 128, N, K, 0, K);
    else if (z == 1)
        gemm_core<false, 1>(A, Wk, bk, 1.f, 1.f, k,
                            blockIdx.y * 128, blockIdx.x * 128, N, K, 0, K);
    else
        gemm_core<false, 2>(A, Wv, bv, 1.f, 1.f, vt,
                            blockIdx.y * 128, blockIdx.x * 128, N, K, 0, K);
}

__global__ __launch_bounds__(256, 2) void gemm_h(
    const __half* __restrict__ A, const __half* __restrict__ Wt,
    const float* __restrict__ bias, __half* C, int N, int K)
{
    gemm_core<true, 1>(A, Wt, bias, 1.f, 1.f, C,
                       blockIdx.y * 128, blockIdx.x * 128, N, K, 0, K);
}

__global__ __launch_bounds__(256, 2) void gemm_sk(
    const __half* __restrict__ A, const __half* __restrict__ Wt,
    const float* __restrict__ bias, float* C0, float* C1, int N, int K)
{
    int z = blockIdx.z;
    int Kh = K >> 1;
    gemm_core<false, 0>(A, Wt, bias, z == 0 ? 1.f : 0.f, 1.f,
                        z == 0 ? (void*)C0 : (void*)C1,
                        blockIdx.y * 128, blockIdx.x * 128, N, K, z * Kh, Kh);
}

// =========================================================================
// fp16 flash attention: 3 KV buffers, single barrier per tile, LDSM frags.
// =========================================================================
#define FQS 72
#define NKV (S_ / 64)
#define FLASH_SMEM (128*FQS*2 + 3*64*FQS*2 + 3*64*FQS*2 + 3*64*4)

__global__ __launch_bounds__(256, 2) void flash_kernel(
    const __half* __restrict__ q, const __half* __restrict__ k,
    const __half* __restrict__ vt, const float* __restrict__ mbias,
    __half* __restrict__ out)
{
    extern __shared__ char smraw[];
    __half* Qh  = (__half*)smraw;
    __half* Ksm = Qh + 128 * FQS;
    __half* Vsm = Ksm + 3 * 64 * FQS;
    float*  MB  = (float*)(Vsm + 3 * 64 * FQS);

    int tid  = threadIdx.x;
    int lane = tid & 31;
    int warp = tid >> 5;
    int wm   = warp * 16;
    int lg = lane >> 2, lt = lane & 3;
    int g  = lane >> 3, lr = lane & 7;
    int brow = blockIdx.x * 128;
    int bh = blockIdx.y;
    int b = bh >> 3, h = bh & 7;

    const __half* Qb  = q  + (size_t)b * S_ * H_ + h * DH_;
    const __half* Kb  = k  + (size_t)b * S_ * H_ + h * DH_;
    const __half* Vtb = vt + (size_t)(b * 512 + h * 64) * 2048;
    const float*  MBg = mbias + b * S_;

    // ldmatrix offsets (halves): A-pattern (Q), B-pattern (K and V pairs)
    int q_off = (wm + (g & 1) * 8 + lr) * FQS + (g >> 1) * 8;
    int kv_off[4];
    #pragma unroll
    for (int p = 0; p < 4; p++)
        kv_off[p] = (p * 16 + (g >> 1) * 8 + lr) * FQS + (g & 1) * 8;

    auto load_kv = [&](int buf, int it) {
        int kv0 = it * 64;
        __half* kd = Ksm + buf * 64 * FQS;
        __half* vd = Vsm + buf * 64 * FQS;
        #pragma unroll
        for (int i = 0; i < 2; i++) {
            int ci = tid + i * 256;
            int r = ci >> 3, c8 = ci & 7;
            cp_async16h(kd + r * FQS + c8 * 8,
                        Kb + (size_t)(kv0 + r) * H_ + c8 * 8);
            cp_async16h(vd + r * FQS + c8 * 8,
                        Vtb + (size_t)r * S_ + kv0 + c8 * 8);
        }
        if (tid < 16) cp_async16f(&MB[buf * 64 + tid * 4], MBg + kv0 + tid * 4);
        cp_commit();
    };

    #pragma unroll
    for (int i = 0; i < 4; i++) {
        int ci = tid + i * 256;
        int r = ci >> 3, c8 = ci & 7;
        cp_async16h(Qh + r * FQS + c8 * 8,
                    Qb + (size_t)(brow + r) * H_ + c8 * 8);
    }
    cp_commit();
    load_kv(0, 0);
    load_kv(1, 1);
    asm volatile("cp.async.wait_group 2;");
    __syncthreads();

    uint32_t qh_u = smem_u32(Qh);
    uint32_t aq[4][4];
    #pragma unroll
    for (int ks = 0; ks < 4; ks++)
        ldsm_x4(aq[ks][0], aq[ks][1], aq[ks][2], aq[ks][3],
                qh_u + (uint32_t)(q_off + ks * 16) * 2);

    float acc_o[8][4];
    #pragma unroll
    for (int j = 0; j < 8; j++)
        #pragma unroll
        for (int rr = 0; rr < 4; rr++) acc_o[j][rr] = 0.f;
    float m0 = -1e30f, m1 = -1e30f, l0 = 0.f, l1 = 0.f;

    for (int it = 0; it < NKV; it++) {
        int buf = it % 3;
        if (it < NKV - 1) asm volatile("cp.async.wait_group 1;");
        else              asm volatile("cp.async.wait_group 0;");
        __syncthreads();
        if (it + 2 < NKV) load_kv((it + 2) % 3, it + 2);

        uint32_t kt_u = smem_u32(Ksm + buf * 64 * FQS);
        uint32_t vt_u = smem_u32(Vsm + buf * 64 * FQS);
        const float* MBt = MB + buf * 64;

        // ---- S = Qs @ K^T ----
        float accs[8][4];
        #pragma unroll
        for (int j = 0; j < 8; j++)
            #pragma unroll
            for (int rr = 0; rr < 4; rr++) accs[j][rr] = 0.f;
        #pragma unroll
        for (int ks = 0; ks < 4; ks++) {
            uint32_t bf[8][2];
            #pragma unroll
            for (int p = 0; p < 4; p++)
                ldsm_x4(bf[2 * p][0], bf[2 * p][1], bf[2 * p + 1][0], bf[2 * p + 1][1],
                        kt_u + (uint32_t)(kv_off[p] + ks * 16) * 2);
            #pragma unroll
            for (int j = 0; j < 8; j++)
                mma_f16(accs[j][0], accs[j][1], accs[j][2], accs[j][3],
                        aq[ks][0], aq[ks][1], aq[ks][2], aq[ks][3],
                        bf[j][0], bf[j][1]);
        }

        // ---- + mask bias, row max ----
        float mr0 = -1e30f, mr1 = -1e30f;
        #pragma unroll
        for (int j = 0; j < 8; j++) {
            float2 mbv = *(const float2*)&MBt[j * 8 + 2 * lt];
            accs[j][0] += mbv.x;
            accs[j][1] += mbv.y;
            accs[j][2] += mbv.x;
            accs[j][3] += mbv.y;
            mr0 = fmaxf(mr0, fmaxf(accs[j][0], accs[j][1]));
            mr1 = fmaxf(mr1, fmaxf(accs[j][2], accs[j][3]));
        }
        mr0 = fmaxf(mr0, __shfl_xor_sync(0xffffffffu, mr0, 1));
        mr0 = fmaxf(mr0, __shfl_xor_sync(0xffffffffu, mr0, 2));
        mr1 = fmaxf(mr1, __shfl_xor_sync(0xffffffffu, mr1, 1));
        mr1 = fmaxf(mr1, __shfl_xor_sync(0xffffffffu, mr1, 2));

        float mn0 = fmaxf(m0, mr0), mn1 = fmaxf(m1, mr1);
        float al0 = __expf(m0 - mn0), al1 = __expf(m1 - mn1);
        m0 = mn0; m1 = mn1;

        uint32_t pp[8][2];
        float ps0 = 0.f, ps1 = 0.f;
        #pragma unroll
        for (int j = 0; j < 8; j++) {
            float p0 = __expf(accs[j][0] - mn0);
            float p1 = __expf(accs[j][1] - mn0);
            float p2 = __expf(accs[j][2] - mn1);
            float p3 = __expf(accs[j][3] - mn1);
            ps0 += p0 + p1;
            ps1 += p2 + p3;
            pp[j][0] = pack_h2(p0, p1);
            pp[j][1] = pack_h2(p2, p3);
        }
        ps0 += __shfl_xor_sync(0xffffffffu, ps0, 1);
        ps0 += __shfl_xor_sync(0xffffffffu, ps0, 2);
        ps1 += __shfl_xor_sync(0xffffffffu, ps1, 1);
        ps1 += __shfl_xor_sync(0xffffffffu, ps1, 2);
        l0 = l0 * al0 + ps0;
        l1 = l1 * al1 + ps1;

        if (!__all_sync(0xffffffffu, (al0 == 1.f) && (al1 == 1.f))) {
            #pragma unroll
            for (int j = 0; j < 8; j++) {
                acc_o[j][0] *= al0; acc_o[j][1] *= al0;
                acc_o[j][2] *= al1; acc_o[j][3] *= al1;
            }
        }

        // ---- O += P @ V ----
        #pragma unroll
        for (int kk = 0; kk < 4; kk++) {
            uint32_t a0 = pp[2 * kk][0];
            uint32_t a1 = pp[2 * kk][1];
            uint32_t a2 = pp[2 * kk + 1][0];
            uint32_t a3 = pp[2 * kk + 1][1];
            uint32_t bf[8][2];
            #pragma unroll
            for (int p = 0; p < 4; p++)
                ldsm_x4(bf[2 * p][0], bf[2 * p][1], bf[2 * p + 1][0], bf[2 * p + 1][1],
                        vt_u + (uint32_t)(kv_off[p] + kk * 16) * 2);
            #pragma unroll
            for (int j = 0; j < 8; j++)
                mma_f16(acc_o[j][0], acc_o[j][1], acc_o[j][2], acc_o[j][3],
                        a0, a1, a2, a3, bf[j][0], bf[j][1]);
        }
    }

    float i0 = 1.f / l0, i1 = 1.f / l1;
    int r0 = brow + wm + lg;
    int tok0 = b * S_ + r0;
    #pragma unroll
    for (int j = 0; j < 8; j++) {
        int col = h * DH_ + j * 8 + 2 * lt;
        *(__half2*)&out[(size_t)tok0 * H_ + col] =
            __floats2half2_rn(acc_o[j][0] * i0, acc_o[j][1] * i0);
        *(__half2*)&out[(size_t)(tok0 + 8) * H_ + col] =
            __floats2half2_rn(acc_o[j][2] * i1, acc_o[j][3] * i1);
    }
}

// ------- residual + LayerNorm over (ya+yb); out float, out_r half ----
__global__ __launch_bounds__(256) void add_ln_kernel(
    const float* __restrict__ xin,
    const float* __restrict__ ya, const float* __restrict__ yb,
    const float* __restrict__ gamma, const float* __restrict__ beta,
    float* __restrict__ out, __half* __restrict__ out_r)
{
    int t = blockIdx.x;
    int tid = threadIdx.x;
    size_t base = (size_t)t * H_;
    float v0 = ya[base + tid]       + yb[base + tid];
    float v1 = ya[base + tid + 256] + yb[base + tid + 256];
    __shared__ float s1[256], s2[256];
    s1[tid] = v0 + v1;
    s2[tid] = v0 * v0 + v1 * v1;
    __syncthreads();
    for (int off = 128; off > 0; off >>= 1) {
        if (tid < off) { s1[tid] += s1[tid + off]; s2[tid] += s2[tid + off]; }
        __syncthreads();
    }
    float mean = s1[0] * (1.f / (float)H_);
    float var  = s2[0] * (1.f / (float)H_) - mean * mean;
    float r = rsqrtf(var + 1e-5f);
    float o0 = xin[base + tid]       + (v0 - mean) * r * gamma[tid]       + beta[tid];
    float o1 = xin[base + tid + 256] + (v1 - mean) * r * gamma[tid + 256] + beta[tid + 256];
    out[base + tid]         = o0;
    out[base + tid + 256]   = o1;
    out_r[base + tid]       = __float2half_rn(o0);
    out_r[base + tid + 256] = __float2half_rn(o1);
}

// ---------------- host launcher ----------------
extern "C" void kernel_launch(void* const* d_in, const int* in_sizes, int n_in,
                              void* d_out, int out_size)
{
    const int*   src  = (const int*)  d_in[0];
    const int*   mask = (const int*)  d_in[1];
    const float* emb  = (const float*)d_in[2];
    const float* Wq   = (const float*)d_in[3];
    const float* bq   = (const float*)d_in[4];
    const float* Wk   = (const float*)d_in[5];
    const float* bk   = (const float*)d_in[6];
    const float* Wv   = (const float*)d_in[7];
    const float* bv   = (const float*)d_in[8];
    const float* Wo   = (const float*)d_in[9];
    const float* bo   = (const float*)d_in[10];
    const float* gamma= (const float*)d_in[11];
    const float* beta = (const float*)d_in[12];
    const float* W1   = (const float*)d_in[13];
    const float* b1   = (const float*)d_in[14];
    const float* W2   = (const float*)d_in[15];
    const float* b2   = (const float*)d_in[16];

    float *x, *res, *t2a, *t2b, *mb;
    __half *xr, *q, *k, *vt, *t, *resr, *h1, *wh;
    cudaGetSymbolAddress((void**)&x,    g_x);
    cudaGetSymbolAddress((void**)&res,  g_res);
    cudaGetSymbolAddress((void**)&t2a,  g_t2a);
    cudaGetSymbolAddress((void**)&t2b,  g_t2b);
    cudaGetSymbolAddress((void**)&mb,   g_mb);
    cudaGetSymbolAddress((void**)&xr,   g_xr);
    cudaGetSymbolAddress((void**)&q,    g_q);
    cudaGetSymbolAddress((void**)&k,    g_k);
    cudaGetSymbolAddress((void**)&vt,   g_vt);
    cudaGetSymbolAddress((void**)&t,    g_t);
    cudaGetSymbolAddress((void**)&resr, g_resr);
    cudaGetSymbolAddress((void**)&h1,   g_h1);
    cudaGetSymbolAddress((void**)&wh,   g_wh);

    cudaFuncSetAttribute(flash_kernel,
                         cudaFuncAttributeMaxDynamicSharedMemorySize, FLASH_SMEM);
    cudaFuncSetAttribute(gemm_qkv,
                         cudaFuncAttributeMaxDynamicSharedMemorySize, GEMM_SMEM);
    cudaFuncSetAttribute(gemm_h,
                         cudaFuncAttributeMaxDynamicSharedMemorySize, GEMM_SMEM);
    cudaFuncSetAttribute(gemm_sk,
                         cudaFuncAttributeMaxDynamicSharedMemorySize, GEMM_SMEM);

    transpose_all_kernel<<<L_ * 3072, 256>>>(Wq, Wk, Wv, Wo, W1, W2, wh);

    embed_kernel<<<(M_ * H_) / 256, 256>>>(src, emb, x, xr);
    maskbias_kernel<<<(M_ + 255) / 256, 256>>>(mask, mb);

    dim3 gQKV (H_ / 128,  M_ / 128, 3);
    dim3 gSK  (H_ / 128,  M_ / 128, 2);
    dim3 gFfn1(FF_ / 128, M_ / 128, 1);
    dim3 gFlash(S_ / 128, B_ * NH_);

    for (int i = 0; i < L_; i++) {
        const __half* WqT = wh + WOFF_Q + (size_t)i * H_ * H_;
        const __half* WkT = wh + WOFF_K + (size_t)i * H_ * H_;
        const __half* WvT = wh + WOFF_V + (size_t)i * H_ * H_;
        const __half* WoT = wh + WOFF_O + (size_t)i * H_ * H_;
        const __half* W1T = wh + WOFF_1 + (size_t)i * H_ * FF_;
        const __half* W2T = wh + WOFF_2 + (size_t)i * FF_ * H_;
        const float* bq_i = bq + i * H_;
        const float* bk_i = bk + i * H_;
        const float* bv_i = bv + i * H_;
        const float* bo_i = bo + i * H_;
        const float* b1_i = b1 + i * FF_;
        const float* b2_i = b2 + i * H_;
        const float* g_i  = gamma + i * H_;
        const float* be_i = beta  + i * H_;
        float* xout = (i == L_ - 1) ? (float*)d_out : x;

        gemm_qkv<<<gQKV, 256, GEMM_SMEM>>>(
            xr, WqT, WkT, WvT, bq_i, bk_i, bv_i, q, k, vt, H_, H_);

        flash_kernel<<<gFlash, 256, FLASH_SMEM>>>(q, k, vt, mb, t);

        gemm_sk<<<gSK, 256, GEMM_SMEM>>>(t, WoT, bo_i, t2a, t2b, H_, H_);
        add_ln_kernel<<<M_, 256>>>(x, t2a, t2b, g_i, be_i, res, resr);

        gemm_h<<<gFfn1, 256, GEMM_SMEM>>>(resr, W1T, b1_i, h1, FF_, H_);

        gemm_sk<<<gSK, 256, GEMM_SMEM>>>(h1, W2T, b2_i, t2a, t2b, H_, FF_);
        add_ln_kernel<<<M_, 256>>>(res, t2a, t2b, g_i, be_i, xout, resr);
        xr = resr;
    }
}

// round 14
// speedup vs baseline: 2.0012x; 1.0358x over previous
#include <cuda_runtime.h>
#include <cuda_fp16.h>
#include <math.h>
#include <stdint.h>

// Problem dims
#define B_  2
#define S_  2048
#define H_  512
#define NH_ 8
#define DH_ 64
#define L_  6
#define FF_ 2048
#define M_  (B_*S_)

// ---------------- device scratch ----------------
__device__ float  g_x  [M_*H_];
__device__ float  g_res[M_*H_];
__device__ float  g_t2a[M_*H_];
__device__ float  g_t2b[M_*H_];
__device__ float  g_mb [M_];
__device__ __half g_xr [M_*H_];
__device__ __half g_q  [M_*H_];
__device__ __half g_k  [M_*H_];
__device__ __half g_vt [M_*H_];     // V transposed: [(b*512+d)][s]
__device__ __half g_t  [M_*H_];
__device__ __half g_resr[M_*H_];
__device__ __half g_h1 [M_*FF_];
__device__ __half g_wh [18874368];  // transposed half weights [N][K]

#define WOFF_Q  0
#define WOFF_K  (L_*H_*H_)
#define WOFF_V  (2*L_*H_*H_)
#define WOFF_O  (3*L_*H_*H_)
#define WOFF_1  (4*L_*H_*H_)
#define WOFF_2  (4*L_*H_*H_ + L_*H_*FF_)

// ---------------- helpers ----------------
__device__ __forceinline__ void mma_f16(
    float& c0, float& c1, float& c2, float& c3,
    uint32_t a0, uint32_t a1, uint32_t a2, uint32_t a3,
    uint32_t b0, uint32_t b1)
{
    asm volatile(
        "mma.sync.aligned.m16n8k16.row.col.f32.f16.f16.f32 "
        "{%0,%1,%2,%3}, {%4,%5,%6,%7}, {%8,%9}, {%0,%1,%2,%3};\n"
        : "+f"(c0), "+f"(c1), "+f"(c2), "+f"(c3)
        : "r"(a0), "r"(a1), "r"(a2), "r"(a3), "r"(b0), "r"(b1));
}
__device__ __forceinline__ void ldsm_x4(
    uint32_t& r0, uint32_t& r1, uint32_t& r2, uint32_t& r3, uint32_t addr)
{
    asm volatile(
        "ldmatrix.sync.aligned.m8n8.x4.shared.b16 {%0,%1,%2,%3}, [%4];"
        : "=r"(r0), "=r"(r1), "=r"(r2), "=r"(r3) : "r"(addr));
}
__device__ __forceinline__ uint32_t smem_u32(const void* p) {
    return (uint32_t)__cvta_generic_to_shared(p);
}
__device__ __forceinline__ uint32_t pack_h2(float lo, float hi) {
    __half2 h = __floats2half2_rn(lo, hi);
    return *(uint32_t*)&h;
}
__device__ __forceinline__ void cp_async16f(float* dst, const float* src) {
    unsigned s = (unsigned)__cvta_generic_to_shared(dst);
    asm volatile("cp.async.cg.shared.global [%0], [%1], 16;" :: "r"(s), "l"(src));
}
__device__ __forceinline__ void cp_async16h(__half* dst, const __half* src) {
    unsigned s = (unsigned)__cvta_generic_to_shared(dst);
    asm volatile("cp.async.cg.shared.global [%0], [%1], 16;" :: "r"(s), "l"(src));
}
__device__ __forceinline__ void cp_commit() {
    asm volatile("cp.async.commit_group;");
}

// ---------------- fused weight transpose (one launch) ----------------
__global__ __launch_bounds__(256) void transpose_all_kernel(
    const float* __restrict__ Wq, const float* __restrict__ Wk,
    const float* __restrict__ Wv, const float* __restrict__ Wo,
    const float* __restrict__ W1, const float* __restrict__ W2,
    __half* __restrict__ wh)
{
    __shared__ float tile[32][33];
    int idx = blockIdx.x;
    int layer = idx / 3072;
    int r = idx % 3072;

    const float* src;
    __half* dst;
    int K, N, nt, kt;
    if (r < 1024) {
        int m = r >> 8, t = r & 255;
        nt = t & 15; kt = t >> 4;
        K = H_; N = H_;
        src = (m == 0) ? Wq : (m == 1) ? Wk : (m == 2) ? Wv : Wo;
        dst = wh + (size_t)m * (L_ * H_ * H_);
        src += (size_t)layer * H_ * H_;
        dst += (size_t)layer * H_ * H_;
    } else if (r < 2048) {
        int t = r - 1024;
        nt = t & 63; kt = t >> 6;
        K = H_; N = FF_;
        src = W1 + (size_t)layer * H_ * FF_;
        dst = wh + WOFF_1 + (size_t)layer * H_ * FF_;
    } else {
        int t = r - 2048;
        nt = t & 15; kt = t >> 4;
        K = FF_; N = H_;
        src = W2 + (size_t)layer * FF_ * H_;
        dst = wh + WOFF_2 + (size_t)layer * FF_ * H_;
    }

    int n0 = nt * 32, k0 = kt * 32;
    int tx = threadIdx.x & 31, ty = threadIdx.x >> 5;
    #pragma unroll
    for (int i = 0; i < 4; i++)
        tile[ty + i * 8][tx] = src[(size_t)(k0 + ty + i * 8) * N + n0 + tx];
    __syncthreads();
    #pragma unroll
    for (int i = 0; i < 4; i++)
        dst[(size_t)(n0 + ty + i * 8) * K + k0 + tx] =
            __float2half_rn(tile[tx][ty + i * 8]);
}

// ---------------- embedding + posenc + mask bias (fused) ----------------
__global__ __launch_bounds__(256) void embed_kernel(
    const int* __restrict__ src, const float* __restrict__ emb,
    const int* __restrict__ mask,
    float* __restrict__ x, __half* __restrict__ xr, float* __restrict__ mb)
{
    int idx = blockIdx.x * 256 + threadIdx.x;
    int d   = idx & (H_ - 1);
    int tok = idx >> 9;
    int s   = tok & (S_ - 1);
    int j2  = (d >> 1) * 2;
    float div = powf(10000.0f, (float)j2 * (1.0f / (float)H_));
    float arg = (float)s / div;
    float pe  = (d & 1) ? cosf(arg) : sinf(arg);
    float v = emb[(size_t)src[tok] * H_ + d] + pe;
    x[idx]  = v;
    xr[idx] = __float2half_rn(v);
    if (idx < M_) mb[idx] = mask[idx] ? 0.f : -1e20f;
}

// =========================================================================
// fp16 GEMM core, BK=64, single-barrier 3-stage pipeline, LDSM fragments.
// =========================================================================
#define GST 72
#define STAGE_H (128 * GST)
#define GEMM_SMEM (3 * 2 * STAGE_H * 2)

template<bool RELU, int OUT>
__device__ __forceinline__ void gemm_core(
    const __half* __restrict__ A, const __half* __restrict__ Wt,
    const float* __restrict__ bias, float biasScale, float outScale,
    void* Cv, int brow, int bcol, int N, int Kfull, int koff, int Kspan)
{
    extern __shared__ char smraw[];
    __half* sbase = (__half*)smraw;
    uint32_t sm_u = smem_u32(sbase);

    int tid  = threadIdx.x;
    int lane = tid & 31;
    int warp = tid >> 5;
    int warp_m = (warp >> 1) * 32;
    int warp_n = (warp & 1) * 64;
    int lg = lane >> 2, lt = lane & 3;
    int g  = lane >> 3, lr = lane & 7;

    int a_off[2], b_off[4];
    #pragma unroll
    for (int i = 0; i < 2; i++)
        a_off[i] = (warp_m + i * 16 + (g & 1) * 8 + lr) * GST + (g >> 1) * 8;
    #pragma unroll
    for (int p = 0; p < 4; p++)
        b_off[p] = (warp_n + p * 16 + (g >> 1) * 8 + lr) * GST + (g & 1) * 8;

    auto load_tile = [&](int st, int k0) {
        __half* as = sbase + st * 2 * STAGE_H;
        __half* bs = as + STAGE_H;
        #pragma unroll
        for (int i = 0; i < 4; i++) {
            int ci = tid + i * 256;
            int r = ci >> 3, c8 = ci & 7;
            cp_async16h(as + r * GST + c8 * 8,
                        A  + (size_t)(brow + r) * Kfull + koff + k0 + c8 * 8);
            cp_async16h(bs + r * GST + c8 * 8,
                        Wt + (size_t)(bcol + r) * Kfull + koff + k0 + c8 * 8);
        }
        cp_commit();
    };

    int nk = Kspan / 64;
    load_tile(0, 0);
    load_tile(1, 64);

    float acc[2][8][4];
    #pragma unroll
    for (int i = 0; i < 2; i++)
        #pragma unroll
        for (int j = 0; j < 8; j++)
            #pragma unroll
            for (int r = 0; r < 4; r++) acc[i][j][r] = 0.f;

    for (int t = 0; t < nk; t++) {
        if (t < nk - 1) asm volatile("cp.async.wait_group 1;");
        else            asm volatile("cp.async.wait_group 0;");
        __syncthreads();
        if (t + 2 < nk) load_tile((t + 2) % 3, (t + 2) * 64);

        uint32_t as_u = sm_u + (t % 3) * 2 * STAGE_H * 2;
        uint32_t bs_u = as_u + STAGE_H * 2;

        #pragma unroll
        for (int ks = 0; ks < 64; ks += 16) {
            uint32_t af[2][4];
            #pragma unroll
            for (int i = 0; i < 2; i++)
                ldsm_x4(af[i][0], af[i][1], af[i][2], af[i][3],
                        as_u + (uint32_t)(a_off[i] + ks) * 2);
            uint32_t bf[8][2];
            #pragma unroll
            for (int p = 0; p < 4; p++)
                ldsm_x4(bf[2 * p][0], bf[2 * p][1], bf[2 * p + 1][0], bf[2 * p + 1][1],
                        bs_u + (uint32_t)(b_off[p] + ks) * 2);
            #pragma unroll
            for (int i = 0; i < 2; i++)
                #pragma unroll
                for (int j = 0; j < 8; j++)
                    mma_f16(acc[i][j][0], acc[i][j][1], acc[i][j][2], acc[i][j][3],
                            af[i][0], af[i][1], af[i][2], af[i][3],
                            bf[j][0], bf[j][1]);
        }
    }

    #pragma unroll
    for (int i = 0; i < 2; i++) {
        #pragma unroll
        for (int j = 0; j < 8; j++) {
            int col = bcol + warp_n + j * 8 + 2 * lt;
            float bx = bias[col] * biasScale, by = bias[col + 1] * biasScale;
            int r0 = brow + warp_m + i * 16 + lg;
            float v0x = (acc[i][j][0] + bx) * outScale;
            float v0y = (acc[i][j][1] + by) * outScale;
            float v1x = (acc[i][j][2] + bx) * outScale;
            float v1y = (acc[i][j][3] + by) * outScale;
            if (RELU) {
                v0x = fmaxf(v0x, 0.f); v0y = fmaxf(v0y, 0.f);
                v1x = fmaxf(v1x, 0.f); v1y = fmaxf(v1y, 0.f);
            }
            if (OUT == 0) {
                float* C = (float*)Cv;
                *(float2*)&C[(size_t)r0 * N + col]       = make_float2(v0x, v0y);
                *(float2*)&C[(size_t)(r0 + 8) * N + col] = make_float2(v1x, v1y);
            } else if (OUT == 1) {
                __half* C = (__half*)Cv;
                *(__half2*)&C[(size_t)r0 * N + col]       = __floats2half2_rn(v0x, v0y);
                *(__half2*)&C[(size_t)(r0 + 8) * N + col] = __floats2half2_rn(v1x, v1y);
            } else {
                __half* C = (__half*)Cv;
                int bb = r0 >> 11, s = r0 & 2047;
                size_t base0 = (size_t)(bb * 512 + col) * 2048;
                size_t base1 = (size_t)(bb * 512 + col + 1) * 2048;
                C[base0 + s]     = __float2half_rn(v0x);
                C[base1 + s]     = __float2half_rn(v0y);
                C[base0 + s + 8] = __float2half_rn(v1x);
                C[base1 + s + 8] = __float2half_rn(v1y);
            }
        }
    }
}

__global__ __launch_bounds__(256, 2) void gemm_qkv(
    const __half* __restrict__ A,
    const __half* __restrict__ Wq, const __half* __restrict__ Wk, const __half* __restrict__ Wv,
    const float* __restrict__ bq, const float* __restrict__ bk, const float* __restrict__ bv,
    __half* q, __half* k, __half* vt, int N, int K)
{
    int z = blockIdx.z;
    if (z == 0)
        gemm_core<false, 1>(A, Wq, bq, 1.f, 0.125f, q,
                            blockIdx.y * 128, blockIdx.x * 128, N, K, 0, K);
    else if (z == 1)
        gemm_core<false, 1>(A, Wk, bk, 1.f, 1.f, k,
                            blockIdx.y * 128, blockIdx.x * 128, N, K, 0, K);
    else
        gemm_core<false, 2>(A, Wv, bv, 1.f, 1.f, vt,
                            blockIdx.y * 128, blockIdx.x * 128, N, K, 0, K);
}

__global__ __launch_bounds__(256, 2) void gemm_h(
    const __half* __restrict__ A, const __half* __restrict__ Wt,
    const float* __restrict__ bias, __half* C, int N, int K)
{
    gemm_core<true, 1>(A, Wt, bias, 1.f, 1.f, C,
                       blockIdx.y * 128, blockIdx.x * 128, N, K, 0, K);
}

__global__ __launch_bounds__(256, 2) void gemm_sk(
    const __half* __restrict__ A, const __half* __restrict__ Wt,
    const float* __restrict__ bias, float* C0, float* C1, int N, int K)
{
    int z = blockIdx.z;
    int Kh = K >> 1;
    gemm_core<false, 0>(A, Wt, bias, z == 0 ? 1.f : 0.f, 1.f,
                        z == 0 ? (void*)C0 : (void*)C1,
                        blockIdx.y * 128, blockIdx.x * 128, N, K, z * Kh, Kh);
}

// =========================================================================
// fp16 flash attention: 3 KV buffers, single barrier per tile, LDSM frags.
// =========================================================================
#define FQS 72
#define NKV (S_ / 64)
#define FLASH_SMEM (128*FQS*2 + 3*64*FQS*2 + 3*64*FQS*2 + 3*64*4)

__global__ __launch_bounds__(256, 2) void flash_kernel(
    const __half* __restrict__ q, const __half* __restrict__ k,
    const __half* __restrict__ vt, const float* __restrict__ mbias,
    __half* __restrict__ out)
{
    extern __shared__ char smraw[];
    __half* Qh  = (__half*)smraw;
    __half* Ksm = Qh + 128 * FQS;
    __half* Vsm = Ksm + 3 * 64 * FQS;
    float*  MB  = (float*)(Vsm + 3 * 64 * FQS);

    int tid  = threadIdx.x;
    int lane = tid & 31;
    int warp = tid >> 5;
    int wm   = warp * 16;
    int lg = lane >> 2, lt = lane & 3;
    int g  = lane >> 3, lr = lane & 7;
    int brow = blockIdx.x * 128;
    int bh = blockIdx.y;
    int b = bh >> 3, h = bh & 7;

    const __half* Qb  = q  + (size_t)b * S_ * H_ + h * DH_;
    const __half* Kb  = k  + (size_t)b * S_ * H_ + h * DH_;
    const __half* Vtb = vt + (size_t)(b * 512 + h * 64) * 2048;
    const float*  MBg = mbias + b * S_;

    int q_off = (wm + (g & 1) * 8 + lr) * FQS + (g >> 1) * 8;
    int kv_off[4];
    #pragma unroll
    for (int p = 0; p < 4; p++)
        kv_off[p] = (p * 16 + (g >> 1) * 8 + lr) * FQS + (g & 1) * 8;

    auto load_kv = [&](int buf, int it) {
        int kv0 = it * 64;
        __half* kd = Ksm + buf * 64 * FQS;
        __half* vd = Vsm + buf * 64 * FQS;
        #pragma unroll
        for (int i = 0; i < 2; i++) {
            int ci = tid + i * 256;
            int r = ci >> 3, c8 = ci & 7;
            cp_async16h(kd + r * FQS + c8 * 8,
                        Kb + (size_t)(kv0 + r) * H_ + c8 * 8);
            cp_async16h(vd + r * FQS + c8 * 8,
                        Vtb + (size_t)r * S_ + kv0 + c8 * 8);
        }
        if (tid < 16) cp_async16f(&MB[buf * 64 + tid * 4], MBg + kv0 + tid * 4);
        cp_commit();
    };

    #pragma unroll
    for (int i = 0; i < 4; i++) {
        int ci = tid + i * 256;
        int r = ci >> 3, c8 = ci & 7;
        cp_async16h(Qh + r * FQS + c8 * 8,
                    Qb + (size_t)(brow + r) * H_ + c8 * 8);
    }
    cp_commit();
    load_kv(0, 0);
    load_kv(1, 1);
    asm volatile("cp.async.wait_group 2;");
    __syncthreads();

    uint32_t qh_u = smem_u32(Qh);
    uint32_t aq[4][4];
    #pragma unroll
    for (int ks = 0; ks < 4; ks++)
        ldsm_x4(aq[ks][0], aq[ks][1], aq[ks][2], aq[ks][3],
                qh_u + (uint32_t)(q_off + ks * 16) * 2);

    float acc_o[8][4];
    #pragma unroll
    for (int j = 0; j < 8; j++)
        #pragma unroll
        for (int rr = 0; rr < 4; rr++) acc_o[j][rr] = 0.f;
    float m0 = -1e30f, m1 = -1e30f, l0 = 0.f, l1 = 0.f;

    for (int it = 0; it < NKV; it++) {
        int buf = it % 3;
        if (it < NKV - 1) asm volatile("cp.async.wait_group 1;");
        else              asm volatile("cp.async.wait_group 0;");
        __syncthreads();
        if (it + 2 < NKV) load_kv((it + 2) % 3, it + 2);

        uint32_t kt_u = smem_u32(Ksm + buf * 64 * FQS);
        uint32_t vt_u = smem_u32(Vsm + buf * 64 * FQS);
        const float* MBt = MB + buf * 64;

        float accs[8][4];
        #pragma unroll
        for (int j = 0; j < 8; j++)
            #pragma unroll
            for (int rr = 0; rr < 4; rr++) accs[j][rr] = 0.f;
        #pragma unroll
        for (int ks = 0; ks < 4; ks++) {
            uint32_t bf[8][2];
            #pragma unroll
            for (int p = 0; p < 4; p++)
                ldsm_x4(bf[2 * p][0], bf[2 * p][1], bf[2 * p + 1][0], bf[2 * p + 1][1],
                        kt_u + (uint32_t)(kv_off[p] + ks * 16) * 2);
            #pragma unroll
            for (int j = 0; j < 8; j++)
                mma_f16(accs[j][0], accs[j][1], accs[j][2], accs[j][3],
                        aq[ks][0], aq[ks][1], aq[ks][2], aq[ks][3],
                        bf[j][0], bf[j][1]);
        }

        float mr0 = -1e30f, mr1 = -1e30f;
        #pragma unroll
        for (int j = 0; j < 8; j++) {
            float2 mbv = *(const float2*)&MBt[j * 8 + 2 * lt];
            accs[j][0] += mbv.x;
            accs[j][1] += mbv.y;
            accs[j][2] += mbv.x;
            accs[j][3] += mbv.y;
            mr0 = fmaxf(mr0, fmaxf(accs[j][0], accs[j][1]));
            mr1 = fmaxf(mr1, fmaxf(accs[j][2], accs[j][3]));
        }
        mr0 = fmaxf(mr0, __shfl_xor_sync(0xffffffffu, mr0, 1));
        mr0 = fmaxf(mr0, __shfl_xor_sync(0xffffffffu, mr0, 2));
        mr1 = fmaxf(mr1, __shfl_xor_sync(0xffffffffu, mr1, 1));
        mr1 = fmaxf(mr1, __shfl_xor_sync(0xffffffffu, mr1, 2));

        float mn0 = fmaxf(m0, mr0), mn1 = fmaxf(m1, mr1);
        float al0 = __expf(m0 - mn0), al1 = __expf(m1 - mn1);
        m0 = mn0; m1 = mn1;

        uint32_t pp[8][2];
        float ps0 = 0.f, ps1 = 0.f;
        #pragma unroll
        for (int j = 0; j < 8; j++) {
            float p0 = __expf(accs[j][0] - mn0);
            float p1 = __expf(accs[j][1] - mn0);
            float p2 = __expf(accs[j][2] - mn1);
            float p3 = __expf(accs[j][3] - mn1);
            ps0 += p0 + p1;
            ps1 += p2 + p3;
            pp[j][0] = pack_h2(p0, p1);
            pp[j][1] = pack_h2(p2, p3);
        }
        ps0 += __shfl_xor_sync(0xffffffffu, ps0, 1);
        ps0 += __shfl_xor_sync(0xffffffffu, ps0, 2);
        ps1 += __shfl_xor_sync(0xffffffffu, ps1, 1);
        ps1 += __shfl_xor_sync(0xffffffffu, ps1, 2);
        l0 = l0 * al0 + ps0;
        l1 = l1 * al1 + ps1;

        if (!__all_sync(0xffffffffu, (al0 == 1.f) && (al1 == 1.f))) {
            #pragma unroll
            for (int j = 0; j < 8; j++) {
                acc_o[j][0] *= al0; acc_o[j][1] *= al0;
                acc_o[j][2] *= al1; acc_o[j][3] *= al1;
            }
        }

        #pragma unroll
        for (int kk = 0; kk < 4; kk++) {
            uint32_t a0 = pp[2 * kk][0];
            uint32_t a1 = pp[2 * kk][1];
            uint32_t a2 = pp[2 * kk + 1][0];
            uint32_t a3 = pp[2 * kk + 1][1];
            uint32_t bf[8][2];
            #pragma unroll
            for (int p = 0; p < 4; p++)
                ldsm_x4(bf[2 * p][0], bf[2 * p][1], bf[2 * p + 1][0], bf[2 * p + 1][1],
                        vt_u + (uint32_t)(kv_off[p] + kk * 16) * 2);
            #pragma unroll
            for (int j = 0; j < 8; j++)
                mma_f16(acc_o[j][0], acc_o[j][1], acc_o[j][2], acc_o[j][3],
                        a0, a1, a2, a3, bf[j][0], bf[j][1]);
        }
    }

    float i0 = 1.f / l0, i1 = 1.f / l1;
    int r0 = brow + wm + lg;
    int tok0 = b * S_ + r0;
    #pragma unroll
    for (int j = 0; j < 8; j++) {
        int col = h * DH_ + j * 8 + 2 * lt;
        *(__half2*)&out[(size_t)tok0 * H_ + col] =
            __floats2half2_rn(acc_o[j][0] * i0, acc_o[j][1] * i0);
        *(__half2*)&out[(size_t)(tok0 + 8) * H_ + col] =
            __floats2half2_rn(acc_o[j][2] * i1, acc_o[j][3] * i1);
    }
}

// ------- residual + LayerNorm, warp-per-row (8 rows/block, shfl reduce) ----
__global__ __launch_bounds__(256) void add_ln_kernel(
    const float* __restrict__ xin,
    const float* __restrict__ ya, const float* __restrict__ yb,
    const float* __restrict__ gamma, const float* __restrict__ beta,
    float* __restrict__ out, __half* __restrict__ out_r)
{
    int warp = threadIdx.x >> 5;
    int lane = threadIdx.x & 31;
    int t = blockIdx.x * 8 + warp;
    size_t base = (size_t)t * H_;

    float v[16];
    float s1 = 0.f, s2 = 0.f;
    #pragma unroll
    for (int i = 0; i < 16; i++) {
        int c = lane + i * 32;
        v[i] = ya[base + c] + yb[base + c];
        s1 += v[i];
        s2 += v[i] * v[i];
    }
    #pragma unroll
    for (int off = 16; off > 0; off >>= 1) {
        s1 += __shfl_xor_sync(0xffffffffu, s1, off);
        s2 += __shfl_xor_sync(0xffffffffu, s2, off);
    }
    float mean = s1 * (1.f / (float)H_);
    float var  = s2 * (1.f / (float)H_) - mean * mean;
    float r = rsqrtf(var + 1e-5f);
    #pragma unroll
    for (int i = 0; i < 16; i++) {
        int c = lane + i * 32;
        float o = xin[base + c] + (v[i] - mean) * r * gamma[c] + beta[c];
        out[base + c]   = o;
        out_r[base + c] = __float2half_rn(o);
    }
}

// ---------------- host launcher ----------------
extern "C" void kernel_launch(void* const* d_in, const int* in_sizes, int n_in,
                              void* d_out, int out_size)
{
    const int*   src  = (const int*)  d_in[0];
    const int*   mask = (const int*)  d_in[1];
    const float* emb  = (const float*)d_in[2];
    const float* Wq   = (const float*)d_in[3];
    const float* bq   = (const float*)d_in[4];
    const float* Wk   = (const float*)d_in[5];
    const float* bk   = (const float*)d_in[6];
    const float* Wv   = (const float*)d_in[7];
    const float* bv   = (const float*)d_in[8];
    const float* Wo   = (const float*)d_in[9];
    const float* bo   = (const float*)d_in[10];
    const float* gamma= (const float*)d_in[11];
    const float* beta = (const float*)d_in[12];
    const float* W1   = (const float*)d_in[13];
    const float* b1   = (const float*)d_in[14];
    const float* W2   = (const float*)d_in[15];
    const float* b2   = (const float*)d_in[16];

    float *x, *res, *t2a, *t2b, *mb;
    __half *xr, *q, *k, *vt, *t, *resr, *h1, *wh;
    cudaGetSymbolAddress((void**)&x,    g_x);
    cudaGetSymbolAddress((void**)&res,  g_res);
    cudaGetSymbolAddress((void**)&t2a,  g_t2a);
    cudaGetSymbolAddress((void**)&t2b,  g_t2b);
    cudaGetSymbolAddress((void**)&mb,   g_mb);
    cudaGetSymbolAddress((void**)&xr,   g_xr);
    cudaGetSymbolAddress((void**)&q,    g_q);
    cudaGetSymbolAddress((void**)&k,    g_k);
    cudaGetSymbolAddress((void**)&vt,   g_vt);
    cudaGetSymbolAddress((void**)&t,    g_t);
    cudaGetSymbolAddress((void**)&resr, g_resr);
    cudaGetSymbolAddress((void**)&h1,   g_h1);
    cudaGetSymbolAddress((void**)&wh,   g_wh);

    cudaFuncSetAttribute(flash_kernel,
                         cudaFuncAttributeMaxDynamicSharedMemorySize, FLASH_SMEM);
    cudaFuncSetAttribute(gemm_qkv,
                         cudaFuncAttributeMaxDynamicSharedMemorySize, GEMM_SMEM);
    cudaFuncSetAttribute(gemm_h,
                         cudaFuncAttributeMaxDynamicSharedMemorySize, GEMM_SMEM);
    cudaFuncSetAttribute(gemm_sk,
                         cudaFuncAttributeMaxDynamicSharedMemorySize, GEMM_SMEM);

    transpose_all_kernel<<<L_ * 3072, 256>>>(Wq, Wk, Wv, Wo, W1, W2, wh);
    embed_kernel<<<(M_ * H_) / 256, 256>>>(src, emb, mask, x, xr, mb);

    dim3 gQKV (H_ / 128,  M_ / 128, 3);
    dim3 gSK  (H_ / 128,  M_ / 128, 2);
    dim3 gFfn1(FF_ / 128, M_ / 128, 1);
    dim3 gFlash(S_ / 128, B_ * NH_);

    for (int i = 0; i < L_; i++) {
        const __half* WqT = wh + WOFF_Q + (size_t)i * H_ * H_;
        const __half* WkT = wh + WOFF_K + (size_t)i * H_ * H_;
        const __half* WvT = wh + WOFF_V + (size_t)i * H_ * H_;
        const __half* WoT = wh + WOFF_O + (size_t)i * H_ * H_;
        const __half* W1T = wh + WOFF_1 + (size_t)i * H_ * FF_;
        const __half* W2T = wh + WOFF_2 + (size_t)i * FF_ * H_;
        const float* bq_i = bq + i * H_;
        const float* bk_i = bk + i * H_;
        const float* bv_i = bv + i * H_;
        const float* bo_i = bo + i * H_;
        const float* b1_i = b1 + i * FF_;
        const float* b2_i = b2 + i * H_;
        const float* g_i  = gamma + i * H_;
        const float* be_i = beta  + i * H_;
        float* xout = (i == L_ - 1) ? (float*)d_out : x;

        gemm_qkv<<<gQKV, 256, GEMM_SMEM>>>(
            xr, WqT, WkT, WvT, bq_i, bk_i, bv_i, q, k, vt, H_, H_);

        flash_kernel<<<gFlash, 256, FLASH_SMEM>>>(q, k, vt, mb, t);

        gemm_sk<<<gSK, 256, GEMM_SMEM>>>(t, WoT, bo_i, t2a, t2b, H_, H_);
        add_ln_kernel<<<M_ / 8, 256>>>(x, t2a, t2b, g_i, be_i, res, resr);

        gemm_h<<<gFfn1, 256, GEMM_SMEM>>>(resr, W1T, b1_i, h1, FF_, H_);

        gemm_sk<<<gSK, 256, GEMM_SMEM>>>(h1, W2T, b2_i, t2a, t2b, H_, FF_);
        add_ln_kernel<<<M_ / 8, 256>>>(res, t2a, t2b, g_i, be_i, xout, resr);
        xr = resr;
    }
}

// round 15
// speedup vs baseline: 2.0133x; 1.0060x over previous
#include <cuda_runtime.h>
#include <cuda_fp16.h>
#include <math.h>
#include <stdint.h>

// Problem dims
#define B_  2
#define S_  2048
#define H_  512
#define NH_ 8
#define DH_ 64
#define L_  6
#define FF_ 2048
#define M_  (B_*S_)

#define LOG2E 1.4426950408889634f

// ---------------- device scratch ----------------
__device__ float  g_x  [M_*H_];
__device__ float  g_res[M_*H_];
__device__ float  g_t2a[M_*H_];
__device__ float  g_t2b[M_*H_];
__device__ float  g_mb [M_];
__device__ __half g_xr [M_*H_];
__device__ __half g_q  [M_*H_];
__device__ __half g_k  [M_*H_];
__device__ __half g_vt [M_*H_];     // V transposed: [(b*512+d)][s]
__device__ __half g_t  [M_*H_];
__device__ __half g_resr[M_*H_];
__device__ __half g_h1 [M_*FF_];
__device__ __half g_wh [18874368];  // transposed half weights [N][K]

#define WOFF_Q  0
#define WOFF_K  (L_*H_*H_)
#define WOFF_V  (2*L_*H_*H_)
#define WOFF_O  (3*L_*H_*H_)
#define WOFF_1  (4*L_*H_*H_)
#define WOFF_2  (4*L_*H_*H_ + L_*H_*FF_)

// ---------------- helpers ----------------
__device__ __forceinline__ void mma_f16(
    float& c0, float& c1, float& c2, float& c3,
    uint32_t a0, uint32_t a1, uint32_t a2, uint32_t a3,
    uint32_t b0, uint32_t b1)
{
    asm volatile(
        "mma.sync.aligned.m16n8k16.row.col.f32.f16.f16.f32 "
        "{%0,%1,%2,%3}, {%4,%5,%6,%7}, {%8,%9}, {%0,%1,%2,%3};\n"
        : "+f"(c0), "+f"(c1), "+f"(c2), "+f"(c3)
        : "r"(a0), "r"(a1), "r"(a2), "r"(a3), "r"(b0), "r"(b1));
}
__device__ __forceinline__ void ldsm_x4(
    uint32_t& r0, uint32_t& r1, uint32_t& r2, uint32_t& r3, uint32_t addr)
{
    asm volatile(
        "ldmatrix.sync.aligned.m8n8.x4.shared.b16 {%0,%1,%2,%3}, [%4];"
        : "=r"(r0), "=r"(r1), "=r"(r2), "=r"(r3) : "r"(addr));
}
__device__ __forceinline__ uint32_t smem_u32(const void* p) {
    return (uint32_t)__cvta_generic_to_shared(p);
}
__device__ __forceinline__ uint32_t pack_h2(float lo, float hi) {
    __half2 h = __floats2half2_rn(lo, hi);
    return *(uint32_t*)&h;
}
__device__ __forceinline__ void cp_async16f(float* dst, const float* src) {
    unsigned s = (unsigned)__cvta_generic_to_shared(dst);
    asm volatile("cp.async.cg.shared.global [%0], [%1], 16;" :: "r"(s), "l"(src));
}
__device__ __forceinline__ void cp_async16h(__half* dst, const __half* src) {
    unsigned s = (unsigned)__cvta_generic_to_shared(dst);
    asm volatile("cp.async.cg.shared.global [%0], [%1], 16;" :: "r"(s), "l"(src));
}
__device__ __forceinline__ void cp_commit() {
    asm volatile("cp.async.commit_group;");
}

// ---------------- fused weight transpose (one launch) ----------------
__global__ __launch_bounds__(256) void transpose_all_kernel(
    const float* __restrict__ Wq, const float* __restrict__ Wk,
    const float* __restrict__ Wv, const float* __restrict__ Wo,
    const float* __restrict__ W1, const float* __restrict__ W2,
    __half* __restrict__ wh)
{
    __shared__ float tile[32][33];
    int idx = blockIdx.x;
    int layer = idx / 3072;
    int r = idx % 3072;

    const float* src;
    __half* dst;
    int K, N, nt, kt;
    if (r < 1024) {
        int m = r >> 8, t = r & 255;
        nt = t & 15; kt = t >> 4;
        K = H_; N = H_;
        src = (m == 0) ? Wq : (m == 1) ? Wk : (m == 2) ? Wv : Wo;
        dst = wh + (size_t)m * (L_ * H_ * H_);
        src += (size_t)layer * H_ * H_;
        dst += (size_t)layer * H_ * H_;
    } else if (r < 2048) {
        int t = r - 1024;
        nt = t & 63; kt = t >> 6;
        K = H_; N = FF_;
        src = W1 + (size_t)layer * H_ * FF_;
        dst = wh + WOFF_1 + (size_t)layer * H_ * FF_;
    } else {
        int t = r - 2048;
        nt = t & 15; kt = t >> 4;
        K = FF_; N = H_;
        src = W2 + (size_t)layer * FF_ * H_;
        dst = wh + WOFF_2 + (size_t)layer * FF_ * H_;
    }

    int n0 = nt * 32, k0 = kt * 32;
    int tx = threadIdx.x & 31, ty = threadIdx.x >> 5;
    #pragma unroll
    for (int i = 0; i < 4; i++)
        tile[ty + i * 8][tx] = src[(size_t)(k0 + ty + i * 8) * N + n0 + tx];
    __syncthreads();
    #pragma unroll
    for (int i = 0; i < 4; i++)
        dst[(size_t)(n0 + ty + i * 8) * K + k0 + tx] =
            __float2half_rn(tile[tx][ty + i * 8]);
}

// ---------------- embedding + posenc + mask bias (log2 domain) ----------
__global__ __launch_bounds__(256) void embed_kernel(
    const int* __restrict__ src, const float* __restrict__ emb,
    const int* __restrict__ mask,
    float* __restrict__ x, __half* __restrict__ xr, float* __restrict__ mb)
{
    int idx = blockIdx.x * 256 + threadIdx.x;
    int d   = idx & (H_ - 1);
    int tok = idx >> 9;
    int s   = tok & (S_ - 1);
    int j2  = (d >> 1) * 2;
    float div = powf(10000.0f, (float)j2 * (1.0f / (float)H_));
    float arg = (float)s / div;
    float pe  = (d & 1) ? cosf(arg) : sinf(arg);
    float v = emb[(size_t)src[tok] * H_ + d] + pe;
    x[idx]  = v;
    xr[idx] = __float2half_rn(v);
    if (idx < M_) mb[idx] = mask[idx] ? 0.f : (-1e20f * LOG2E);
}

// =========================================================================
// fp16 GEMM core, BK=64, single-barrier 3-stage pipeline, LDSM fragments.
// =========================================================================
#define GST 72
#define STAGE_H (128 * GST)
#define GEMM_SMEM (3 * 2 * STAGE_H * 2)

template<bool RELU, int OUT>
__device__ __forceinline__ void gemm_core(
    const __half* __restrict__ A, const __half* __restrict__ Wt,
    const float* __restrict__ bias, float biasScale, float outScale,
    void* Cv, int brow, int bcol, int N, int Kfull, int koff, int Kspan)
{
    extern __shared__ char smraw[];
    __half* sbase = (__half*)smraw;
    uint32_t sm_u = smem_u32(sbase);

    int tid  = threadIdx.x;
    int lane = tid & 31;
    int warp = tid >> 5;
    int warp_m = (warp >> 1) * 32;
    int warp_n = (warp & 1) * 64;
    int lg = lane >> 2, lt = lane & 3;
    int g  = lane >> 3, lr = lane & 7;

    int a_off[2], b_off[4];
    #pragma unroll
    for (int i = 0; i < 2; i++)
        a_off[i] = (warp_m + i * 16 + (g & 1) * 8 + lr) * GST + (g >> 1) * 8;
    #pragma unroll
    for (int p = 0; p < 4; p++)
        b_off[p] = (warp_n + p * 16 + (g >> 1) * 8 + lr) * GST + (g & 1) * 8;

    auto load_tile = [&](int st, int k0) {
        __half* as = sbase + st * 2 * STAGE_H;
        __half* bs = as + STAGE_H;
        #pragma unroll
        for (int i = 0; i < 4; i++) {
            int ci = tid + i * 256;
            int r = ci >> 3, c8 = ci & 7;
            cp_async16h(as + r * GST + c8 * 8,
                        A  + (size_t)(brow + r) * Kfull + koff + k0 + c8 * 8);
            cp_async16h(bs + r * GST + c8 * 8,
                        Wt + (size_t)(bcol + r) * Kfull + koff + k0 + c8 * 8);
        }
        cp_commit();
    };

    int nk = Kspan / 64;
    load_tile(0, 0);
    load_tile(1, 64);

    float acc[2][8][4];
    #pragma unroll
    for (int i = 0; i < 2; i++)
        #pragma unroll
        for (int j = 0; j < 8; j++)
            #pragma unroll
            for (int r = 0; r < 4; r++) acc[i][j][r] = 0.f;

    for (int t = 0; t < nk; t++) {
        if (t < nk - 1) asm volatile("cp.async.wait_group 1;");
        else            asm volatile("cp.async.wait_group 0;");
        __syncthreads();
        if (t + 2 < nk) load_tile((t + 2) % 3, (t + 2) * 64);

        uint32_t as_u = sm_u + (t % 3) * 2 * STAGE_H * 2;
        uint32_t bs_u = as_u + STAGE_H * 2;

        #pragma unroll
        for (int ks = 0; ks < 64; ks += 16) {
            uint32_t af[2][4];
            #pragma unroll
            for (int i = 0; i < 2; i++)
                ldsm_x4(af[i][0], af[i][1], af[i][2], af[i][3],
                        as_u + (uint32_t)(a_off[i] + ks) * 2);
            uint32_t bf[8][2];
            #pragma unroll
            for (int p = 0; p < 4; p++)
                ldsm_x4(bf[2 * p][0], bf[2 * p][1], bf[2 * p + 1][0], bf[2 * p + 1][1],
                        bs_u + (uint32_t)(b_off[p] + ks) * 2);
            #pragma unroll
            for (int i = 0; i < 2; i++)
                #pragma unroll
                for (int j = 0; j < 8; j++)
                    mma_f16(acc[i][j][0], acc[i][j][1], acc[i][j][2], acc[i][j][3],
                            af[i][0], af[i][1], af[i][2], af[i][3],
                            bf[j][0], bf[j][1]);
        }
    }

    #pragma unroll
    for (int i = 0; i < 2; i++) {
        #pragma unroll
        for (int j = 0; j < 8; j++) {
            int col = bcol + warp_n + j * 8 + 2 * lt;
            float bx = bias[col] * biasScale, by = bias[col + 1] * biasScale;
            int r0 = brow + warp_m + i * 16 + lg;
            float v0x = (acc[i][j][0] + bx) * outScale;
            float v0y = (acc[i][j][1] + by) * outScale;
            float v1x = (acc[i][j][2] + bx) * outScale;
            float v1y = (acc[i][j][3] + by) * outScale;
            if (RELU) {
                v0x = fmaxf(v0x, 0.f); v0y = fmaxf(v0y, 0.f);
                v1x = fmaxf(v1x, 0.f); v1y = fmaxf(v1y, 0.f);
            }
            if (OUT == 0) {
                float* C = (float*)Cv;
                *(float2*)&C[(size_t)r0 * N + col]       = make_float2(v0x, v0y);
                *(float2*)&C[(size_t)(r0 + 8) * N + col] = make_float2(v1x, v1y);
            } else if (OUT == 1) {
                __half* C = (__half*)Cv;
                *(__half2*)&C[(size_t)r0 * N + col]       = __floats2half2_rn(v0x, v0y);
                *(__half2*)&C[(size_t)(r0 + 8) * N + col] = __floats2half2_rn(v1x, v1y);
            } else {
                __half* C = (__half*)Cv;
                int bb = r0 >> 11, s = r0 & 2047;
                size_t base0 = (size_t)(bb * 512 + col) * 2048;
                size_t base1 = (size_t)(bb * 512 + col + 1) * 2048;
                C[base0 + s]     = __float2half_rn(v0x);
                C[base1 + s]     = __float2half_rn(v0y);
                C[base0 + s + 8] = __float2half_rn(v1x);
                C[base1 + s + 8] = __float2half_rn(v1y);
            }
        }
    }
}

__global__ __launch_bounds__(256, 2) void gemm_qkv(
    const __half* __restrict__ A,
    const __half* __restrict__ Wq, const __half* __restrict__ Wk, const __half* __restrict__ Wv,
    const float* __restrict__ bq, const float* __restrict__ bk, const float* __restrict__ bv,
    __half* q, __half* k, __half* vt, int N, int K)
{
    int z = blockIdx.z;
    if (z == 0)
        gemm_core<false, 1>(A, Wq, bq, 1.f, 0.125f * LOG2E, q,
                            blockIdx.y * 128, blockIdx.x * 128, N, K, 0, K);
    else if (z == 1)
        gemm_core<false, 1>(A, Wk, bk, 1.f, 1.f, k,
                            blockIdx.y * 128, blockIdx.x * 128, N, K, 0, K);
    else
        gemm_core<false, 2>(A, Wv, bv, 1.f, 1.f, vt,
                            blockIdx.y * 128, blockIdx.x * 128, N, K, 0, K);
}

__global__ __launch_bounds__(256, 2) void gemm_h(
    const __half* __restrict__ A, const __half* __restrict__ Wt,
    const float* __restrict__ bias, __half* C, int N, int K)
{
    gemm_core<true, 1>(A, Wt, bias, 1.f, 1.f, C,
                       blockIdx.y * 128, blockIdx.x * 128, N, K, 0, K);
}

__global__ __launch_bounds__(256, 2) void gemm_sk(
    const __half* __restrict__ A, const __half* __restrict__ Wt,
    const float* __restrict__ bias, float* C0, float* C1, int N, int K)
{
    int z = blockIdx.z;
    int Kh = K >> 1;
    gemm_core<false, 0>(A, Wt, bias, z == 0 ? 1.f : 0.f, 1.f,
                        z == 0 ? (void*)C0 : (void*)C1,
                        blockIdx.y * 128, blockIdx.x * 128, N, K, z * Kh, Kh);
}

// =========================================================================
// fp16 flash attention, log2-domain softmax (scores pre-scaled by log2e).
// =========================================================================
#define FQS 72
#define NKV (S_ / 64)
#define FLASH_SMEM (128*FQS*2 + 3*64*FQS*2 + 3*64*FQS*2 + 3*64*4)

__global__ __launch_bounds__(256, 2) void flash_kernel(
    const __half* __restrict__ q, const __half* __restrict__ k,
    const __half* __restrict__ vt, const float* __restrict__ mbias,
    __half* __restrict__ out)
{
    extern __shared__ char smraw[];
    __half* Qh  = (__half*)smraw;
    __half* Ksm = Qh + 128 * FQS;
    __half* Vsm = Ksm + 3 * 64 * FQS;
    float*  MB  = (float*)(Vsm + 3 * 64 * FQS);

    int tid  = threadIdx.x;
    int lane = tid & 31;
    int warp = tid >> 5;
    int wm   = warp * 16;
    int lg = lane >> 2, lt = lane & 3;
    int g  = lane >> 3, lr = lane & 7;
    int brow = blockIdx.x * 128;
    int bh = blockIdx.y;
    int b = bh >> 3, h = bh & 7;

    const __half* Qb  = q  + (size_t)b * S_ * H_ + h * DH_;
    const __half* Kb  = k  + (size_t)b * S_ * H_ + h * DH_;
    const __half* Vtb = vt + (size_t)(b * 512 + h * 64) * 2048;
    const float*  MBg = mbias + b * S_;

    int q_off = (wm + (g & 1) * 8 + lr) * FQS + (g >> 1) * 8;
    int kv_off[4];
    #pragma unroll
    for (int p = 0; p < 4; p++)
        kv_off[p] = (p * 16 + (g >> 1) * 8 + lr) * FQS + (g & 1) * 8;

    auto load_kv = [&](int buf, int it) {
        int kv0 = it * 64;
        __half* kd = Ksm + buf * 64 * FQS;
        __half* vd = Vsm + buf * 64 * FQS;
        #pragma unroll
        for (int i = 0; i < 2; i++) {
            int ci = tid + i * 256;
            int r = ci >> 3, c8 = ci & 7;
            cp_async16h(kd + r * FQS + c8 * 8,
                        Kb + (size_t)(kv0 + r) * H_ + c8 * 8);
            cp_async16h(vd + r * FQS + c8 * 8,
                        Vtb + (size_t)r * S_ + kv0 + c8 * 8);
        }
        if (tid < 16) cp_async16f(&MB[buf * 64 + tid * 4], MBg + kv0 + tid * 4);
        cp_commit();
    };

    #pragma unroll
    for (int i = 0; i < 4; i++) {
        int ci = tid + i * 256;
        int r = ci >> 3, c8 = ci & 7;
        cp_async16h(Qh + r * FQS + c8 * 8,
                    Qb + (size_t)(brow + r) * H_ + c8 * 8);
    }
    cp_commit();
    load_kv(0, 0);
    load_kv(1, 1);
    asm volatile("cp.async.wait_group 2;");
    __syncthreads();

    uint32_t qh_u = smem_u32(Qh);
    uint32_t aq[4][4];
    #pragma unroll
    for (int ks = 0; ks < 4; ks++)
        ldsm_x4(aq[ks][0], aq[ks][1], aq[ks][2], aq[ks][3],
                qh_u + (uint32_t)(q_off + ks * 16) * 2);

    float acc_o[8][4];
    #pragma unroll
    for (int j = 0; j < 8; j++)
        #pragma unroll
        for (int rr = 0; rr < 4; rr++) acc_o[j][rr] = 0.f;
    float m0 = -1e30f, m1 = -1e30f, l0 = 0.f, l1 = 0.f;

    for (int it = 0; it < NKV; it++) {
        int buf = it % 3;
        if (it < NKV - 1) asm volatile("cp.async.wait_group 1;");
        else              asm volatile("cp.async.wait_group 0;");
        __syncthreads();
        if (it + 2 < NKV) load_kv((it + 2) % 3, it + 2);

        uint32_t kt_u = smem_u32(Ksm + buf * 64 * FQS);
        uint32_t vt_u = smem_u32(Vsm + buf * 64 * FQS);
        const float* MBt = MB + buf * 64;

        // ---- S' = (Q*log2e/8) @ K^T  (log2-domain scores) ----
        float accs[8][4];
        #pragma unroll
        for (int j = 0; j < 8; j++)
            #pragma unroll
            for (int rr = 0; rr < 4; rr++) accs[j][rr] = 0.f;
        #pragma unroll
        for (int ks = 0; ks < 4; ks++) {
            uint32_t bf[8][2];
            #pragma unroll
            for (int p = 0; p < 4; p++)
                ldsm_x4(bf[2 * p][0], bf[2 * p][1], bf[2 * p + 1][0], bf[2 * p + 1][1],
                        kt_u + (uint32_t)(kv_off[p] + ks * 16) * 2);
            #pragma unroll
            for (int j = 0; j < 8; j++)
                mma_f16(accs[j][0], accs[j][1], accs[j][2], accs[j][3],
                        aq[ks][0], aq[ks][1], aq[ks][2], aq[ks][3],
                        bf[j][0], bf[j][1]);
        }

        // ---- + mask bias (skipped exactly when all-zero), row max ----
        float2 mbv = *(const float2*)&MBt[0 * 8 + 2 * lt];   // representative pair
        // check all 64 cols this warp sees: each thread holds 8 pairs
        bool zerob = true;
        #pragma unroll
        for (int j = 0; j < 8; j++) {
            float2 mv = *(const float2*)&MBt[j * 8 + 2 * lt];
            zerob = zerob && (mv.x == 0.f) && (mv.y == 0.f);
        }
        if (!__all_sync(0xffffffffu, zerob)) {
            #pragma unroll
            for (int j = 0; j < 8; j++) {
                float2 mv = *(const float2*)&MBt[j * 8 + 2 * lt];
                accs[j][0] += mv.x;
                accs[j][1] += mv.y;
                accs[j][2] += mv.x;
                accs[j][3] += mv.y;
            }
        }
        (void)mbv;

        float mr0 = -1e30f, mr1 = -1e30f;
        #pragma unroll
        for (int j = 0; j < 8; j++) {
            mr0 = fmaxf(mr0, fmaxf(accs[j][0], accs[j][1]));
            mr1 = fmaxf(mr1, fmaxf(accs[j][2], accs[j][3]));
        }
        mr0 = fmaxf(mr0, __shfl_xor_sync(0xffffffffu, mr0, 1));
        mr0 = fmaxf(mr0, __shfl_xor_sync(0xffffffffu, mr0, 2));
        mr1 = fmaxf(mr1, __shfl_xor_sync(0xffffffffu, mr1, 1));
        mr1 = fmaxf(mr1, __shfl_xor_sync(0xffffffffu, mr1, 2));

        float mn0 = fmaxf(m0, mr0), mn1 = fmaxf(m1, mr1);
        float al0 = exp2f(m0 - mn0), al1 = exp2f(m1 - mn1);
        m0 = mn0; m1 = mn1;

        // ---- P = exp2(S' - m'), pack ----
        uint32_t pp[8][2];
        float ps0 = 0.f, ps1 = 0.f;
        #pragma unroll
        for (int j = 0; j < 8; j++) {
            float p0 = exp2f(accs[j][0] - mn0);
            float p1 = exp2f(accs[j][1] - mn0);
            float p2 = exp2f(accs[j][2] - mn1);
            float p3 = exp2f(accs[j][3] - mn1);
            ps0 += p0 + p1;
            ps1 += p2 + p3;
            pp[j][0] = pack_h2(p0, p1);
            pp[j][1] = pack_h2(p2, p3);
        }
        ps0 += __shfl_xor_sync(0xffffffffu, ps0, 1);
        ps0 += __shfl_xor_sync(0xffffffffu, ps0, 2);
        ps1 += __shfl_xor_sync(0xffffffffu, ps1, 1);
        ps1 += __shfl_xor_sync(0xffffffffu, ps1, 2);
        l0 = l0 * al0 + ps0;
        l1 = l1 * al1 + ps1;

        if (!__all_sync(0xffffffffu, (al0 == 1.f) && (al1 == 1.f))) {
            #pragma unroll
            for (int j = 0; j < 8; j++) {
                acc_o[j][0] *= al0; acc_o[j][1] *= al0;
                acc_o[j][2] *= al1; acc_o[j][3] *= al1;
            }
        }

        // ---- O += P @ V ----
        #pragma unroll
        for (int kk = 0; kk < 4; kk++) {
            uint32_t a0 = pp[2 * kk][0];
            uint32_t a1 = pp[2 * kk][1];
            uint32_t a2 = pp[2 * kk + 1][0];
            uint32_t a3 = pp[2 * kk + 1][1];
            uint32_t bf[8][2];
            #pragma unroll
            for (int p = 0; p < 4; p++)
                ldsm_x4(bf[2 * p][0], bf[2 * p][1], bf[2 * p + 1][0], bf[2 * p + 1][1],
                        vt_u + (uint32_t)(kv_off[p] + kk * 16) * 2);
            #pragma unroll
            for (int j = 0; j < 8; j++)
                mma_f16(acc_o[j][0], acc_o[j][1], acc_o[j][2], acc_o[j][3],
                        a0, a1, a2, a3, bf[j][0], bf[j][1]);
        }
    }

    float i0 = 1.f / l0, i1 = 1.f / l1;
    int r0 = brow + wm + lg;
    int tok0 = b * S_ + r0;
    #pragma unroll
    for (int j = 0; j < 8; j++) {
        int col = h * DH_ + j * 8 + 2 * lt;
        *(__half2*)&out[(size_t)tok0 * H_ + col] =
            __floats2half2_rn(acc_o[j][0] * i0, acc_o[j][1] * i0);
        *(__half2*)&out[(size_t)(tok0 + 8) * H_ + col] =
            __floats2half2_rn(acc_o[j][2] * i1, acc_o[j][3] * i1);
    }
}

// ------- residual + LayerNorm, warp-per-row ----
__global__ __launch_bounds__(256) void add_ln_kernel(
    const float* __restrict__ xin,
    const float* __restrict__ ya, const float* __restrict__ yb,
    const float* __restrict__ gamma, const float* __restrict__ beta,
    float* __restrict__ out, __half* __restrict__ out_r)
{
    int warp = threadIdx.x >> 5;
    int lane = threadIdx.x & 31;
    int t = blockIdx.x * 8 + warp;
    size_t base = (size_t)t * H_;

    float v[16];
    float s1 = 0.f, s2 = 0.f;
    #pragma unroll
    for (int i = 0; i < 16; i++) {
        int c = lane + i * 32;
        v[i] = ya[base + c] + yb[base + c];
        s1 += v[i];
        s2 += v[i] * v[i];
    }
    #pragma unroll
    for (int off = 16; off > 0; off >>= 1) {
        s1 += __shfl_xor_sync(0xffffffffu, s1, off);
        s2 += __shfl_xor_sync(0xffffffffu, s2, off);
    }
    float mean = s1 * (1.f / (float)H_);
    float var  = s2 * (1.f / (float)H_) - mean * mean;
    float r = rsqrtf(var + 1e-5f);
    #pragma unroll
    for (int i = 0; i < 16; i++) {
        int c = lane + i * 32;
        float o = xin[base + c] + (v[i] - mean) * r * gamma[c] + beta[c];
        out[base + c]   = o;
        out_r[base + c] = __float2half_rn(o);
    }
}

// ---------------- host launcher ----------------
extern "C" void kernel_launch(void* const* d_in, const int* in_sizes, int n_in,
                              void* d_out, int out_size)
{
    const int*   src  = (const int*)  d_in[0];
    const int*   mask = (const int*)  d_in[1];
    const float* emb  = (const float*)d_in[2];
    const float* Wq   = (const float*)d_in[3];
    const float* bq   = (const float*)d_in[4];
    const float* Wk   = (const float*)d_in[5];
    const float* bk   = (const float*)d_in[6];
    const float* Wv   = (const float*)d_in[7];
    const float* bv   = (const float*)d_in[8];
    const float* Wo   = (const float*)d_in[9];
    const float* bo   = (const float*)d_in[10];
    const float* gamma= (const float*)d_in[11];
    const float* beta = (const float*)d_in[12];
    const float* W1   = (const float*)d_in[13];
    const float* b1   = (const float*)d_in[14];
    const float* W2   = (const float*)d_in[15];
    const float* b2   = (const float*)d_in[16];

    float *x, *res, *t2a, *t2b, *mb;
    __half *xr, *q, *k, *vt, *t, *resr, *h1, *wh;
    cudaGetSymbolAddress((void**)&x,    g_x);
    cudaGetSymbolAddress((void**)&res,  g_res);
    cudaGetSymbolAddress((void**)&t2a,  g_t2a);
    cudaGetSymbolAddress((void**)&t2b,  g_t2b);
    cudaGetSymbolAddress((void**)&mb,   g_mb);
    cudaGetSymbolAddress((void**)&xr,   g_xr);
    cudaGetSymbolAddress((void**)&q,    g_q);
    cudaGetSymbolAddress((void**)&k,    g_k);
    cudaGetSymbolAddress((void**)&vt,   g_vt);
    cudaGetSymbolAddress((void**)&t,    g_t);
    cudaGetSymbolAddress((void**)&resr, g_resr);
    cudaGetSymbolAddress((void**)&h1,   g_h1);
    cudaGetSymbolAddress((void**)&wh,   g_wh);

    cudaFuncSetAttribute(flash_kernel,
                         cudaFuncAttributeMaxDynamicSharedMemorySize, FLASH_SMEM);
    cudaFuncSetAttribute(gemm_qkv,
                         cudaFuncAttributeMaxDynamicSharedMemorySize, GEMM_SMEM);
    cudaFuncSetAttribute(gemm_h,
                         cudaFuncAttributeMaxDynamicSharedMemorySize, GEMM_SMEM);
    cudaFuncSetAttribute(gemm_sk,
                         cudaFuncAttributeMaxDynamicSharedMemorySize, GEMM_SMEM);

    transpose_all_kernel<<<L_ * 3072, 256>>>(Wq, Wk, Wv, Wo, W1, W2, wh);
    embed_kernel<<<(M_ * H_) / 256, 256>>>(src, emb, mask, x, xr, mb);

    dim3 gQKV (H_ / 128,  M_ / 128, 3);
    dim3 gSK  (H_ / 128,  M_ / 128, 2);
    dim3 gFfn1(FF_ / 128, M_ / 128, 1);
    dim3 gFlash(S_ / 128, B_ * NH_);

    for (int i = 0; i < L_; i++) {
        const __half* WqT = wh + WOFF_Q + (size_t)i * H_ * H_;
        const __half* WkT = wh + WOFF_K + (size_t)i * H_ * H_;
        const __half* WvT = wh + WOFF_V + (size_t)i * H_ * H_;
        const __half* WoT = wh + WOFF_O + (size_t)i * H_ * H_;
        const __half* W1T = wh + WOFF_1 + (size_t)i * H_ * FF_;
        const __half* W2T = wh + WOFF_2 + (size_t)i * FF_ * H_;
        const float* bq_i = bq + i * H_;
        const float* bk_i = bk + i * H_;
        const float* bv_i = bv + i * H_;
        const float* bo_i = bo + i * H_;
        const float* b1_i = b1 + i * FF_;
        const float* b2_i = b2 + i * H_;
        const float* g_i  = gamma + i * H_;
        const float* be_i = beta  + i * H_;
        float* xout = (i == L_ - 1) ? (float*)d_out : x;

        gemm_qkv<<<gQKV, 256, GEMM_SMEM>>>(
            xr, WqT, WkT, WvT, bq_i, bk_i, bv_i, q, k, vt, H_, H_);

        flash_kernel<<<gFlash, 256, FLASH_SMEM>>>(q, k, vt, mb, t);

        gemm_sk<<<gSK, 256, GEMM_SMEM>>>(t, WoT, bo_i, t2a, t2b, H_, H_);
        add_ln_kernel<<<M_ / 8, 256>>>(x, t2a, t2b, g_i, be_i, res, resr);

        gemm_h<<<gFfn1, 256, GEMM_SMEM>>>(resr, W1T, b1_i, h1, FF_, H_);

        gemm_sk<<<gSK, 256, GEMM_SMEM>>>(h1, W2T, b2_i, t2a, t2b, H_, FF_);
        add_ln_kernel<<<M_ / 8, 256>>>(res, t2a, t2b, g_i, be_i, xout, resr);
        xr = resr;
    }
}

// round 16
// speedup vs baseline: 2.0370x; 1.0118x over previous
#include <cuda_runtime.h>
#include <cuda_fp16.h>
#include <math.h>
#include <stdint.h>

// Problem dims
#define B_  2
#define S_  2048
#define H_  512
#define NH_ 8
#define DH_ 64
#define L_  6
#define FF_ 2048
#define M_  (B_*S_)

#define LOG2E 1.4426950408889634f
#define ONES_H2 0x3C003C00u   // (1.0h, 1.0h)

// ---------------- device scratch ----------------
__device__ float  g_x  [M_*H_];
__device__ float  g_res[M_*H_];
__device__ float  g_t2a[M_*H_];
__device__ float  g_t2b[M_*H_];
__device__ float  g_mb [M_];
__device__ __half g_xr [M_*H_];
__device__ __half g_q  [M_*H_];
__device__ __half g_k  [M_*H_];
__device__ __half g_vt [M_*H_];     // V transposed: [(b*512+d)][s]
__device__ __half g_t  [M_*H_];
__device__ __half g_resr[M_*H_];
__device__ __half g_h1 [M_*FF_];
__device__ __half g_wh [18874368];  // transposed half weights [N][K]

#define WOFF_Q  0
#define WOFF_K  (L_*H_*H_)
#define WOFF_V  (2*L_*H_*H_)
#define WOFF_O  (3*L_*H_*H_)
#define WOFF_1  (4*L_*H_*H_)
#define WOFF_2  (4*L_*H_*H_ + L_*H_*FF_)

// ---------------- helpers ----------------
__device__ __forceinline__ void mma_f16(
    float& c0, float& c1, float& c2, float& c3,
    uint32_t a0, uint32_t a1, uint32_t a2, uint32_t a3,
    uint32_t b0, uint32_t b1)
{
    asm volatile(
        "mma.sync.aligned.m16n8k16.row.col.f32.f16.f16.f32 "
        "{%0,%1,%2,%3}, {%4,%5,%6,%7}, {%8,%9}, {%0,%1,%2,%3};\n"
        : "+f"(c0), "+f"(c1), "+f"(c2), "+f"(c3)
        : "r"(a0), "r"(a1), "r"(a2), "r"(a3), "r"(b0), "r"(b1));
}
__device__ __forceinline__ void ldsm_x4(
    uint32_t& r0, uint32_t& r1, uint32_t& r2, uint32_t& r3, uint32_t addr)
{
    asm volatile(
        "ldmatrix.sync.aligned.m8n8.x4.shared.b16 {%0,%1,%2,%3}, [%4];"
        : "=r"(r0), "=r"(r1), "=r"(r2), "=r"(r3) : "r"(addr));
}
__device__ __forceinline__ uint32_t smem_u32(const void* p) {
    return (uint32_t)__cvta_generic_to_shared(p);
}
__device__ __forceinline__ uint32_t pack_h2(float lo, float hi) {
    __half2 h = __floats2half2_rn(lo, hi);
    return *(uint32_t*)&h;
}
__device__ __forceinline__ void cp_async16f(float* dst, const float* src) {
    unsigned s = (unsigned)__cvta_generic_to_shared(dst);
    asm volatile("cp.async.cg.shared.global [%0], [%1], 16;" :: "r"(s), "l"(src));
}
__device__ __forceinline__ void cp_async16h(__half* dst, const __half* src) {
    unsigned s = (unsigned)__cvta_generic_to_shared(dst);
    asm volatile("cp.async.cg.shared.global [%0], [%1], 16;" :: "r"(s), "l"(src));
}
__device__ __forceinline__ void cp_commit() {
    asm volatile("cp.async.commit_group;");
}

// ---------------- fused weight transpose (one launch) ----------------
__global__ __launch_bounds__(256) void transpose_all_kernel(
    const float* __restrict__ Wq, const float* __restrict__ Wk,
    const float* __restrict__ Wv, const float* __restrict__ Wo,
    const float* __restrict__ W1, const float* __restrict__ W2,
    __half* __restrict__ wh)
{
    __shared__ float tile[32][33];
    int idx = blockIdx.x;
    int layer = idx / 3072;
    int r = idx % 3072;

    const float* src;
    __half* dst;
    int K, N, nt, kt;
    if (r < 1024) {
        int m = r >> 8, t = r & 255;
        nt = t & 15; kt = t >> 4;
        K = H_; N = H_;
        src = (m == 0) ? Wq : (m == 1) ? Wk : (m == 2) ? Wv : Wo;
        dst = wh + (size_t)m * (L_ * H_ * H_);
        src += (size_t)layer * H_ * H_;
        dst += (size_t)layer * H_ * H_;
    } else if (r < 2048) {
        int t = r - 1024;
        nt = t & 63; kt = t >> 6;
        K = H_; N = FF_;
        src = W1 + (size_t)layer * H_ * FF_;
        dst = wh + WOFF_1 + (size_t)layer * H_ * FF_;
    } else {
        int t = r - 2048;
        nt = t & 15; kt = t >> 4;
        K = FF_; N = H_;
        src = W2 + (size_t)layer * FF_ * H_;
        dst = wh + WOFF_2 + (size_t)layer * FF_ * H_;
    }

    int n0 = nt * 32, k0 = kt * 32;
    int tx = threadIdx.x & 31, ty = threadIdx.x >> 5;
    #pragma unroll
    for (int i = 0; i < 4; i++)
        tile[ty + i * 8][tx] = src[(size_t)(k0 + ty + i * 8) * N + n0 + tx];
    __syncthreads();
    #pragma unroll
    for (int i = 0; i < 4; i++)
        dst[(size_t)(n0 + ty + i * 8) * K + k0 + tx] =
            __float2half_rn(tile[tx][ty + i * 8]);
}

// ---------------- embedding + posenc + mask bias (log2 domain) ----------
__global__ __launch_bounds__(256) void embed_kernel(
    const int* __restrict__ src, const float* __restrict__ emb,
    const int* __restrict__ mask,
    float* __restrict__ x, __half* __restrict__ xr, float* __restrict__ mb)
{
    int idx = blockIdx.x * 256 + threadIdx.x;
    int d   = idx & (H_ - 1);
    int tok = idx >> 9;
    int s   = tok & (S_ - 1);
    int j2  = (d >> 1) * 2;
    float div = powf(10000.0f, (float)j2 * (1.0f / (float)H_));
    float arg = (float)s / div;
    float pe  = (d & 1) ? cosf(arg) : sinf(arg);
    float v = emb[(size_t)src[tok] * H_ + d] + pe;
    x[idx]  = v;
    xr[idx] = __float2half_rn(v);
    if (idx < M_) mb[idx] = mask[idx] ? 0.f : (-1e20f * LOG2E);
}

// =========================================================================
// fp16 GEMM core, BK=64, single-barrier 3-stage pipeline, LDSM fragments.
// =========================================================================
#define GST 72
#define STAGE_H (128 * GST)
#define GEMM_SMEM (3 * 2 * STAGE_H * 2)

template<bool RELU, int OUT>
__device__ __forceinline__ void gemm_core(
    const __half* __restrict__ A, const __half* __restrict__ Wt,
    const float* __restrict__ bias, float biasScale, float outScale,
    void* Cv, int brow, int bcol, int N, int Kfull, int koff, int Kspan)
{
    extern __shared__ char smraw[];
    __half* sbase = (__half*)smraw;
    uint32_t sm_u = smem_u32(sbase);

    int tid  = threadIdx.x;
    int lane = tid & 31;
    int warp = tid >> 5;
    int warp_m = (warp >> 1) * 32;
    int warp_n = (warp & 1) * 64;
    int lg = lane >> 2, lt = lane & 3;
    int g  = lane >> 3, lr = lane & 7;

    int a_off[2], b_off[4];
    #pragma unroll
    for (int i = 0; i < 2; i++)
        a_off[i] = (warp_m + i * 16 + (g & 1) * 8 + lr) * GST + (g >> 1) * 8;
    #pragma unroll
    for (int p = 0; p < 4; p++)
        b_off[p] = (warp_n + p * 16 + (g >> 1) * 8 + lr) * GST + (g & 1) * 8;

    auto load_tile = [&](int st, int k0) {
        __half* as = sbase + st * 2 * STAGE_H;
        __half* bs = as + STAGE_H;
        #pragma unroll
        for (int i = 0; i < 4; i++) {
            int ci = tid + i * 256;
            int r = ci >> 3, c8 = ci & 7;
            cp_async16h(as + r * GST + c8 * 8,
                        A  + (size_t)(brow + r) * Kfull + koff + k0 + c8 * 8);
            cp_async16h(bs + r * GST + c8 * 8,
                        Wt + (size_t)(bcol + r) * Kfull + koff + k0 + c8 * 8);
        }
        cp_commit();
    };

    int nk = Kspan / 64;
    load_tile(0, 0);
    load_tile(1, 64);

    float acc[2][8][4];
    #pragma unroll
    for (int i = 0; i < 2; i++)
        #pragma unroll
        for (int j = 0; j < 8; j++)
            #pragma unroll
            for (int r = 0; r < 4; r++) acc[i][j][r] = 0.f;

    for (int t = 0; t < nk; t++) {
        if (t < nk - 1) asm volatile("cp.async.wait_group 1;");
        else            asm volatile("cp.async.wait_group 0;");
        __syncthreads();
        if (t + 2 < nk) load_tile((t + 2) % 3, (t + 2) * 64);

        uint32_t as_u = sm_u + (t % 3) * 2 * STAGE_H * 2;
        uint32_t bs_u = as_u + STAGE_H * 2;

        #pragma unroll
        for (int ks = 0; ks < 64; ks += 16) {
            uint32_t af[2][4];
            #pragma unroll
            for (int i = 0; i < 2; i++)
                ldsm_x4(af[i][0], af[i][1], af[i][2], af[i][3],
                        as_u + (uint32_t)(a_off[i] + ks) * 2);
            uint32_t bf[8][2];
            #pragma unroll
            for (int p = 0; p < 4; p++)
                ldsm_x4(bf[2 * p][0], bf[2 * p][1], bf[2 * p + 1][0], bf[2 * p + 1][1],
                        bs_u + (uint32_t)(b_off[p] + ks) * 2);
            #pragma unroll
            for (int i = 0; i < 2; i++)
                #pragma unroll
                for (int j = 0; j < 8; j++)
                    mma_f16(acc[i][j][0], acc[i][j][1], acc[i][j][2], acc[i][j][3],
                            af[i][0], af[i][1], af[i][2], af[i][3],
                            bf[j][0], bf[j][1]);
        }
    }

    #pragma unroll
    for (int i = 0; i < 2; i++) {
        #pragma unroll
        for (int j = 0; j < 8; j++) {
            int col = bcol + warp_n + j * 8 + 2 * lt;
            float bx = bias[col] * biasScale, by = bias[col + 1] * biasScale;
            int r0 = brow + warp_m + i * 16 + lg;
            float v0x = (acc[i][j][0] + bx) * outScale;
            float v0y = (acc[i][j][1] + by) * outScale;
            float v1x = (acc[i][j][2] + bx) * outScale;
            float v1y = (acc[i][j][3] + by) * outScale;
            if (RELU) {
                v0x = fmaxf(v0x, 0.f); v0y = fmaxf(v0y, 0.f);
                v1x = fmaxf(v1x, 0.f); v1y = fmaxf(v1y, 0.f);
            }
            if (OUT == 0) {
                float* C = (float*)Cv;
                *(float2*)&C[(size_t)r0 * N + col]       = make_float2(v0x, v0y);
                *(float2*)&C[(size_t)(r0 + 8) * N + col] = make_float2(v1x, v1y);
            } else if (OUT == 1) {
                __half* C = (__half*)Cv;
                *(__half2*)&C[(size_t)r0 * N + col]       = __floats2half2_rn(v0x, v0y);
                *(__half2*)&C[(size_t)(r0 + 8) * N + col] = __floats2half2_rn(v1x, v1y);
            } else {
                __half* C = (__half*)Cv;
                int bb = r0 >> 11, s = r0 & 2047;
                size_t base0 = (size_t)(bb * 512 + col) * 2048;
                size_t base1 = (size_t)(bb * 512 + col + 1) * 2048;
                C[base0 + s]     = __float2half_rn(v0x);
                C[base1 + s]     = __float2half_rn(v0y);
                C[base0 + s + 8] = __float2half_rn(v1x);
                C[base1 + s + 8] = __float2half_rn(v1y);
            }
        }
    }
}

__global__ __launch_bounds__(256, 2) void gemm_qkv(
    const __half* __restrict__ A,
    const __half* __restrict__ Wq, const __half* __restrict__ Wk, const __half* __restrict__ Wv,
    const float* __restrict__ bq, const float* __restrict__ bk, const float* __restrict__ bv,
    __half* q, __half* k, __half* vt, int N, int K)
{
    int z = blockIdx.z;
    if (z == 0)
        gemm_core<false, 1>(A, Wq, bq, 1.f, 0.125f * LOG2E, q,
                            blockIdx.y * 128, blockIdx.x * 128, N, K, 0, K);
    else if (z == 1)
        gemm_core<false, 1>(A, Wk, bk, 1.f, 1.f, k,
                            blockIdx.y * 128, blockIdx.x * 128, N, K, 0, K);
    else
        gemm_core<false, 2>(A, Wv, bv, 1.f, 1.f, vt,
                            blockIdx.y * 128, blockIdx.x * 128, N, K, 0, K);
}

__global__ __launch_bounds__(256, 2) void gemm_h(
    const __half* __restrict__ A, const __half* __restrict__ Wt,
    const float* __restrict__ bias, __half* C, int N, int K)
{
    gemm_core<true, 1>(A, Wt, bias, 1.f, 1.f, C,
                       blockIdx.y * 128, blockIdx.x * 128, N, K, 0, K);
}

__global__ __launch_bounds__(256, 2) void gemm_sk(
    const __half* __restrict__ A, const __half* __restrict__ Wt,
    const float* __restrict__ bias, float* C0, float* C1, int N, int K)
{
    int z = blockIdx.z;
    int Kh = K >> 1;
    gemm_core<false, 0>(A, Wt, bias, z == 0 ? 1.f : 0.f, 1.f,
                        z == 0 ? (void*)C0 : (void*)C1,
                        blockIdx.y * 128, blockIdx.x * 128, N, K, z * Kh, Kh);
}

// =========================================================================
// fp16 flash attention, log2-domain softmax, row-sums computed by MMA
// (B = all-ones): each thread's row sums live in acc_l[0]/acc_l[2].
// =========================================================================
#define FQS 72
#define NKV (S_ / 64)
#define FLASH_SMEM (128*FQS*2 + 3*64*FQS*2 + 3*64*FQS*2 + 3*64*4)

__global__ __launch_bounds__(256, 2) void flash_kernel(
    const __half* __restrict__ q, const __half* __restrict__ k,
    const __half* __restrict__ vt, const float* __restrict__ mbias,
    __half* __restrict__ out)
{
    extern __shared__ char smraw[];
    __half* Qh  = (__half*)smraw;
    __half* Ksm = Qh + 128 * FQS;
    __half* Vsm = Ksm + 3 * 64 * FQS;
    float*  MB  = (float*)(Vsm + 3 * 64 * FQS);

    int tid  = threadIdx.x;
    int lane = tid & 31;
    int warp = tid >> 5;
    int wm   = warp * 16;
    int lg = lane >> 2, lt = lane & 3;
    int g  = lane >> 3, lr = lane & 7;
    int brow = blockIdx.x * 128;
    int bh = blockIdx.y;
    int b = bh >> 3, h = bh & 7;

    const __half* Qb  = q  + (size_t)b * S_ * H_ + h * DH_;
    const __half* Kb  = k  + (size_t)b * S_ * H_ + h * DH_;
    const __half* Vtb = vt + (size_t)(b * 512 + h * 64) * 2048;
    const float*  MBg = mbias + b * S_;

    int q_off = (wm + (g & 1) * 8 + lr) * FQS + (g >> 1) * 8;
    int kv_off[4];
    #pragma unroll
    for (int p = 0; p < 4; p++)
        kv_off[p] = (p * 16 + (g >> 1) * 8 + lr) * FQS + (g & 1) * 8;

    auto load_kv = [&](int buf, int it) {
        int kv0 = it * 64;
        __half* kd = Ksm + buf * 64 * FQS;
        __half* vd = Vsm + buf * 64 * FQS;
        #pragma unroll
        for (int i = 0; i < 2; i++) {
            int ci = tid + i * 256;
            int r = ci >> 3, c8 = ci & 7;
            cp_async16h(kd + r * FQS + c8 * 8,
                        Kb + (size_t)(kv0 + r) * H_ + c8 * 8);
            cp_async16h(vd + r * FQS + c8 * 8,
                        Vtb + (size_t)r * S_ + kv0 + c8 * 8);
        }
        if (tid < 16) cp_async16f(&MB[buf * 64 + tid * 4], MBg + kv0 + tid * 4);
        cp_commit();
    };

    #pragma unroll
    for (int i = 0; i < 4; i++) {
        int ci = tid + i * 256;
        int r = ci >> 3, c8 = ci & 7;
        cp_async16h(Qh + r * FQS + c8 * 8,
                    Qb + (size_t)(brow + r) * H_ + c8 * 8);
    }
    cp_commit();
    load_kv(0, 0);
    load_kv(1, 1);
    asm volatile("cp.async.wait_group 2;");
    __syncthreads();

    uint32_t qh_u = smem_u32(Qh);
    uint32_t aq[4][4];
    #pragma unroll
    for (int ks = 0; ks < 4; ks++)
        ldsm_x4(aq[ks][0], aq[ks][1], aq[ks][2], aq[ks][3],
                qh_u + (uint32_t)(q_off + ks * 16) * 2);

    float acc_o[8][4];
    #pragma unroll
    for (int j = 0; j < 8; j++)
        #pragma unroll
        for (int rr = 0; rr < 4; rr++) acc_o[j][rr] = 0.f;
    float acc_l[4] = {0.f, 0.f, 0.f, 0.f};
    float m0 = -1e30f, m1 = -1e30f;

    for (int it = 0; it < NKV; it++) {
        int buf = it % 3;
        if (it < NKV - 1) asm volatile("cp.async.wait_group 1;");
        else              asm volatile("cp.async.wait_group 0;");
        __syncthreads();
        if (it + 2 < NKV) load_kv((it + 2) % 3, it + 2);

        uint32_t kt_u = smem_u32(Ksm + buf * 64 * FQS);
        uint32_t vt_u = smem_u32(Vsm + buf * 64 * FQS);
        const float* MBt = MB + buf * 64;

        // ---- S' = (Q*log2e/8) @ K^T ----
        float accs[8][4];
        #pragma unroll
        for (int j = 0; j < 8; j++)
            #pragma unroll
            for (int rr = 0; rr < 4; rr++) accs[j][rr] = 0.f;
        #pragma unroll
        for (int ks = 0; ks < 4; ks++) {
            uint32_t bf[8][2];
            #pragma unroll
            for (int p = 0; p < 4; p++)
                ldsm_x4(bf[2 * p][0], bf[2 * p][1], bf[2 * p + 1][0], bf[2 * p + 1][1],
                        kt_u + (uint32_t)(kv_off[p] + ks * 16) * 2);
            #pragma unroll
            for (int j = 0; j < 8; j++)
                mma_f16(accs[j][0], accs[j][1], accs[j][2], accs[j][3],
                        aq[ks][0], aq[ks][1], aq[ks][2], aq[ks][3],
                        bf[j][0], bf[j][1]);
        }

        // ---- + mask bias (skipped exactly when all-zero) ----
        bool zerob = true;
        #pragma unroll
        for (int j = 0; j < 8; j++) {
            float2 mv = *(const float2*)&MBt[j * 8 + 2 * lt];
            zerob = zerob && (mv.x == 0.f) && (mv.y == 0.f);
        }
        if (!__all_sync(0xffffffffu, zerob)) {
            #pragma unroll
            for (int j = 0; j < 8; j++) {
                float2 mv = *(const float2*)&MBt[j * 8 + 2 * lt];
                accs[j][0] += mv.x;
                accs[j][1] += mv.y;
                accs[j][2] += mv.x;
                accs[j][3] += mv.y;
            }
        }

        // ---- row max ----
        float mr0 = -1e30f, mr1 = -1e30f;
        #pragma unroll
        for (int j = 0; j < 8; j++) {
            mr0 = fmaxf(mr0, fmaxf(accs[j][0], accs[j][1]));
            mr1 = fmaxf(mr1, fmaxf(accs[j][2], accs[j][3]));
        }
        mr0 = fmaxf(mr0, __shfl_xor_sync(0xffffffffu, mr0, 1));
        mr0 = fmaxf(mr0, __shfl_xor_sync(0xffffffffu, mr0, 2));
        mr1 = fmaxf(mr1, __shfl_xor_sync(0xffffffffu, mr1, 1));
        mr1 = fmaxf(mr1, __shfl_xor_sync(0xffffffffu, mr1, 2));

        float mn0 = fmaxf(m0, mr0), mn1 = fmaxf(m1, mr1);
        float al0 = exp2f(m0 - mn0), al1 = exp2f(m1 - mn1);
        m0 = mn0; m1 = mn1;

        // ---- P = exp2(S' - m'), pack ----
        uint32_t pp[8][2];
        #pragma unroll
        for (int j = 0; j < 8; j++) {
            float p0 = exp2f(accs[j][0] - mn0);
            float p1 = exp2f(accs[j][1] - mn0);
            float p2 = exp2f(accs[j][2] - mn1);
            float p3 = exp2f(accs[j][3] - mn1);
            pp[j][0] = pack_h2(p0, p1);
            pp[j][1] = pack_h2(p2, p3);
        }

        // rescale running output + running sums (skip is exact)
        if (!__all_sync(0xffffffffu, (al0 == 1.f) && (al1 == 1.f))) {
            #pragma unroll
            for (int j = 0; j < 8; j++) {
                acc_o[j][0] *= al0; acc_o[j][1] *= al0;
                acc_o[j][2] *= al1; acc_o[j][3] *= al1;
            }
            acc_l[0] *= al0; acc_l[1] *= al0;
            acc_l[2] *= al1; acc_l[3] *= al1;
        }

        // ---- O += P @ V, and l += P @ ones (row sums via MMA) ----
        #pragma unroll
        for (int kk = 0; kk < 4; kk++) {
            uint32_t a0 = pp[2 * kk][0];
            uint32_t a1 = pp[2 * kk][1];
            uint32_t a2 = pp[2 * kk + 1][0];
            uint32_t a3 = pp[2 * kk + 1][1];
            uint32_t bf[8][2];
            #pragma unroll
            for (int p = 0; p < 4; p++)
                ldsm_x4(bf[2 * p][0], bf[2 * p][1], bf[2 * p + 1][0], bf[2 * p + 1][1],
                        vt_u + (uint32_t)(kv_off[p] + kk * 16) * 2);
            #pragma unroll
            for (int j = 0; j < 8; j++)
                mma_f16(acc_o[j][0], acc_o[j][1], acc_o[j][2], acc_o[j][3],
                        a0, a1, a2, a3, bf[j][0], bf[j][1]);
            mma_f16(acc_l[0], acc_l[1], acc_l[2], acc_l[3],
                    a0, a1, a2, a3, ONES_H2, ONES_H2);
        }
    }

    float i0 = 1.f / acc_l[0], i1 = 1.f / acc_l[2];
    int r0 = brow + wm + lg;
    int tok0 = b * S_ + r0;
    #pragma unroll
    for (int j = 0; j < 8; j++) {
        int col = h * DH_ + j * 8 + 2 * lt;
        *(__half2*)&out[(size_t)tok0 * H_ + col] =
            __floats2half2_rn(acc_o[j][0] * i0, acc_o[j][1] * i0);
        *(__half2*)&out[(size_t)(tok0 + 8) * H_ + col] =
            __floats2half2_rn(acc_o[j][2] * i1, acc_o[j][3] * i1);
    }
}

// ------- residual + LayerNorm, warp-per-row ----
__global__ __launch_bounds__(256) void add_ln_kernel(
    const float* __restrict__ xin,
    const float* __restrict__ ya, const float* __restrict__ yb,
    const float* __restrict__ gamma, const float* __restrict__ beta,
    float* __restrict__ out, __half* __restrict__ out_r)
{
    int warp = threadIdx.x >> 5;
    int lane = threadIdx.x & 31;
    int t = blockIdx.x * 8 + warp;
    size_t base = (size_t)t * H_;

    float v[16];
    float s1 = 0.f, s2 = 0.f;
    #pragma unroll
    for (int i = 0; i < 16; i++) {
        int c = lane + i * 32;
        v[i] = ya[base + c] + yb[base + c];
        s1 += v[i];
        s2 += v[i] * v[i];
    }
    #pragma unroll
    for (int off = 16; off > 0; off >>= 1) {
        s1 += __shfl_xor_sync(0xffffffffu, s1, off);
        s2 += __shfl_xor_sync(0xffffffffu, s2, off);
    }
    float mean = s1 * (1.f / (float)H_);
    float var  = s2 * (1.f / (float)H_) - mean * mean;
    float r = rsqrtf(var + 1e-5f);
    #pragma unroll
    for (int i = 0; i < 16; i++) {
        int c = lane + i * 32;
        float o = xin[base + c] + (v[i] - mean) * r * gamma[c] + beta[c];
        out[base + c]   = o;
        out_r[base + c] = __float2half_rn(o);
    }
}

// ---------------- host launcher ----------------
extern "C" void kernel_launch(void* const* d_in, const int* in_sizes, int n_in,
                              void* d_out, int out_size)
{
    const int*   src  = (const int*)  d_in[0];
    const int*   mask = (const int*)  d_in[1];
    const float* emb  = (const float*)d_in[2];
    const float* Wq   = (const float*)d_in[3];
    const float* bq   = (const float*)d_in[4];
    const float* Wk   = (const float*)d_in[5];
    const float* bk   = (const float*)d_in[6];
    const float* Wv   = (const float*)d_in[7];
    const float* bv   = (const float*)d_in[8];
    const float* Wo   = (const float*)d_in[9];
    const float* bo   = (const float*)d_in[10];
    const float* gamma= (const float*)d_in[11];
    const float* beta = (const float*)d_in[12];
    const float* W1   = (const float*)d_in[13];
    const float* b1   = (const float*)d_in[14];
    const float* W2   = (const float*)d_in[15];
    const float* b2   = (const float*)d_in[16];

    float *x, *res, *t2a, *t2b, *mb;
    __half *xr, *q, *k, *vt, *t, *resr, *h1, *wh;
    cudaGetSymbolAddress((void**)&x,    g_x);
    cudaGetSymbolAddress((void**)&res,  g_res);
    cudaGetSymbolAddress((void**)&t2a,  g_t2a);
    cudaGetSymbolAddress((void**)&t2b,  g_t2b);
    cudaGetSymbolAddress((void**)&mb,   g_mb);
    cudaGetSymbolAddress((void**)&xr,   g_xr);
    cudaGetSymbolAddress((void**)&q,    g_q);
    cudaGetSymbolAddress((void**)&k,    g_k);
    cudaGetSymbolAddress((void**)&vt,   g_vt);
    cudaGetSymbolAddress((void**)&t,    g_t);
    cudaGetSymbolAddress((void**)&resr, g_resr);
    cudaGetSymbolAddress((void**)&h1,   g_h1);
    cudaGetSymbolAddress((void**)&wh,   g_wh);

    cudaFuncSetAttribute(flash_kernel,
                         cudaFuncAttributeMaxDynamicSharedMemorySize, FLASH_SMEM);
    cudaFuncSetAttribute(gemm_qkv,
                         cudaFuncAttributeMaxDynamicSharedMemorySize, GEMM_SMEM);
    cudaFuncSetAttribute(gemm_h,
                         cudaFuncAttributeMaxDynamicSharedMemorySize, GEMM_SMEM);
    cudaFuncSetAttribute(gemm_sk,
                         cudaFuncAttributeMaxDynamicSharedMemorySize, GEMM_SMEM);

    transpose_all_kernel<<<L_ * 3072, 256>>>(Wq, Wk, Wv, Wo, W1, W2, wh);
    embed_kernel<<<(M_ * H_) / 256, 256>>>(src, emb, mask, x, xr, mb);

    dim3 gQKV (H_ / 128,  M_ / 128, 3);
    dim3 gSK  (H_ / 128,  M_ / 128, 2);
    dim3 gFfn1(FF_ / 128, M_ / 128, 1);
    dim3 gFlash(S_ / 128, B_ * NH_);

    for (int i = 0; i < L_; i++) {
        const __half* WqT = wh + WOFF_Q + (size_t)i * H_ * H_;
        const __half* WkT = wh + WOFF_K + (size_t)i * H_ * H_;
        const __half* WvT = wh + WOFF_V + (size_t)i * H_ * H_;
        const __half* WoT = wh + WOFF_O + (size_t)i * H_ * H_;
        const __half* W1T = wh + WOFF_1 + (size_t)i * H_ * FF_;
        const __half* W2T = wh + WOFF_2 + (size_t)i * FF_ * H_;
        const float* bq_i = bq + i * H_;
        const float* bk_i = bk + i * H_;
        const float* bv_i = bv + i * H_;
        const float* bo_i = bo + i * H_;
        const float* b1_i = b1 + i * FF_;
        const float* b2_i = b2 + i * H_;
        const float* g_i  = gamma + i * H_;
        const float* be_i = beta  + i * H_;
        float* xout = (i == L_ - 1) ? (float*)d_out : x;

        gemm_qkv<<<gQKV, 256, GEMM_SMEM>>>(
            xr, WqT, WkT, WvT, bq_i, bk_i, bv_i, q, k, vt, H_, H_);

        flash_kernel<<<gFlash, 256, FLASH_SMEM>>>(q, k, vt, mb, t);

        gemm_sk<<<gSK, 256, GEMM_SMEM>>>(t, WoT, bo_i, t2a, t2b, H_, H_);
        add_ln_kernel<<<M_ / 8, 256>>>(x, t2a, t2b, g_i, be_i, res, resr);

        gemm_h<<<gFfn1, 256, GEMM_SMEM>>>(resr, W1T, b1_i, h1, FF_, H_);

        gemm_sk<<<gSK, 256, GEMM_SMEM>>>(h1, W2T, b2_i, t2a, t2b, H_, FF_);
        add_ln_kernel<<<M_ / 8, 256>>>(res, t2a, t2b, g_i, be_i, xout, resr);
        xr = resr;
    }
}

// round 17
// speedup vs baseline: 2.1086x; 1.0352x over previous
#include <cuda_runtime.h>
#include <cuda_fp16.h>
#include <math.h>
#include <stdint.h>

// Problem dims
#define B_  2
#define S_  2048
#define H_  512
#define NH_ 8
#define DH_ 64
#define L_  6
#define FF_ 2048
#define M_  (B_*S_)

#define LOG2E 1.4426950408889634f
#define ONES_H2 0x3C003C00u   // (1.0h, 1.0h)
#define NKV (S_ / 64)

// ---------------- device scratch ----------------
__device__ float  g_x  [M_*H_];
__device__ float  g_res[M_*H_];
__device__ float  g_t2a[M_*H_];
__device__ float  g_t2b[M_*H_];
__device__ float  g_mb [M_];
__device__ int    g_mbf[B_*NKV];    // 1 if kv tile fully unmasked
__device__ __half g_xr [M_*H_];
__device__ __half g_q  [M_*H_];
__device__ __half g_k  [M_*H_];
__device__ __half g_vt [M_*H_];     // V transposed: [(b*512+d)][s]
__device__ __half g_t  [M_*H_];
__device__ __half g_resr[M_*H_];
__device__ __half g_h1 [M_*FF_];
__device__ __half g_wh [18874368];  // transposed half weights [N][K]

#define WOFF_Q  0
#define WOFF_K  (L_*H_*H_)
#define WOFF_V  (2*L_*H_*H_)
#define WOFF_O  (3*L_*H_*H_)
#define WOFF_1  (4*L_*H_*H_)
#define WOFF_2  (4*L_*H_*H_ + L_*H_*FF_)

// ---------------- helpers ----------------
__device__ __forceinline__ void mma_f16(
    float& c0, float& c1, float& c2, float& c3,
    uint32_t a0, uint32_t a1, uint32_t a2, uint32_t a3,
    uint32_t b0, uint32_t b1)
{
    asm volatile(
        "mma.sync.aligned.m16n8k16.row.col.f32.f16.f16.f32 "
        "{%0,%1,%2,%3}, {%4,%5,%6,%7}, {%8,%9}, {%0,%1,%2,%3};\n"
        : "+f"(c0), "+f"(c1), "+f"(c2), "+f"(c3)
        : "r"(a0), "r"(a1), "r"(a2), "r"(a3), "r"(b0), "r"(b1));
}
__device__ __forceinline__ void ldsm_x4(
    uint32_t& r0, uint32_t& r1, uint32_t& r2, uint32_t& r3, uint32_t addr)
{
    asm volatile(
        "ldmatrix.sync.aligned.m8n8.x4.shared.b16 {%0,%1,%2,%3}, [%4];"
        : "=r"(r0), "=r"(r1), "=r"(r2), "=r"(r3) : "r"(addr));
}
__device__ __forceinline__ uint32_t smem_u32(const void* p) {
    return (uint32_t)__cvta_generic_to_shared(p);
}
__device__ __forceinline__ uint32_t pack_h2(float lo, float hi) {
    __half2 h = __floats2half2_rn(lo, hi);
    return *(uint32_t*)&h;
}
__device__ __forceinline__ uint32_t ex2_h2(uint32_t x) {
    uint32_t y;
    asm("ex2.approx.f16x2 %0, %1;" : "=r"(y) : "r"(x));
    return y;
}
__device__ __forceinline__ void cp_async16f(float* dst, const float* src) {
    unsigned s = (unsigned)__cvta_generic_to_shared(dst);
    asm volatile("cp.async.cg.shared.global [%0], [%1], 16;" :: "r"(s), "l"(src));
}
__device__ __forceinline__ void cp_async16h(__half* dst, const __half* src) {
    unsigned s = (unsigned)__cvta_generic_to_shared(dst);
    asm volatile("cp.async.cg.shared.global [%0], [%1], 16;" :: "r"(s), "l"(src));
}
__device__ __forceinline__ void cp_commit() {
    asm volatile("cp.async.commit_group;");
}

// ---------------- fused weight transpose (one launch) ----------------
__global__ __launch_bounds__(256) void transpose_all_kernel(
    const float* __restrict__ Wq, const float* __restrict__ Wk,
    const float* __restrict__ Wv, const float* __restrict__ Wo,
    const float* __restrict__ W1, const float* __restrict__ W2,
    __half* __restrict__ wh)
{
    __shared__ float tile[32][33];
    int idx = blockIdx.x;
    int layer = idx / 3072;
    int r = idx % 3072;

    const float* src;
    __half* dst;
    int K, N, nt, kt;
    if (r < 1024) {
        int m = r >> 8, t = r & 255;
        nt = t & 15; kt = t >> 4;
        K = H_; N = H_;
        src = (m == 0) ? Wq : (m == 1) ? Wk : (m == 2) ? Wv : Wo;
        dst = wh + (size_t)m * (L_ * H_ * H_);
        src += (size_t)layer * H_ * H_;
        dst += (size_t)layer * H_ * H_;
    } else if (r < 2048) {
        int t = r - 1024;
        nt = t & 63; kt = t >> 6;
        K = H_; N = FF_;
        src = W1 + (size_t)layer * H_ * FF_;
        dst = wh + WOFF_1 + (size_t)layer * H_ * FF_;
    } else {
        int t = r - 2048;
        nt = t & 15; kt = t >> 4;
        K = FF_; N = H_;
        src = W2 + (size_t)layer * FF_ * H_;
        dst = wh + WOFF_2 + (size_t)layer * FF_ * H_;
    }

    int n0 = nt * 32, k0 = kt * 32;
    int tx = threadIdx.x & 31, ty = threadIdx.x >> 5;
    #pragma unroll
    for (int i = 0; i < 4; i++)
        tile[ty + i * 8][tx] = src[(size_t)(k0 + ty + i * 8) * N + n0 + tx];
    __syncthreads();
    #pragma unroll
    for (int i = 0; i < 4; i++)
        dst[(size_t)(n0 + ty + i * 8) * K + k0 + tx] =
            __float2half_rn(tile[tx][ty + i * 8]);
}

// ---------------- embedding + posenc + mask bias + tile flags ----------
__global__ __launch_bounds__(256) void embed_kernel(
    const int* __restrict__ src, const float* __restrict__ emb,
    const int* __restrict__ mask,
    float* __restrict__ x, __half* __restrict__ xr, float* __restrict__ mb,
    int* __restrict__ mbf)
{
    int idx = blockIdx.x * 256 + threadIdx.x;
    int d   = idx & (H_ - 1);
    int tok = idx >> 9;
    int s   = tok & (S_ - 1);
    int j2  = (d >> 1) * 2;
    float div = powf(10000.0f, (float)j2 * (1.0f / (float)H_));
    float arg = (float)s / div;
    float pe  = (d & 1) ? cosf(arg) : sinf(arg);
    float v = emb[(size_t)src[tok] * H_ + d] + pe;
    x[idx]  = v;
    xr[idx] = __float2half_rn(v);
    if (idx < M_) mb[idx] = mask[idx] ? 0.f : (-1e20f * LOG2E);
    if (idx < B_ * NKV) {
        int ok = 1;
        int base = idx * 64;            // (b, tile) flat -> mask offset
        #pragma unroll 8
        for (int i = 0; i < 64; i++) ok &= (mask[base + i] != 0);
        mbf[idx] = ok;
    }
}

// =========================================================================
// fp16 GEMM core, BK=64, single-barrier 3-stage pipeline, LDSM fragments.
// =========================================================================
#define GST 72
#define STAGE_H (128 * GST)
#define GEMM_SMEM (3 * 2 * STAGE_H * 2)

template<bool RELU, int OUT>
__device__ __forceinline__ void gemm_core(
    const __half* __restrict__ A, const __half* __restrict__ Wt,
    const float* __restrict__ bias, float biasScale, float outScale,
    void* Cv, int brow, int bcol, int N, int Kfull, int koff, int Kspan)
{
    extern __shared__ char smraw[];
    __half* sbase = (__half*)smraw;
    uint32_t sm_u = smem_u32(sbase);

    int tid  = threadIdx.x;
    int lane = tid & 31;
    int warp = tid >> 5;
    int warp_m = (warp >> 1) * 32;
    int warp_n = (warp & 1) * 64;
    int lg = lane >> 2, lt = lane & 3;
    int g  = lane >> 3, lr = lane & 7;

    int a_off[2], b_off[4];
    #pragma unroll
    for (int i = 0; i < 2; i++)
        a_off[i] = (warp_m + i * 16 + (g & 1) * 8 + lr) * GST + (g >> 1) * 8;
    #pragma unroll
    for (int p = 0; p < 4; p++)
        b_off[p] = (warp_n + p * 16 + (g >> 1) * 8 + lr) * GST + (g & 1) * 8;

    auto load_tile = [&](int st, int k0) {
        __half* as = sbase + st * 2 * STAGE_H;
        __half* bs = as + STAGE_H;
        #pragma unroll
        for (int i = 0; i < 4; i++) {
            int ci = tid + i * 256;
            int r = ci >> 3, c8 = ci & 7;
            cp_async16h(as + r * GST + c8 * 8,
                        A  + (size_t)(brow + r) * Kfull + koff + k0 + c8 * 8);
            cp_async16h(bs + r * GST + c8 * 8,
                        Wt + (size_t)(bcol + r) * Kfull + koff + k0 + c8 * 8);
        }
        cp_commit();
    };

    int nk = Kspan / 64;
    load_tile(0, 0);
    load_tile(1, 64);

    float acc[2][8][4];
    #pragma unroll
    for (int i = 0; i < 2; i++)
        #pragma unroll
        for (int j = 0; j < 8; j++)
            #pragma unroll
            for (int r = 0; r < 4; r++) acc[i][j][r] = 0.f;

    for (int t = 0; t < nk; t++) {
        if (t < nk - 1) asm volatile("cp.async.wait_group 1;");
        else            asm volatile("cp.async.wait_group 0;");
        __syncthreads();
        if (t + 2 < nk) load_tile((t + 2) % 3, (t + 2) * 64);

        uint32_t as_u = sm_u + (t % 3) * 2 * STAGE_H * 2;
        uint32_t bs_u = as_u + STAGE_H * 2;

        #pragma unroll
        for (int ks = 0; ks < 64; ks += 16) {
            uint32_t af[2][4];
            #pragma unroll
            for (int i = 0; i < 2; i++)
                ldsm_x4(af[i][0], af[i][1], af[i][2], af[i][3],
                        as_u + (uint32_t)(a_off[i] + ks) * 2);
            uint32_t bf[8][2];
            #pragma unroll
            for (int p = 0; p < 4; p++)
                ldsm_x4(bf[2 * p][0], bf[2 * p][1], bf[2 * p + 1][0], bf[2 * p + 1][1],
                        bs_u + (uint32_t)(b_off[p] + ks) * 2);
            #pragma unroll
            for (int i = 0; i < 2; i++)
                #pragma unroll
                for (int j = 0; j < 8; j++)
                    mma_f16(acc[i][j][0], acc[i][j][1], acc[i][j][2], acc[i][j][3],
                            af[i][0], af[i][1], af[i][2], af[i][3],
                            bf[j][0], bf[j][1]);
        }
    }

    #pragma unroll
    for (int i = 0; i < 2; i++) {
        #pragma unroll
        for (int j = 0; j < 8; j++) {
            int col = bcol + warp_n + j * 8 + 2 * lt;
            float bx = bias[col] * biasScale, by = bias[col + 1] * biasScale;
            int r0 = brow + warp_m + i * 16 + lg;
            float v0x = (acc[i][j][0] + bx) * outScale;
            float v0y = (acc[i][j][1] + by) * outScale;
            float v1x = (acc[i][j][2] + bx) * outScale;
            float v1y = (acc[i][j][3] + by) * outScale;
            if (RELU) {
                v0x = fmaxf(v0x, 0.f); v0y = fmaxf(v0y, 0.f);
                v1x = fmaxf(v1x, 0.f); v1y = fmaxf(v1y, 0.f);
            }
            if (OUT == 0) {
                float* C = (float*)Cv;
                *(float2*)&C[(size_t)r0 * N + col]       = make_float2(v0x, v0y);
                *(float2*)&C[(size_t)(r0 + 8) * N + col] = make_float2(v1x, v1y);
            } else if (OUT == 1) {
                __half* C = (__half*)Cv;
                *(__half2*)&C[(size_t)r0 * N + col]       = __floats2half2_rn(v0x, v0y);
                *(__half2*)&C[(size_t)(r0 + 8) * N + col] = __floats2half2_rn(v1x, v1y);
            } else {
                __half* C = (__half*)Cv;
                int bb = r0 >> 11, s = r0 & 2047;
                size_t base0 = (size_t)(bb * 512 + col) * 2048;
                size_t base1 = (size_t)(bb * 512 + col + 1) * 2048;
                C[base0 + s]     = __float2half_rn(v0x);
                C[base1 + s]     = __float2half_rn(v0y);
                C[base0 + s + 8] = __float2half_rn(v1x);
                C[base1 + s + 8] = __float2half_rn(v1y);
            }
        }
    }
}

__global__ __launch_bounds__(256, 2) void gemm_qkv(
    const __half* __restrict__ A,
    const __half* __restrict__ Wq, const __half* __restrict__ Wk, const __half* __restrict__ Wv,
    const float* __restrict__ bq, const float* __restrict__ bk, const float* __restrict__ bv,
    __half* q, __half* k, __half* vt, int N, int K)
{
    int z = blockIdx.z;
    if (z == 0)
        gemm_core<false, 1>(A, Wq, bq, 1.f, 0.125f * LOG2E, q,
                            blockIdx.y * 128, blockIdx.x * 128, N, K, 0, K);
    else if (z == 1)
        gemm_core<false, 1>(A, Wk, bk, 1.f, 1.f, k,
                            blockIdx.y * 128, blockIdx.x * 128, N, K, 0, K);
    else
        gemm_core<false, 2>(A, Wv, bv, 1.f, 1.f, vt,
                            blockIdx.y * 128, blockIdx.x * 128, N, K, 0, K);
}

__global__ __launch_bounds__(256, 2) void gemm_h(
    const __half* __restrict__ A, const __half* __restrict__ Wt,
    const float* __restrict__ bias, __half* C, int N, int K)
{
    gemm_core<true, 1>(A, Wt, bias, 1.f, 1.f, C,
                       blockIdx.y * 128, blockIdx.x * 128, N, K, 0, K);
}

__global__ __launch_bounds__(256, 2) void gemm_sk(
    const __half* __restrict__ A, const __half* __restrict__ Wt,
    const float* __restrict__ bias, float* C0, float* C1, int N, int K)
{
    int z = blockIdx.z;
    int Kh = K >> 1;
    gemm_core<false, 0>(A, Wt, bias, z == 0 ? 1.f : 0.f, 1.f,
                        z == 0 ? (void*)C0 : (void*)C1,
                        blockIdx.y * 128, blockIdx.x * 128, N, K, z * Kh, Kh);
}

// =========================================================================
// fp16 flash attention, log2-domain softmax, MMA row-sums, f16x2 EX2,
// hoisted per-tile mask flag.
// =========================================================================
#define FQS 72
#define FLASH_SMEM (128*FQS*2 + 3*64*FQS*2 + 3*64*FQS*2 + 3*64*4)

__global__ __launch_bounds__(256, 2) void flash_kernel(
    const __half* __restrict__ q, const __half* __restrict__ k,
    const __half* __restrict__ vt, const float* __restrict__ mbias,
    const int* __restrict__ mbf, __half* __restrict__ out)
{
    extern __shared__ char smraw[];
    __half* Qh  = (__half*)smraw;
    __half* Ksm = Qh + 128 * FQS;
    __half* Vsm = Ksm + 3 * 64 * FQS;
    float*  MB  = (float*)(Vsm + 3 * 64 * FQS);

    int tid  = threadIdx.x;
    int lane = tid & 31;
    int warp = tid >> 5;
    int wm   = warp * 16;
    int lg = lane >> 2, lt = lane & 3;
    int g  = lane >> 3, lr = lane & 7;
    int brow = blockIdx.x * 128;
    int bh = blockIdx.y;
    int b = bh >> 3, h = bh & 7;

    const __half* Qb  = q  + (size_t)b * S_ * H_ + h * DH_;
    const __half* Kb  = k  + (size_t)b * S_ * H_ + h * DH_;
    const __half* Vtb = vt + (size_t)(b * 512 + h * 64) * 2048;
    const float*  MBg = mbias + b * S_;
    const int*    MBF = mbf + b * NKV;

    int q_off = (wm + (g & 1) * 8 + lr) * FQS + (g >> 1) * 8;
    int kv_off[4];
    #pragma unroll
    for (int p = 0; p < 4; p++)
        kv_off[p] = (p * 16 + (g >> 1) * 8 + lr) * FQS + (g & 1) * 8;

    auto load_kv = [&](int buf, int it) {
        int kv0 = it * 64;
        __half* kd = Ksm + buf * 64 * FQS;
        __half* vd = Vsm + buf * 64 * FQS;
        #pragma unroll
        for (int i = 0; i < 2; i++) {
            int ci = tid + i * 256;
            int r = ci >> 3, c8 = ci & 7;
            cp_async16h(kd + r * FQS + c8 * 8,
                        Kb + (size_t)(kv0 + r) * H_ + c8 * 8);
            cp_async16h(vd + r * FQS + c8 * 8,
                        Vtb + (size_t)r * S_ + kv0 + c8 * 8);
        }
        if (tid < 16) cp_async16f(&MB[buf * 64 + tid * 4], MBg + kv0 + tid * 4);
        cp_commit();
    };

    #pragma unroll
    for (int i = 0; i < 4; i++) {
        int ci = tid + i * 256;
        int r = ci >> 3, c8 = ci & 7;
        cp_async16h(Qh + r * FQS + c8 * 8,
                    Qb + (size_t)(brow + r) * H_ + c8 * 8);
    }
    cp_commit();
    load_kv(0, 0);
    load_kv(1, 1);
    asm volatile("cp.async.wait_group 2;");
    __syncthreads();

    uint32_t qh_u = smem_u32(Qh);
    uint32_t aq[4][4];
    #pragma unroll
    for (int ks = 0; ks < 4; ks++)
        ldsm_x4(aq[ks][0], aq[ks][1], aq[ks][2], aq[ks][3],
                qh_u + (uint32_t)(q_off + ks * 16) * 2);

    float acc_o[8][4];
    #pragma unroll
    for (int j = 0; j < 8; j++)
        #pragma unroll
        for (int rr = 0; rr < 4; rr++) acc_o[j][rr] = 0.f;
    float acc_l[4] = {0.f, 0.f, 0.f, 0.f};
    float m0 = -1e30f, m1 = -1e30f;

    for (int it = 0; it < NKV; it++) {
        int buf = it % 3;
        if (it < NKV - 1) asm volatile("cp.async.wait_group 1;");
        else              asm volatile("cp.async.wait_group 0;");
        __syncthreads();
        if (it + 2 < NKV) load_kv((it + 2) % 3, it + 2);

        uint32_t kt_u = smem_u32(Ksm + buf * 64 * FQS);
        uint32_t vt_u = smem_u32(Vsm + buf * 64 * FQS);
        const float* MBt = MB + buf * 64;

        // ---- S' = (Q*log2e/8) @ K^T ----
        float accs[8][4];
        #pragma unroll
        for (int j = 0; j < 8; j++)
            #pragma unroll
            for (int rr = 0; rr < 4; rr++) accs[j][rr] = 0.f;
        #pragma unroll
        for (int ks = 0; ks < 4; ks++) {
            uint32_t bf[8][2];
            #pragma unroll
            for (int p = 0; p < 4; p++)
                ldsm_x4(bf[2 * p][0], bf[2 * p][1], bf[2 * p + 1][0], bf[2 * p + 1][1],
                        kt_u + (uint32_t)(kv_off[p] + ks * 16) * 2);
            #pragma unroll
            for (int j = 0; j < 8; j++)
                mma_f16(accs[j][0], accs[j][1], accs[j][2], accs[j][3],
                        aq[ks][0], aq[ks][1], aq[ks][2], aq[ks][3],
                        bf[j][0], bf[j][1]);
        }

        // ---- + mask bias only if this tile has masked columns ----
        if (!__ldg(&MBF[it])) {
            #pragma unroll
            for (int j = 0; j < 8; j++) {
                float2 mv = *(const float2*)&MBt[j * 8 + 2 * lt];
                accs[j][0] += mv.x;
                accs[j][1] += mv.y;
                accs[j][2] += mv.x;
                accs[j][3] += mv.y;
            }
        }

        // ---- row max ----
        float mr0 = -1e30f, mr1 = -1e30f;
        #pragma unroll
        for (int j = 0; j < 8; j++) {
            mr0 = fmaxf(mr0, fmaxf(accs[j][0], accs[j][1]));
            mr1 = fmaxf(mr1, fmaxf(accs[j][2], accs[j][3]));
        }
        mr0 = fmaxf(mr0, __shfl_xor_sync(0xffffffffu, mr0, 1));
        mr0 = fmaxf(mr0, __shfl_xor_sync(0xffffffffu, mr0, 2));
        mr1 = fmaxf(mr1, __shfl_xor_sync(0xffffffffu, mr1, 1));
        mr1 = fmaxf(mr1, __shfl_xor_sync(0xffffffffu, mr1, 2));

        float mn0 = fmaxf(m0, mr0), mn1 = fmaxf(m1, mr1);
        float al0 = exp2f(m0 - mn0), al1 = exp2f(m1 - mn1);
        m0 = mn0; m1 = mn1;

        // ---- P = exp2(S' - m') via f16x2 EX2 (pack exponents, then exp) ----
        uint32_t pp[8][2];
        #pragma unroll
        for (int j = 0; j < 8; j++) {
            pp[j][0] = ex2_h2(pack_h2(accs[j][0] - mn0, accs[j][1] - mn0));
            pp[j][1] = ex2_h2(pack_h2(accs[j][2] - mn1, accs[j][3] - mn1));
        }

        // rescale running output + running sums (skip is exact)
        if (!__all_sync(0xffffffffu, (al0 == 1.f) && (al1 == 1.f))) {
            #pragma unroll
            for (int j = 0; j < 8; j++) {
                acc_o[j][0] *= al0; acc_o[j][1] *= al0;
                acc_o[j][2] *= al1; acc_o[j][3] *= al1;
            }
            acc_l[0] *= al0; acc_l[1] *= al0;
            acc_l[2] *= al1; acc_l[3] *= al1;
        }

        // ---- O += P @ V, and l += P @ ones (row sums via MMA) ----
        #pragma unroll
        for (int kk = 0; kk < 4; kk++) {
            uint32_t a0 = pp[2 * kk][0];
            uint32_t a1 = pp[2 * kk][1];
            uint32_t a2 = pp[2 * kk + 1][0];
            uint32_t a3 = pp[2 * kk + 1][1];
            uint32_t bf[8][2];
            #pragma unroll
            for (int p = 0; p < 4; p++)
                ldsm_x4(bf[2 * p][0], bf[2 * p][1], bf[2 * p + 1][0], bf[2 * p + 1][1],
                        vt_u + (uint32_t)(kv_off[p] + kk * 16) * 2);
            #pragma unroll
            for (int j = 0; j < 8; j++)
                mma_f16(acc_o[j][0], acc_o[j][1], acc_o[j][2], acc_o[j][3],
                        a0, a1, a2, a3, bf[j][0], bf[j][1]);
            mma_f16(acc_l[0], acc_l[1], acc_l[2], acc_l[3],
                    a0, a1, a2, a3, ONES_H2, ONES_H2);
        }
    }

    float i0 = 1.f / acc_l[0], i1 = 1.f / acc_l[2];
    int r0 = brow + wm + lg;
    int tok0 = b * S_ + r0;
    #pragma unroll
    for (int j = 0; j < 8; j++) {
        int col = h * DH_ + j * 8 + 2 * lt;
        *(__half2*)&out[(size_t)tok0 * H_ + col] =
            __floats2half2_rn(acc_o[j][0] * i0, acc_o[j][1] * i0);
        *(__half2*)&out[(size_t)(tok0 + 8) * H_ + col] =
            __floats2half2_rn(acc_o[j][2] * i1, acc_o[j][3] * i1);
    }
}

// ------- residual + LayerNorm, warp-per-row ----
__global__ __launch_bounds__(256) void add_ln_kernel(
    const float* __restrict__ xin,
    const float* __restrict__ ya, const float* __restrict__ yb,
    const float* __restrict__ gamma, const float* __restrict__ beta,
    float* __restrict__ out, __half* __restrict__ out_r)
{
    int warp = threadIdx.x >> 5;
    int lane = threadIdx.x & 31;
    int t = blockIdx.x * 8 + warp;
    size_t base = (size_t)t * H_;

    float v[16];
    float s1 = 0.f, s2 = 0.f;
    #pragma unroll
    for (int i = 0; i < 16; i++) {
        int c = lane + i * 32;
        v[i] = ya[base + c] + yb[base + c];
        s1 += v[i];
        s2 += v[i] * v[i];
    }
    #pragma unroll
    for (int off = 16; off > 0; off >>= 1) {
        s1 += __shfl_xor_sync(0xffffffffu, s1, off);
        s2 += __shfl_xor_sync(0xffffffffu, s2, off);
    }
    float mean = s1 * (1.f / (float)H_);
    float var  = s2 * (1.f / (float)H_) - mean * mean;
    float r = rsqrtf(var + 1e-5f);
    #pragma unroll
    for (int i = 0; i < 16; i++) {
        int c = lane + i * 32;
        float o = xin[base + c] + (v[i] - mean) * r * gamma[c] + beta[c];
        out[base + c]   = o;
        out_r[base + c] = __float2half_rn(o);
    }
}

// ---------------- host launcher ----------------
extern "C" void kernel_launch(void* const* d_in, const int* in_sizes, int n_in,
                              void* d_out, int out_size)
{
    const int*   src  = (const int*)  d_in[0];
    const int*   mask = (const int*)  d_in[1];
    const float* emb  = (const float*)d_in[2];
    const float* Wq   = (const float*)d_in[3];
    const float* bq   = (const float*)d_in[4];
    const float* Wk   = (const float*)d_in[5];
    const float* bk   = (const float*)d_in[6];
    const float* Wv   = (const float*)d_in[7];
    const float* bv   = (const float*)d_in[8];
    const float* Wo   = (const float*)d_in[9];
    const float* bo   = (const float*)d_in[10];
    const float* gamma= (const float*)d_in[11];
    const float* beta = (const float*)d_in[12];
    const float* W1   = (const float*)d_in[13];
    const float* b1   = (const float*)d_in[14];
    const float* W2   = (const float*)d_in[15];
    const float* b2   = (const float*)d_in[16];

    float *x, *res, *t2a, *t2b, *mb;
    int *mbf;
    __half *xr, *q, *k, *vt, *t, *resr, *h1, *wh;
    cudaGetSymbolAddress((void**)&x,    g_x);
    cudaGetSymbolAddress((void**)&res,  g_res);
    cudaGetSymbolAddress((void**)&t2a,  g_t2a);
    cudaGetSymbolAddress((void**)&t2b,  g_t2b);
    cudaGetSymbolAddress((void**)&mb,   g_mb);
    cudaGetSymbolAddress((void**)&mbf,  g_mbf);
    cudaGetSymbolAddress((void**)&xr,   g_xr);
    cudaGetSymbolAddress((void**)&q,    g_q);
    cudaGetSymbolAddress((void**)&k,    g_k);
    cudaGetSymbolAddress((void**)&vt,   g_vt);
    cudaGetSymbolAddress((void**)&t,    g_t);
    cudaGetSymbolAddress((void**)&resr, g_resr);
    cudaGetSymbolAddress((void**)&h1,   g_h1);
    cudaGetSymbolAddress((void**)&wh,   g_wh);

    cudaFuncSetAttribute(flash_kernel,
                         cudaFuncAttributeMaxDynamicSharedMemorySize, FLASH_SMEM);
    cudaFuncSetAttribute(gemm_qkv,
                         cudaFuncAttributeMaxDynamicSharedMemorySize, GEMM_SMEM);
    cudaFuncSetAttribute(gemm_h,
                         cudaFuncAttributeMaxDynamicSharedMemorySize, GEMM_SMEM);
    cudaFuncSetAttribute(gemm_sk,
                         cudaFuncAttributeMaxDynamicSharedMemorySize, GEMM_SMEM);

    transpose_all_kernel<<<L_ * 3072, 256>>>(Wq, Wk, Wv, Wo, W1, W2, wh);
    embed_kernel<<<(M_ * H_) / 256, 256>>>(src, emb, mask, x, xr, mb, mbf);

    dim3 gQKV (H_ / 128,  M_ / 128, 3);
    dim3 gSK  (H_ / 128,  M_ / 128, 2);
    dim3 gFfn1(FF_ / 128, M_ / 128, 1);
    dim3 gFlash(S_ / 128, B_ * NH_);

    for (int i = 0; i < L_; i++) {
        const __half* WqT = wh + WOFF_Q + (size_t)i * H_ * H_;
        const __half* WkT = wh + WOFF_K + (size_t)i * H_ * H_;
        const __half* WvT = wh + WOFF_V + (size_t)i * H_ * H_;
        const __half* WoT = wh + WOFF_O + (size_t)i * H_ * H_;
        const __half* W1T = wh + WOFF_1 + (size_t)i * H_ * FF_;
        const __half* W2T = wh + WOFF_2 + (size_t)i * FF_ * H_;
        const float* bq_i = bq + i * H_;
        const float* bk_i = bk + i * H_;
        const float* bv_i = bv + i * H_;
        const float* bo_i = bo + i * H_;
        const float* b1_i = b1 + i * FF_;
        const float* b2_i = b2 + i * H_;
        const float* g_i  = gamma + i * H_;
        const float* be_i = beta  + i * H_;
        float* xout = (i == L_ - 1) ? (float*)d_out : x;

        gemm_qkv<<<gQKV, 256, GEMM_SMEM>>>(
            xr, WqT, WkT, WvT, bq_i, bk_i, bv_i, q, k, vt, H_, H_);

        flash_kernel<<<gFlash, 256, FLASH_SMEM>>>(q, k, vt, mb, mbf, t);

        gemm_sk<<<gSK, 256, GEMM_SMEM>>>(t, WoT, bo_i, t2a, t2b, H_, H_);
        add_ln_kernel<<<M_ / 8, 256>>>(x, t2a, t2b, g_i, be_i, res, resr);

        gemm_h<<<gFfn1, 256, GEMM_SMEM>>>(resr, W1T, b1_i, h1, FF_, H_);

        gemm_sk<<<gSK, 256, GEMM_SMEM>>>(h1, W2T, b2_i, t2a, t2b, H_, FF_);
        add_ln_kernel<<<M_ / 8, 256>>>(res, t2a, t2b, g_i, be_i, xout, resr);
        xr = resr;
    }
}